// round 4
// baseline (speedup 1.0000x reference)
#include <cuda_runtime.h>

#define BB 2
#define TT 2048
#define CC 768
#define HH 12
#define NLEFT 6
#define DD 64
#define MM (BB*TT)
#define N1 (3*CC)

#define NEGF (-3.402823466e38f)

// Scratch (device globals: allocation-free)
__device__ float g_q[BB*HH*TT*DD];
__device__ float g_k[BB*HH*TT*DD];
__device__ float g_v[BB*HH*TT*DD];
__device__ float g_ctx[BB*TT*CC];

__device__ __forceinline__ unsigned f2tf32(float f) {
    unsigned r;
    asm("cvt.rna.tf32.f32 %0, %1;" : "=r"(r) : "f"(f));
    return r;
}

// D += A(16x8,row) * B(8x8,col)  tf32 -> f32
__device__ __forceinline__ void mma8(float* d,
    unsigned a0, unsigned a1, unsigned a2, unsigned a3,
    unsigned b0, unsigned b1)
{
    asm volatile(
        "mma.sync.aligned.m16n8k8.row.col.f32.tf32.tf32.f32 "
        "{%0,%1,%2,%3}, {%4,%5,%6,%7}, {%8,%9}, {%0,%1,%2,%3};"
        : "+f"(d[0]), "+f"(d[1]), "+f"(d[2]), "+f"(d[3])
        : "r"(a0), "r"(a1), "r"(a2), "r"(a3), "r"(b0), "r"(b1));
}

// Pair-packed k index: p(k) = (k>>3)*8 + (k&3)*2 + ((k&4)>>2)
// -> fragment pair {kk+t, kk+4+t} sits at consecutive words (ks*4+t)*2.

// ---------------------------------------------------------------------------
// tf32 MMA GEMM: C = A(MxK) @ W(NxK)^T + bias.
// BM=128, BN=128, BK=32. 256 thr = 8 warps (4M x 2N), warp tile 32x64.
// Pair-packed smem (stride 40 words: 64-bit-bank conflict-free frag loads),
// double-buffered, one __syncthreads per k-chunk.
// MODE 0: A = x, scatter to g_q/g_k/g_v.  MODE 1: A = g_ctx, write out.
// ---------------------------------------------------------------------------
#define GSTR 40
#define GBUF (128 * GSTR)

template<int MODE>
__global__ __launch_bounds__(256, 2) void mma_gemm_kernel(
    const float* __restrict__ A_in, const float* __restrict__ W,
    const float* __restrict__ bias, float* __restrict__ out)
{
    extern __shared__ unsigned gsm[];   // 2 buffers x (As + Bs), 81920 B

    const float* Ag = (MODE == 0) ? A_in : (const float*)g_ctx;

    const int K = CC;
    const int tid  = threadIdx.x;
    const int lane = tid & 31, warp = tid >> 5;
    const int mw = warp >> 1, nw = warp & 1;
    const int m0 = blockIdx.y * 128, n0 = blockIdx.x * 128;
    const int g = lane >> 2, t = lane & 3;

    // Loader indexing (shared by A and B tiles): 1024 float4 each, 4/thread.
    const int lrow[4] = { (tid + 0*256) >> 3, (tid + 1*256) >> 3,
                          (tid + 2*256) >> 3, (tid + 3*256) >> 3 };
    const int lkq  = (tid & 7) << 2;
    const int lbase = ((lkq >> 3) << 3) + ((lkq & 4) >> 2);

    float acc[2][8][4];
#pragma unroll
    for (int mt = 0; mt < 2; mt++)
#pragma unroll
        for (int nt = 0; nt < 8; nt++)
#pragma unroll
            for (int c = 0; c < 4; c++) acc[mt][nt][c] = 0.f;

    const int NCH = K / 32;

    // Preload chunk 0 into buffer 0
    {
        unsigned* As = gsm;
        unsigned* Bs = gsm + GBUF;
#pragma unroll
        for (int i = 0; i < 4; i++) {
            float4 va = *(const float4*)(Ag + (size_t)(m0 + lrow[i]) * K + lkq);
            As[lrow[i] * GSTR + lbase + 0] = f2tf32(va.x);
            As[lrow[i] * GSTR + lbase + 2] = f2tf32(va.y);
            As[lrow[i] * GSTR + lbase + 4] = f2tf32(va.z);
            As[lrow[i] * GSTR + lbase + 6] = f2tf32(va.w);
            float4 vb = *(const float4*)(W + (size_t)(n0 + lrow[i]) * K + lkq);
            Bs[lrow[i] * GSTR + lbase + 0] = f2tf32(vb.x);
            Bs[lrow[i] * GSTR + lbase + 2] = f2tf32(vb.y);
            Bs[lrow[i] * GSTR + lbase + 4] = f2tf32(vb.z);
            Bs[lrow[i] * GSTR + lbase + 6] = f2tf32(vb.w);
        }
    }
    __syncthreads();

    for (int c = 0; c < NCH; c++) {
        unsigned* As = gsm + (c & 1) * 2 * GBUF;
        unsigned* Bs = As + GBUF;

        if (c + 1 < NCH) {                       // fill other buffer
            unsigned* An = gsm + ((c + 1) & 1) * 2 * GBUF;
            unsigned* Bn = An + GBUF;
            const int k0n = (c + 1) * 32;
#pragma unroll
            for (int i = 0; i < 4; i++) {
                float4 va = *(const float4*)(Ag + (size_t)(m0 + lrow[i]) * K + k0n + lkq);
                An[lrow[i] * GSTR + lbase + 0] = f2tf32(va.x);
                An[lrow[i] * GSTR + lbase + 2] = f2tf32(va.y);
                An[lrow[i] * GSTR + lbase + 4] = f2tf32(va.z);
                An[lrow[i] * GSTR + lbase + 6] = f2tf32(va.w);
                float4 vb = *(const float4*)(W + (size_t)(n0 + lrow[i]) * K + k0n + lkq);
                Bn[lrow[i] * GSTR + lbase + 0] = f2tf32(vb.x);
                Bn[lrow[i] * GSTR + lbase + 2] = f2tf32(vb.y);
                Bn[lrow[i] * GSTR + lbase + 4] = f2tf32(vb.z);
                Bn[lrow[i] * GSTR + lbase + 6] = f2tf32(vb.w);
            }
        }

#pragma unroll
        for (int ks = 0; ks < 4; ks++) {
            const int po = (ks * 4 + t) * 2;
            uint2 aA[2], aB[2];
            {
                int rm = mw * 32;
                aA[0] = *(const uint2*)&As[(rm     + g) * GSTR + po];
                aB[0] = *(const uint2*)&As[(rm + 8 + g) * GSTR + po];
                aA[1] = *(const uint2*)&As[(rm + 16 + g) * GSTR + po];
                aB[1] = *(const uint2*)&As[(rm + 24 + g) * GSTR + po];
            }
#pragma unroll
            for (int nt = 0; nt < 8; nt++) {
                uint2 bf = *(const uint2*)&Bs[(nw * 64 + nt * 8 + g) * GSTR + po];
                mma8(acc[0][nt], aA[0].x, aB[0].x, aA[0].y, aB[0].y, bf.x, bf.y);
                mma8(acc[1][nt], aA[1].x, aB[1].x, aA[1].y, aB[1].y, bf.x, bf.y);
            }
        }
        __syncthreads();
    }

    // Epilogue. C frag: rows g, g+8 ; cols t*2, t*2+1. Warp n-span = one head.
    if (MODE == 0) {
        const int s  = n0 / CC;                       // 128 | 768 -> constant
        const int hh = ((n0 % CC) + nw * 64) / DD;
        float* dst = (s == 0) ? g_q : ((s == 1) ? g_k : g_v);
#pragma unroll
        for (int mt = 0; mt < 2; mt++) {
            int m = m0 + mw * 32 + mt * 16 + g;
            int b0i = m >> 11, tok0 = m & 2047;
            int m1 = m + 8, b1i = m1 >> 11, tok1 = m1 & 2047;
#pragma unroll
            for (int nt = 0; nt < 8; nt++) {
                int dcol = nt * 8 + t * 2;            // 0..63 within head
                int n = n0 + nw * 64 + dcol;
                float bv0 = bias[n], bv1 = bias[n + 1];
                float2 r0 = make_float2(acc[mt][nt][0] + bv0, acc[mt][nt][1] + bv1);
                float2 r1 = make_float2(acc[mt][nt][2] + bv0, acc[mt][nt][3] + bv1);
                *(float2*)(dst + ((size_t)(b0i * HH + hh) * TT + tok0) * DD + dcol) = r0;
                *(float2*)(dst + ((size_t)(b1i * HH + hh) * TT + tok1) * DD + dcol) = r1;
            }
        }
    } else {
#pragma unroll
        for (int mt = 0; mt < 2; mt++) {
            int m = m0 + mw * 32 + mt * 16 + g;
#pragma unroll
            for (int nt = 0; nt < 8; nt++) {
                int n = n0 + nw * 64 + nt * 8 + t * 2;
                float bv0 = bias[n], bv1 = bias[n + 1];
                float2 r0 = make_float2(acc[mt][nt][0] + bv0, acc[mt][nt][1] + bv1);
                float2 r1 = make_float2(acc[mt][nt][2] + bv0, acc[mt][nt][3] + bv1);
                *(float2*)(out + (size_t)m * CC + n) = r0;
                *(float2*)(out + (size_t)(m + 8) * CC + n) = r1;
            }
        }
    }
}

// ---------------------------------------------------------------------------
// tf32 MMA flash attention. 128 thr = 4 warps; warp owns 16 q-rows x 64 k-cols.
// Q/K/P pair-packed (stride 72 words: conflict-free LDS.64 frag loads);
// V row-major (stride 68, scalar b-frags). Q pre-scaled by 1/8.
// ---------------------------------------------------------------------------
#define ASTR 72

__global__ __launch_bounds__(128) void attn_mma_kernel(const int* __restrict__ amask)
{
    extern __shared__ unsigned smu[];
    unsigned* Qs = smu;                    // [q][p(d)]     64*72
    unsigned* Ks = smu + 64 * ASTR;        // [kcol][p(d)]  64*72
    unsigned* Ps = smu + 2 * 64 * ASTR;    // [q][p(kseq)]  64*72
    unsigned* Vs = smu + 3 * 64 * ASTR;    // [kseq][d]     64*68
    float*    pm = (float*)(smu + 3 * 64 * ASTR + 64 * 68);

    const int bh = blockIdx.x, qb = blockIdx.y;
    const int b = bh / HH, h = bh % HH;
    const bool left = (h < NLEFT);

    const float* Qg = g_q + (size_t)bh * TT * DD;
    const float* Kg = g_k + (size_t)bh * TT * DD;
    const float* Vg = g_v + (size_t)bh * TT * DD;

    const int tid = threadIdx.x;
    const int lane = tid & 31, warp = tid >> 5;
    const int g = lane >> 2, t = lane & 3;
    const int rm = warp * 16;

    // Loader indexing: row = idx>>4, d4 = (idx&15)*4, pair-packed base.
    const int ld4 = (tid & 15) << 2;
    const int lpb = ((ld4 >> 3) << 3) + ((ld4 & 4) >> 2);

    // Load Q (scaled by 1/8, exact), pair-packed
#pragma unroll
    for (int i = 0; i < 8; i++) {
        int row = (tid + i * 128) >> 4;
        float4 v = *(const float4*)(Qg + (size_t)(qb * 64 + row) * DD + ld4);
        Qs[row * ASTR + lpb + 0] = f2tf32(v.x * 0.125f);
        Qs[row * ASTR + lpb + 2] = f2tf32(v.y * 0.125f);
        Qs[row * ASTR + lpb + 4] = f2tf32(v.z * 0.125f);
        Qs[row * ASTR + lpb + 6] = f2tf32(v.w * 0.125f);
    }

    float m_r[2] = {NEGF, NEGF};
    float l_r[2] = {0.f, 0.f};
    float O[8][4];
#pragma unroll
    for (int nt = 0; nt < 8; nt++)
#pragma unroll
        for (int c = 0; c < 4; c++) O[nt][c] = 0.f;

    const int kb0 = left ? 0 : qb;
    const int kb1 = left ? qb : (TT / 64 - 1);
    const int qi0 = qb * 64 + rm + g, qi1 = qi0 + 8;

    // P store column offsets (pair-packed kseq): pp0 for col t*2, pp1 for t*2+1
    const int pp0 = ((2 * t) & 3) * 2 + (((2 * t) & 4) >> 2);
    const int pp1 = ((2 * t + 1) & 3) * 2 + (((2 * t + 1) & 4) >> 2);

    for (int kb = kb0; kb <= kb1; kb++) {
        __syncthreads();                       // prev iter done with Ks/Vs
#pragma unroll
        for (int i = 0; i < 8; i++) {
            int row = (tid + i * 128) >> 4;
            float4 kv = *(const float4*)(Kg + (size_t)(kb * 64 + row) * DD + ld4);
            Ks[row * ASTR + lpb + 0] = f2tf32(kv.x);
            Ks[row * ASTR + lpb + 2] = f2tf32(kv.y);
            Ks[row * ASTR + lpb + 4] = f2tf32(kv.z);
            Ks[row * ASTR + lpb + 6] = f2tf32(kv.w);
            float4 vv = *(const float4*)(Vg + (size_t)(kb * 64 + row) * DD + ld4);
            Vs[row * 68 + ld4 + 0] = f2tf32(vv.x);
            Vs[row * 68 + ld4 + 1] = f2tf32(vv.y);
            Vs[row * 68 + ld4 + 2] = f2tf32(vv.z);
            Vs[row * 68 + ld4 + 3] = f2tf32(vv.w);
        }
        if (tid < 64)
            pm[tid] = amask[b * TT + kb * 64 + tid] ? 0.f : NEGF;
        __syncthreads();

        // S = Qs @ Ks^T  (warp: 16 rows x 64 cols)
        float S[8][4];
#pragma unroll
        for (int nt = 0; nt < 8; nt++)
#pragma unroll
            for (int c = 0; c < 4; c++) S[nt][c] = 0.f;

#pragma unroll
        for (int ks = 0; ks < 8; ks++) {
            const int po = (ks * 4 + t) * 2;
            uint2 aL = *(const uint2*)&Qs[(rm     + g) * ASTR + po];
            uint2 aH = *(const uint2*)&Qs[(rm + 8 + g) * ASTR + po];
#pragma unroll
            for (int nt = 0; nt < 8; nt++) {
                uint2 bf = *(const uint2*)&Ks[(nt * 8 + g) * ASTR + po];
                mma8(S[nt], aL.x, aH.x, aL.y, aH.y, bf.x, bf.y);
            }
        }

        // Mask + online softmax (C frag cols = t*2, t*2+1; rows g, g+8)
        float mx0 = NEGF, mx1 = NEGF;
        const bool diag = (kb == qb);
#pragma unroll
        for (int nt = 0; nt < 8; nt++) {
            int c0 = nt * 8 + t * 2;
            float p0 = pm[c0], p1 = pm[c0 + 1];
            float s0 = S[nt][0] + p0, s1 = S[nt][1] + p1;
            float s2 = S[nt][2] + p0, s3 = S[nt][3] + p1;
            if (diag) {
                int k0i = kb * 64 + c0, k1i = k0i + 1;
                if (left) {
                    if (k0i > qi0) s0 = NEGF;
                    if (k1i > qi0) s1 = NEGF;
                    if (k0i > qi1) s2 = NEGF;
                    if (k1i > qi1) s3 = NEGF;
                } else {
                    if (k0i < qi0) s0 = NEGF;
                    if (k1i < qi0) s1 = NEGF;
                    if (k0i < qi1) s2 = NEGF;
                    if (k1i < qi1) s3 = NEGF;
                }
            }
            S[nt][0] = s0; S[nt][1] = s1; S[nt][2] = s2; S[nt][3] = s3;
            mx0 = fmaxf(mx0, fmaxf(s0, s1));
            mx1 = fmaxf(mx1, fmaxf(s2, s3));
        }
        mx0 = fmaxf(mx0, __shfl_xor_sync(0xffffffffu, mx0, 1));
        mx0 = fmaxf(mx0, __shfl_xor_sync(0xffffffffu, mx0, 2));
        mx1 = fmaxf(mx1, __shfl_xor_sync(0xffffffffu, mx1, 1));
        mx1 = fmaxf(mx1, __shfl_xor_sync(0xffffffffu, mx1, 2));

        float mn0 = fmaxf(m_r[0], mx0), mn1 = fmaxf(m_r[1], mx1);
        float al0 = __expf(m_r[0] - mn0), al1 = __expf(m_r[1] - mn1);
        m_r[0] = mn0; m_r[1] = mn1;

        float rs0 = 0.f, rs1 = 0.f;
#pragma unroll
        for (int nt = 0; nt < 8; nt++) {
            float e0 = __expf(S[nt][0] - mn0), e1 = __expf(S[nt][1] - mn0);
            float e2 = __expf(S[nt][2] - mn1), e3 = __expf(S[nt][3] - mn1);
            S[nt][0] = e0; S[nt][1] = e1; S[nt][2] = e2; S[nt][3] = e3;
            rs0 += e0 + e1; rs1 += e2 + e3;
        }
        rs0 += __shfl_xor_sync(0xffffffffu, rs0, 1);
        rs0 += __shfl_xor_sync(0xffffffffu, rs0, 2);
        rs1 += __shfl_xor_sync(0xffffffffu, rs1, 1);
        rs1 += __shfl_xor_sync(0xffffffffu, rs1, 2);
        l_r[0] = l_r[0] * al0 + rs0;
        l_r[1] = l_r[1] * al1 + rs1;
#pragma unroll
        for (int nt = 0; nt < 8; nt++) {
            O[nt][0] *= al0; O[nt][1] *= al0;
            O[nt][2] *= al1; O[nt][3] *= al1;
        }

        // P -> smem (tf32, pair-packed kseq, warp-private rows)
        __syncwarp();
#pragma unroll
        for (int nt = 0; nt < 8; nt++) {
            Ps[(rm     + g) * ASTR + nt * 8 + pp0] = f2tf32(S[nt][0]);
            Ps[(rm     + g) * ASTR + nt * 8 + pp1] = f2tf32(S[nt][1]);
            Ps[(rm + 8 + g) * ASTR + nt * 8 + pp0] = f2tf32(S[nt][2]);
            Ps[(rm + 8 + g) * ASTR + nt * 8 + pp1] = f2tf32(S[nt][3]);
        }
        __syncwarp();

        // O += P @ V
#pragma unroll
        for (int ks = 0; ks < 8; ks++) {
            const int kk = ks * 8;
            const int po = (ks * 4 + t) * 2;
            uint2 aL = *(const uint2*)&Ps[(rm     + g) * ASTR + po];
            uint2 aH = *(const uint2*)&Ps[(rm + 8 + g) * ASTR + po];
#pragma unroll
            for (int nt = 0; nt < 8; nt++) {
                unsigned b0 = Vs[(kk     + t) * 68 + nt * 8 + g];
                unsigned b1 = Vs[(kk + 4 + t) * 68 + nt * 8 + g];
                mma8(O[nt], aL.x, aH.x, aL.y, aH.y, b0, b1);
            }
        }
    }

    // Epilogue -> g_ctx
    float inv0 = 1.0f / l_r[0], inv1 = 1.0f / l_r[1];
    int t0 = qb * 64 + rm + g, t1 = t0 + 8;
#pragma unroll
    for (int nt = 0; nt < 8; nt++) {
        int col = h * DD + nt * 8 + t * 2;
        *(float2*)(g_ctx + ((size_t)b * TT + t0) * CC + col) =
            make_float2(O[nt][0] * inv0, O[nt][1] * inv0);
        *(float2*)(g_ctx + ((size_t)b * TT + t1) * CC + col) =
            make_float2(O[nt][2] * inv1, O[nt][3] * inv1);
    }
}

// ---------------------------------------------------------------------------
extern "C" void kernel_launch(void* const* d_in, const int* in_sizes, int n_in,
                              void* d_out, int out_size)
{
    const float* x      = (const float*)d_in[0];
    const int*   amask  = (const int*)  d_in[1];
    const float* Wqkv_w = (const float*)d_in[2];
    const float* Wqkv_b = (const float*)d_in[3];
    const float* Wo_w   = (const float*)d_in[4];
    const float* Wo_b   = (const float*)d_in[5];
    float* out = (float*)d_out;

    (void)in_sizes; (void)n_in; (void)out_size;

    const int gemm_smem = 4 * GBUF * 4;                       // 81920 B
    const int attn_smem = (3 * 64 * ASTR + 64 * 68 + 64) * 4; // 72960 B

    cudaFuncSetAttribute(mma_gemm_kernel<0>,
                         cudaFuncAttributeMaxDynamicSharedMemorySize, gemm_smem);
    cudaFuncSetAttribute(mma_gemm_kernel<1>,
                         cudaFuncAttributeMaxDynamicSharedMemorySize, gemm_smem);
    cudaFuncSetAttribute(attn_mma_kernel,
                         cudaFuncAttributeMaxDynamicSharedMemorySize, attn_smem);

    mma_gemm_kernel<0><<<dim3(N1 / 128, MM / 128), 256, gemm_smem>>>(x, Wqkv_w, Wqkv_b, nullptr);
    attn_mma_kernel<<<dim3(BB * HH, TT / 64), 128, attn_smem>>>(amask);
    mma_gemm_kernel<1><<<dim3(CC / 128, MM / 128), 256, gemm_smem>>>(nullptr, Wo_w, Wo_b, out);
}

// round 5
// speedup vs baseline: 1.5056x; 1.5056x over previous
#include <cuda_runtime.h>

#define BB 2
#define TT 2048
#define CC 768
#define HH 12
#define NLEFT 6
#define DD 64
#define MM (BB*TT)
#define N1 (3*CC)

#define NEGF (-3.402823466e38f)

// Scratch (device globals: allocation-free)
__device__ float g_q[BB*HH*TT*DD];
__device__ float g_k[BB*HH*TT*DD];
__device__ float g_v[BB*HH*TT*DD];
__device__ float g_ctx[BB*TT*CC];

__device__ __forceinline__ unsigned f2tf32(float f) {
    unsigned r;
    asm("cvt.rna.tf32.f32 %0, %1;" : "=r"(r) : "f"(f));
    return r;
}

// D += A(16x8,row) * B(8x8,col)  tf32 -> f32
__device__ __forceinline__ void mma8(float* d,
    unsigned a0, unsigned a1, unsigned a2, unsigned a3,
    unsigned b0, unsigned b1)
{
    asm volatile(
        "mma.sync.aligned.m16n8k8.row.col.f32.tf32.tf32.f32 "
        "{%0,%1,%2,%3}, {%4,%5,%6,%7}, {%8,%9}, {%0,%1,%2,%3};"
        : "+f"(d[0]), "+f"(d[1]), "+f"(d[2]), "+f"(d[3])
        : "r"(a0), "r"(a1), "r"(a2), "r"(a3), "r"(b0), "r"(b1));
}

// Pair-packed k index: p(k) = (k>>3)*8 + (k&3)*2 + ((k&4)>>2)
// -> fragment pair {kk+t, kk+4+t} sits at consecutive words (ks*4+t)*2,
//    loadable as one LDS.64.

// ---------------------------------------------------------------------------
// tf32 MMA GEMM: C = A(MxK) @ W(NxK)^T + bias.
// BM=128, BN=64, BK=32. 256 thr = 8 warps (4M x 2N), warp tile 32x32.
// Pair-packed smem, stride 40 words: 64-bit-bank conflict-free frag loads.
// MODE 0: A = x, scatter to g_q/g_k/g_v.  MODE 1: A = g_ctx, write out.
// ---------------------------------------------------------------------------
#define GSTR 40

template<int MODE>
__global__ __launch_bounds__(256) void mma_gemm_kernel(
    const float* __restrict__ A_in, const float* __restrict__ W,
    const float* __restrict__ bias, float* __restrict__ out)
{
    __shared__ unsigned As[128 * GSTR];   // [m][p(k)]
    __shared__ unsigned Bs[64 * GSTR];    // [n][p(k)]

    const float* Ag = (MODE == 0) ? A_in : (const float*)g_ctx;

    const int K = CC;
    const int tid  = threadIdx.x;
    const int lane = tid & 31, warp = tid >> 5;
    const int mw = warp >> 1, nw = warp & 1;
    const int m0 = blockIdx.y * 128, n0 = blockIdx.x * 64;
    const int g = lane >> 2, t = lane & 3;

    // Loader indexing: each float4 (4 consecutive k) packs to lbase+{0,2,4,6}.
    const int lkq = (tid & 7) << 2;
    const int lbase = ((lkq >> 3) << 3) + ((lkq & 4) >> 2);

    float acc[2][4][4];
#pragma unroll
    for (int mt = 0; mt < 2; mt++)
#pragma unroll
        for (int nt = 0; nt < 4; nt++)
#pragma unroll
            for (int c = 0; c < 4; c++) acc[mt][nt][c] = 0.f;

    for (int k0 = 0; k0 < K; k0 += 32) {
#pragma unroll
        for (int i = 0; i < 4; i++) {          // 1024 float4 of A
            int idx = tid + i * 256;
            int row = idx >> 3;
            float4 v = *(const float4*)(Ag + (size_t)(m0 + row) * K + k0 + lkq);
            As[row * GSTR + lbase + 0] = f2tf32(v.x);
            As[row * GSTR + lbase + 2] = f2tf32(v.y);
            As[row * GSTR + lbase + 4] = f2tf32(v.z);
            As[row * GSTR + lbase + 6] = f2tf32(v.w);
        }
#pragma unroll
        for (int i = 0; i < 2; i++) {          // 512 float4 of B
            int idx = tid + i * 256;
            int row = idx >> 3;
            float4 v = *(const float4*)(W + (size_t)(n0 + row) * K + k0 + lkq);
            Bs[row * GSTR + lbase + 0] = f2tf32(v.x);
            Bs[row * GSTR + lbase + 2] = f2tf32(v.y);
            Bs[row * GSTR + lbase + 4] = f2tf32(v.z);
            Bs[row * GSTR + lbase + 6] = f2tf32(v.w);
        }
        __syncthreads();

#pragma unroll
        for (int ks = 0; ks < 4; ks++) {
            const int po = (ks * 4 + t) * 2;
            uint2 aL[2], aH[2], bf[4];
#pragma unroll
            for (int mt = 0; mt < 2; mt++) {
                int rm = mw * 32 + mt * 16;
                aL[mt] = *(const uint2*)&As[(rm     + g) * GSTR + po];
                aH[mt] = *(const uint2*)&As[(rm + 8 + g) * GSTR + po];
            }
#pragma unroll
            for (int nt = 0; nt < 4; nt++)
                bf[nt] = *(const uint2*)&Bs[(nw * 32 + nt * 8 + g) * GSTR + po];
#pragma unroll
            for (int mt = 0; mt < 2; mt++)
#pragma unroll
                for (int nt = 0; nt < 4; nt++)
                    mma8(acc[mt][nt], aL[mt].x, aH[mt].x, aL[mt].y, aH[mt].y,
                         bf[nt].x, bf[nt].y);
        }
        __syncthreads();
    }

    // Epilogue. C frag: rows g, g+8 ; cols t*2, t*2+1.
    if (MODE == 0) {
        const int s  = n0 / CC;
        const int hh = (n0 % CC) / DD;
        float* dst = (s == 0) ? g_q : ((s == 1) ? g_k : g_v);
#pragma unroll
        for (int mt = 0; mt < 2; mt++) {
            int m = m0 + mw * 32 + mt * 16 + g;
            int b0i = m >> 11, tok0 = m & 2047;
            int m1 = m + 8, b1i = m1 >> 11, tok1 = m1 & 2047;
#pragma unroll
            for (int nt = 0; nt < 4; nt++) {
                int dcol = nw * 32 + nt * 8 + t * 2;
                int n = n0 + dcol;
                float bv0 = bias[n], bv1 = bias[n + 1];
                float2 r0 = make_float2(acc[mt][nt][0] + bv0, acc[mt][nt][1] + bv1);
                float2 r1 = make_float2(acc[mt][nt][2] + bv0, acc[mt][nt][3] + bv1);
                *(float2*)(dst + ((size_t)(b0i * HH + hh) * TT + tok0) * DD + dcol) = r0;
                *(float2*)(dst + ((size_t)(b1i * HH + hh) * TT + tok1) * DD + dcol) = r1;
            }
        }
    } else {
#pragma unroll
        for (int mt = 0; mt < 2; mt++) {
            int m = m0 + mw * 32 + mt * 16 + g;
#pragma unroll
            for (int nt = 0; nt < 4; nt++) {
                int n = n0 + nw * 32 + nt * 8 + t * 2;
                float bv0 = bias[n], bv1 = bias[n + 1];
                float2 r0 = make_float2(acc[mt][nt][0] + bv0, acc[mt][nt][1] + bv1);
                float2 r1 = make_float2(acc[mt][nt][2] + bv0, acc[mt][nt][3] + bv1);
                *(float2*)(out + (size_t)m * CC + n) = r0;
                *(float2*)(out + (size_t)(m + 8) * CC + n) = r1;
            }
        }
    }
}

// ---------------------------------------------------------------------------
// tf32 MMA flash attention (R3-proven version, unchanged).
// 128 thr = 4 warps; warp owns 16 q-rows x 64 k-cols. Q pre-scaled by 1/8.
// smem (dynamic): Qs,Ks,Vs,Ps [64][68] tf32 + pm[64] f32.
// ---------------------------------------------------------------------------
__global__ __launch_bounds__(128) void attn_mma_kernel(const int* __restrict__ amask)
{
    extern __shared__ unsigned smu[];
    unsigned* Qs = smu;                 // [q][d]
    unsigned* Ks = smu + 64 * 68;       // [kcol][d]
    unsigned* Vs = smu + 2 * 64 * 68;   // [kseq][d]
    unsigned* Ps = smu + 3 * 64 * 68;   // [q][kseq]  (warp-private rows)
    float*    pm = (float*)(smu + 4 * 64 * 68);

    const int bh = blockIdx.x, qb = blockIdx.y;
    const int b = bh / HH, h = bh % HH;
    const bool left = (h < NLEFT);

    const float* Qg = g_q + (size_t)bh * TT * DD;
    const float* Kg = g_k + (size_t)bh * TT * DD;
    const float* Vg = g_v + (size_t)bh * TT * DD;

    const int tid = threadIdx.x;
    const int lane = tid & 31, warp = tid >> 5;
    const int g = lane >> 2, t = lane & 3;
    const int rm = warp * 16;

    // Load Q (scaled by 1/8, exact)
#pragma unroll
    for (int i = 0; i < 8; i++) {
        int idx = tid + i * 128;
        int row = idx >> 4, d4 = (idx & 15) << 2;
        float4 v = *(const float4*)(Qg + (size_t)(qb * 64 + row) * DD + d4);
        Qs[row * 68 + d4 + 0] = f2tf32(v.x * 0.125f);
        Qs[row * 68 + d4 + 1] = f2tf32(v.y * 0.125f);
        Qs[row * 68 + d4 + 2] = f2tf32(v.z * 0.125f);
        Qs[row * 68 + d4 + 3] = f2tf32(v.w * 0.125f);
    }

    float m_r[2] = {NEGF, NEGF};
    float l_r[2] = {0.f, 0.f};
    float O[8][4];
#pragma unroll
    for (int nt = 0; nt < 8; nt++)
#pragma unroll
        for (int c = 0; c < 4; c++) O[nt][c] = 0.f;

    const int kb0 = left ? 0 : qb;
    const int kb1 = left ? qb : (TT / 64 - 1);
    const int qi0 = qb * 64 + rm + g, qi1 = qi0 + 8;

    for (int kb = kb0; kb <= kb1; kb++) {
        __syncthreads();                       // prev iter done with Ks/Vs
#pragma unroll
        for (int i = 0; i < 8; i++) {
            int idx = tid + i * 128;
            int row = idx >> 4, d4 = (idx & 15) << 2;
            float4 kv = *(const float4*)(Kg + (size_t)(kb * 64 + row) * DD + d4);
            Ks[row * 68 + d4 + 0] = f2tf32(kv.x);
            Ks[row * 68 + d4 + 1] = f2tf32(kv.y);
            Ks[row * 68 + d4 + 2] = f2tf32(kv.z);
            Ks[row * 68 + d4 + 3] = f2tf32(kv.w);
            float4 vv = *(const float4*)(Vg + (size_t)(kb * 64 + row) * DD + d4);
            Vs[row * 68 + d4 + 0] = f2tf32(vv.x);
            Vs[row * 68 + d4 + 1] = f2tf32(vv.y);
            Vs[row * 68 + d4 + 2] = f2tf32(vv.z);
            Vs[row * 68 + d4 + 3] = f2tf32(vv.w);
        }
        if (tid < 64)
            pm[tid] = amask[b * TT + kb * 64 + tid] ? 0.f : NEGF;
        __syncthreads();

        // S = Qs @ Ks^T  (warp: 16 rows x 64 cols)
        float S[8][4];
#pragma unroll
        for (int nt = 0; nt < 8; nt++)
#pragma unroll
            for (int c = 0; c < 4; c++) S[nt][c] = 0.f;

#pragma unroll
        for (int ks = 0; ks < 8; ks++) {
            const int kk = ks * 8;
            unsigned a0 = Qs[(rm     + g) * 68 + kk     + t];
            unsigned a1 = Qs[(rm + 8 + g) * 68 + kk     + t];
            unsigned a2 = Qs[(rm     + g) * 68 + kk + 4 + t];
            unsigned a3 = Qs[(rm + 8 + g) * 68 + kk + 4 + t];
#pragma unroll
            for (int nt = 0; nt < 8; nt++) {
                unsigned b0 = Ks[(nt * 8 + g) * 68 + kk     + t];
                unsigned b1 = Ks[(nt * 8 + g) * 68 + kk + 4 + t];
                mma8(S[nt], a0, a1, a2, a3, b0, b1);
            }
        }

        // Mask + online softmax (C frag cols = t*2, t*2+1; rows g, g+8)
        float mx0 = NEGF, mx1 = NEGF;
        const bool diag = (kb == qb);
#pragma unroll
        for (int nt = 0; nt < 8; nt++) {
            int c0 = nt * 8 + t * 2;
            float p0 = pm[c0], p1 = pm[c0 + 1];
            float s0 = S[nt][0] + p0, s1 = S[nt][1] + p1;
            float s2 = S[nt][2] + p0, s3 = S[nt][3] + p1;
            if (diag) {
                int k0i = kb * 64 + c0, k1i = k0i + 1;
                if (left) {
                    if (k0i > qi0) s0 = NEGF;
                    if (k1i > qi0) s1 = NEGF;
                    if (k0i > qi1) s2 = NEGF;
                    if (k1i > qi1) s3 = NEGF;
                } else {
                    if (k0i < qi0) s0 = NEGF;
                    if (k1i < qi0) s1 = NEGF;
                    if (k0i < qi1) s2 = NEGF;
                    if (k1i < qi1) s3 = NEGF;
                }
            }
            S[nt][0] = s0; S[nt][1] = s1; S[nt][2] = s2; S[nt][3] = s3;
            mx0 = fmaxf(mx0, fmaxf(s0, s1));
            mx1 = fmaxf(mx1, fmaxf(s2, s3));
        }
        mx0 = fmaxf(mx0, __shfl_xor_sync(0xffffffffu, mx0, 1));
        mx0 = fmaxf(mx0, __shfl_xor_sync(0xffffffffu, mx0, 2));
        mx1 = fmaxf(mx1, __shfl_xor_sync(0xffffffffu, mx1, 1));
        mx1 = fmaxf(mx1, __shfl_xor_sync(0xffffffffu, mx1, 2));

        float mn0 = fmaxf(m_r[0], mx0), mn1 = fmaxf(m_r[1], mx1);
        float al0 = __expf(m_r[0] - mn0), al1 = __expf(m_r[1] - mn1);
        m_r[0] = mn0; m_r[1] = mn1;

        float rs0 = 0.f, rs1 = 0.f;
#pragma unroll
        for (int nt = 0; nt < 8; nt++) {
            float e0 = __expf(S[nt][0] - mn0), e1 = __expf(S[nt][1] - mn0);
            float e2 = __expf(S[nt][2] - mn1), e3 = __expf(S[nt][3] - mn1);
            S[nt][0] = e0; S[nt][1] = e1; S[nt][2] = e2; S[nt][3] = e3;
            rs0 += e0 + e1; rs1 += e2 + e3;
        }
        rs0 += __shfl_xor_sync(0xffffffffu, rs0, 1);
        rs0 += __shfl_xor_sync(0xffffffffu, rs0, 2);
        rs1 += __shfl_xor_sync(0xffffffffu, rs1, 1);
        rs1 += __shfl_xor_sync(0xffffffffu, rs1, 2);
        l_r[0] = l_r[0] * al0 + rs0;
        l_r[1] = l_r[1] * al1 + rs1;
#pragma unroll
        for (int nt = 0; nt < 8; nt++) {
            O[nt][0] *= al0; O[nt][1] *= al0;
            O[nt][2] *= al1; O[nt][3] *= al1;
        }

        // P -> smem (tf32, warp-private rows)
        __syncwarp();
#pragma unroll
        for (int nt = 0; nt < 8; nt++) {
            int c0 = nt * 8 + t * 2;
            Ps[(rm     + g) * 68 + c0    ] = f2tf32(S[nt][0]);
            Ps[(rm     + g) * 68 + c0 + 1] = f2tf32(S[nt][1]);
            Ps[(rm + 8 + g) * 68 + c0    ] = f2tf32(S[nt][2]);
            Ps[(rm + 8 + g) * 68 + c0 + 1] = f2tf32(S[nt][3]);
        }
        __syncwarp();

        // O += P @ V
#pragma unroll
        for (int ks = 0; ks < 8; ks++) {
            const int kk = ks * 8;
            unsigned a0 = Ps[(rm     + g) * 68 + kk     + t];
            unsigned a1 = Ps[(rm + 8 + g) * 68 + kk     + t];
            unsigned a2 = Ps[(rm     + g) * 68 + kk + 4 + t];
            unsigned a3 = Ps[(rm + 8 + g) * 68 + kk + 4 + t];
#pragma unroll
            for (int nt = 0; nt < 8; nt++) {
                unsigned b0 = Vs[(kk     + t) * 68 + nt * 8 + g];
                unsigned b1 = Vs[(kk + 4 + t) * 68 + nt * 8 + g];
                mma8(O[nt], a0, a1, a2, a3, b0, b1);
            }
        }
    }

    // Epilogue -> g_ctx
    float inv0 = 1.0f / l_r[0], inv1 = 1.0f / l_r[1];
    int t0 = qb * 64 + rm + g, t1 = t0 + 8;
#pragma unroll
    for (int nt = 0; nt < 8; nt++) {
        int col = h * DD + nt * 8 + t * 2;
        *(float2*)(g_ctx + ((size_t)b * TT + t0) * CC + col) =
            make_float2(O[nt][0] * inv0, O[nt][1] * inv0);
        *(float2*)(g_ctx + ((size_t)b * TT + t1) * CC + col) =
            make_float2(O[nt][2] * inv1, O[nt][3] * inv1);
    }
}

// ---------------------------------------------------------------------------
extern "C" void kernel_launch(void* const* d_in, const int* in_sizes, int n_in,
                              void* d_out, int out_size)
{
    const float* x      = (const float*)d_in[0];
    const int*   amask  = (const int*)  d_in[1];
    const float* Wqkv_w = (const float*)d_in[2];
    const float* Wqkv_b = (const float*)d_in[3];
    const float* Wo_w   = (const float*)d_in[4];
    const float* Wo_b   = (const float*)d_in[5];
    float* out = (float*)d_out;

    (void)in_sizes; (void)n_in; (void)out_size;

    const int attn_smem = 4 * 64 * 68 * 4 + 64 * 4;   // 69888 B
    cudaFuncSetAttribute(attn_mma_kernel,
                         cudaFuncAttributeMaxDynamicSharedMemorySize, attn_smem);

    mma_gemm_kernel<0><<<dim3(N1 / 64, MM / 128), 256>>>(x, Wqkv_w, Wqkv_b, nullptr);
    attn_mma_kernel<<<dim3(BB * HH, TT / 64), 128, attn_smem>>>(amask);
    mma_gemm_kernel<1><<<dim3(CC / 64, MM / 128), 256>>>(nullptr, Wo_w, Wo_b, out);
}

// round 7
// speedup vs baseline: 1.6964x; 1.1268x over previous
#include <cuda_runtime.h>

#define BB 2
#define TT 2048
#define CC 768
#define HH 12
#define NLEFT 6
#define DD 64
#define MM (BB*TT)
#define N1 (3*CC)
#define QT 128   // q rows per attention CTA

#define NEGF (-3.402823466e38f)

// Scratch (device globals: allocation-free)
__device__ float g_q[BB*HH*TT*DD];
__device__ float g_k[BB*HH*TT*DD];
__device__ float g_v[BB*HH*TT*DD];
__device__ float g_ctx[BB*TT*CC];

__device__ __forceinline__ unsigned f2tf32(float f) {
    unsigned r;
    asm("cvt.rna.tf32.f32 %0, %1;" : "=r"(r) : "f"(f));
    return r;
}

// D += A(16x8,row) * B(8x8,col)  tf32 -> f32
__device__ __forceinline__ void mma8(float* d,
    unsigned a0, unsigned a1, unsigned a2, unsigned a3,
    unsigned b0, unsigned b1)
{
    asm volatile(
        "mma.sync.aligned.m16n8k8.row.col.f32.tf32.tf32.f32 "
        "{%0,%1,%2,%3}, {%4,%5,%6,%7}, {%8,%9}, {%0,%1,%2,%3};"
        : "+f"(d[0]), "+f"(d[1]), "+f"(d[2]), "+f"(d[3])
        : "r"(a0), "r"(a1), "r"(a2), "r"(a3), "r"(b0), "r"(b1));
}

// ---------------------------------------------------------------------------
// tf32 MMA GEMM (R3-proven, unchanged): C = A(MxK) @ W(NxK)^T + bias.
// BM=128, BN=64, BK=32. 256 thr = 8 warps (4M x 2N), warp tile 32x32.
// MODE 0: A = x, scatter to g_q/g_k/g_v.  MODE 1: A = g_ctx, write out.
// ---------------------------------------------------------------------------
template<int MODE>
__global__ __launch_bounds__(256) void mma_gemm_kernel(
    const float* __restrict__ A_in, const float* __restrict__ W,
    const float* __restrict__ bias, float* __restrict__ out)
{
    __shared__ unsigned As[128 * 36];
    __shared__ unsigned Bs[64 * 36];

    const float* Ag = (MODE == 0) ? A_in : (const float*)g_ctx;

    const int K = CC;
    const int tid  = threadIdx.x;
    const int lane = tid & 31, warp = tid >> 5;
    const int mw = warp >> 1, nw = warp & 1;
    const int m0 = blockIdx.y * 128, n0 = blockIdx.x * 64;
    const int g = lane >> 2, t = lane & 3;

    float acc[2][4][4];
#pragma unroll
    for (int mt = 0; mt < 2; mt++)
#pragma unroll
        for (int nt = 0; nt < 4; nt++)
#pragma unroll
            for (int c = 0; c < 4; c++) acc[mt][nt][c] = 0.f;

    for (int k0 = 0; k0 < K; k0 += 32) {
#pragma unroll
        for (int i = 0; i < 4; i++) {
            int idx = tid + i * 256;
            int row = idx >> 3, kq = (idx & 7) << 2;
            float4 v = *(const float4*)(Ag + (size_t)(m0 + row) * K + k0 + kq);
            As[row * 36 + kq + 0] = f2tf32(v.x);
            As[row * 36 + kq + 1] = f2tf32(v.y);
            As[row * 36 + kq + 2] = f2tf32(v.z);
            As[row * 36 + kq + 3] = f2tf32(v.w);
        }
#pragma unroll
        for (int i = 0; i < 2; i++) {
            int idx = tid + i * 256;
            int row = idx >> 3, kq = (idx & 7) << 2;
            float4 v = *(const float4*)(W + (size_t)(n0 + row) * K + k0 + kq);
            Bs[row * 36 + kq + 0] = f2tf32(v.x);
            Bs[row * 36 + kq + 1] = f2tf32(v.y);
            Bs[row * 36 + kq + 2] = f2tf32(v.z);
            Bs[row * 36 + kq + 3] = f2tf32(v.w);
        }
        __syncthreads();

#pragma unroll
        for (int ks = 0; ks < 4; ks++) {
            const int kk = ks * 8;
            unsigned af[2][4], bf[4][2];
#pragma unroll
            for (int mt = 0; mt < 2; mt++) {
                int rm = mw * 32 + mt * 16;
                af[mt][0] = As[(rm     + g) * 36 + kk     + t];
                af[mt][1] = As[(rm + 8 + g) * 36 + kk     + t];
                af[mt][2] = As[(rm     + g) * 36 + kk + 4 + t];
                af[mt][3] = As[(rm + 8 + g) * 36 + kk + 4 + t];
            }
#pragma unroll
            for (int nt = 0; nt < 4; nt++) {
                int rn = nw * 32 + nt * 8;
                bf[nt][0] = Bs[(rn + g) * 36 + kk     + t];
                bf[nt][1] = Bs[(rn + g) * 36 + kk + 4 + t];
            }
#pragma unroll
            for (int mt = 0; mt < 2; mt++)
#pragma unroll
                for (int nt = 0; nt < 4; nt++)
                    mma8(acc[mt][nt], af[mt][0], af[mt][1], af[mt][2], af[mt][3],
                         bf[nt][0], bf[nt][1]);
        }
        __syncthreads();
    }

    if (MODE == 0) {
        const int s  = n0 / CC;
        const int hh = (n0 % CC) / DD;
        float* dst = (s == 0) ? g_q : ((s == 1) ? g_k : g_v);
#pragma unroll
        for (int mt = 0; mt < 2; mt++) {
            int m = m0 + mw * 32 + mt * 16 + g;
            int b0i = m >> 11, tok0 = m & 2047;
            int m1 = m + 8, b1i = m1 >> 11, tok1 = m1 & 2047;
#pragma unroll
            for (int nt = 0; nt < 4; nt++) {
                int dcol = nw * 32 + nt * 8 + t * 2;
                int n = n0 + dcol;
                float bv0 = bias[n], bv1 = bias[n + 1];
                float2 r0 = make_float2(acc[mt][nt][0] + bv0, acc[mt][nt][1] + bv1);
                float2 r1 = make_float2(acc[mt][nt][2] + bv0, acc[mt][nt][3] + bv1);
                *(float2*)(dst + ((size_t)(b0i * HH + hh) * TT + tok0) * DD + dcol) = r0;
                *(float2*)(dst + ((size_t)(b1i * HH + hh) * TT + tok1) * DD + dcol) = r1;
            }
        }
    } else {
#pragma unroll
        for (int mt = 0; mt < 2; mt++) {
            int m = m0 + mw * 32 + mt * 16 + g;
#pragma unroll
            for (int nt = 0; nt < 4; nt++) {
                int n = n0 + nw * 32 + nt * 8 + t * 2;
                float bv0 = bias[n], bv1 = bias[n + 1];
                float2 r0 = make_float2(acc[mt][nt][0] + bv0, acc[mt][nt][1] + bv1);
                float2 r1 = make_float2(acc[mt][nt][2] + bv0, acc[mt][nt][3] + bv1);
                *(float2*)(out + (size_t)m * CC + n) = r0;
                *(float2*)(out + (size_t)(m + 8) * CC + n) = r1;
            }
        }
    }
}

// ---------------------------------------------------------------------------
// tf32 MMA flash attention, 256 thr = 8 warps, 128 q-rows per CTA.
// Warp w owns q-rows [w*16, w*16+16) x all 64 k-cols; per-warp softmax code
// identical to the proven R3 version. K/V tiles feed 8 warps (2x reuse vs R3).
// Warps fully outside a k-block's causal range skip the compute section.
// smem: Qs[128][68] Ks[64][68] Vs[64][68] Ps[128][68] + pm[64]  = 104704 B
// ---------------------------------------------------------------------------
__global__ __launch_bounds__(256) void attn_mma_kernel(const int* __restrict__ amask)
{
    extern __shared__ unsigned smu[];
    unsigned* Qs = smu;                          // [128][68]
    unsigned* Ks = smu + 128 * 68;               // [64][68]
    unsigned* Vs = smu + 128 * 68 + 64 * 68;     // [64][68]
    unsigned* Ps = smu + 128 * 68 + 2 * 64 * 68; // [128][68] (warp-private rows)
    float*    pm = (float*)(smu + 2 * 128 * 68 + 2 * 64 * 68);

    const int bh = blockIdx.x, qb = blockIdx.y;  // qb: 0..15 (128-row tiles)
    const int b = bh / HH, h = bh % HH;
    const bool left = (h < NLEFT);

    const float* Qg = g_q + (size_t)bh * TT * DD;
    const float* Kg = g_k + (size_t)bh * TT * DD;
    const float* Vg = g_v + (size_t)bh * TT * DD;

    const int tid = threadIdx.x;
    const int lane = tid & 31, warp = tid >> 5;
    const int g = lane >> 2, t = lane & 3;
    const int rm = warp * 16;
    const int own_qb = qb * 2 + (warp >> 2);     // 64-granular block this warp owns

    // Load Q tile (scaled by 1/8, exact): 128 rows x 16 float4 = 2048 lds
#pragma unroll
    for (int i = 0; i < 8; i++) {
        int idx = tid + i * 256;
        int row = idx >> 4, d4 = (idx & 15) << 2;
        float4 v = *(const float4*)(Qg + (size_t)(qb * QT + row) * DD + d4);
        Qs[row * 68 + d4 + 0] = f2tf32(v.x * 0.125f);
        Qs[row * 68 + d4 + 1] = f2tf32(v.y * 0.125f);
        Qs[row * 68 + d4 + 2] = f2tf32(v.z * 0.125f);
        Qs[row * 68 + d4 + 3] = f2tf32(v.w * 0.125f);
    }

    float m_r[2] = {NEGF, NEGF};
    float l_r[2] = {0.f, 0.f};
    float O[8][4];
#pragma unroll
    for (int nt = 0; nt < 8; nt++)
#pragma unroll
        for (int c = 0; c < 4; c++) O[nt][c] = 0.f;

    // Union k-block range across the CTA's two 64-row halves.
    const int kb0 = left ? 0 : qb * 2;
    const int kb1 = left ? (qb * 2 + 1) : (TT / 64 - 1);
    const int qi0 = qb * QT + rm + g, qi1 = qi0 + 8;

    for (int kb = kb0; kb <= kb1; kb++) {
        __syncthreads();                       // prev iter done with Ks/Vs
#pragma unroll
        for (int i = 0; i < 4; i++) {          // K/V: 64 rows x 16 float4 each
            int idx = tid + i * 256;
            int row = idx >> 4, d4 = (idx & 15) << 2;
            float4 kv = *(const float4*)(Kg + (size_t)(kb * 64 + row) * DD + d4);
            Ks[row * 68 + d4 + 0] = f2tf32(kv.x);
            Ks[row * 68 + d4 + 1] = f2tf32(kv.y);
            Ks[row * 68 + d4 + 2] = f2tf32(kv.z);
            Ks[row * 68 + d4 + 3] = f2tf32(kv.w);
            float4 vv = *(const float4*)(Vg + (size_t)(kb * 64 + row) * DD + d4);
            Vs[row * 68 + d4 + 0] = f2tf32(vv.x);
            Vs[row * 68 + d4 + 1] = f2tf32(vv.y);
            Vs[row * 68 + d4 + 2] = f2tf32(vv.z);
            Vs[row * 68 + d4 + 3] = f2tf32(vv.w);
        }
        if (tid < 64)
            pm[tid] = amask[b * TT + kb * 64 + tid] ? 0.f : NEGF;
        __syncthreads();

        // Warp-uniform skip: block entirely outside this warp's causal range.
        const bool skip = left ? (kb > own_qb) : (kb < own_qb);
        if (skip) continue;

        // S = Qs @ Ks^T  (warp: 16 rows x 64 cols)
        float S[8][4];
#pragma unroll
        for (int nt = 0; nt < 8; nt++)
#pragma unroll
            for (int c = 0; c < 4; c++) S[nt][c] = 0.f;

#pragma unroll
        for (int ks = 0; ks < 8; ks++) {
            const int kk = ks * 8;
            unsigned a0 = Qs[(rm     + g) * 68 + kk     + t];
            unsigned a1 = Qs[(rm + 8 + g) * 68 + kk     + t];
            unsigned a2 = Qs[(rm     + g) * 68 + kk + 4 + t];
            unsigned a3 = Qs[(rm + 8 + g) * 68 + kk + 4 + t];
#pragma unroll
            for (int nt = 0; nt < 8; nt++) {
                unsigned b0 = Ks[(nt * 8 + g) * 68 + kk     + t];
                unsigned b1 = Ks[(nt * 8 + g) * 68 + kk + 4 + t];
                mma8(S[nt], a0, a1, a2, a3, b0, b1);
            }
        }

        // Mask + online softmax (C frag cols = t*2, t*2+1; rows g, g+8)
        float mx0 = NEGF, mx1 = NEGF;
        const bool diag = (kb == own_qb);
#pragma unroll
        for (int nt = 0; nt < 8; nt++) {
            int c0 = nt * 8 + t * 2;
            float p0 = pm[c0], p1 = pm[c0 + 1];
            float s0 = S[nt][0] + p0, s1 = S[nt][1] + p1;
            float s2 = S[nt][2] + p0, s3 = S[nt][3] + p1;
            if (diag) {
                int k0i = kb * 64 + c0, k1i = k0i + 1;
                if (left) {
                    if (k0i > qi0) s0 = NEGF;
                    if (k1i > qi0) s1 = NEGF;
                    if (k0i > qi1) s2 = NEGF;
                    if (k1i > qi1) s3 = NEGF;
                } else {
                    if (k0i < qi0) s0 = NEGF;
                    if (k1i < qi0) s1 = NEGF;
                    if (k0i < qi1) s2 = NEGF;
                    if (k1i < qi1) s3 = NEGF;
                }
            }
            S[nt][0] = s0; S[nt][1] = s1; S[nt][2] = s2; S[nt][3] = s3;
            mx0 = fmaxf(mx0, fmaxf(s0, s1));
            mx1 = fmaxf(mx1, fmaxf(s2, s3));
        }
        mx0 = fmaxf(mx0, __shfl_xor_sync(0xffffffffu, mx0, 1));
        mx0 = fmaxf(mx0, __shfl_xor_sync(0xffffffffu, mx0, 2));
        mx1 = fmaxf(mx1, __shfl_xor_sync(0xffffffffu, mx1, 1));
        mx1 = fmaxf(mx1, __shfl_xor_sync(0xffffffffu, mx1, 2));

        float mn0 = fmaxf(m_r[0], mx0), mn1 = fmaxf(m_r[1], mx1);
        float al0 = __expf(m_r[0] - mn0), al1 = __expf(m_r[1] - mn1);
        m_r[0] = mn0; m_r[1] = mn1;

        float rs0 = 0.f, rs1 = 0.f;
#pragma unroll
        for (int nt = 0; nt < 8; nt++) {
            float e0 = __expf(S[nt][0] - mn0), e1 = __expf(S[nt][1] - mn0);
            float e2 = __expf(S[nt][2] - mn1), e3 = __expf(S[nt][3] - mn1);
            S[nt][0] = e0; S[nt][1] = e1; S[nt][2] = e2; S[nt][3] = e3;
            rs0 += e0 + e1; rs1 += e2 + e3;
        }
        rs0 += __shfl_xor_sync(0xffffffffu, rs0, 1);
        rs0 += __shfl_xor_sync(0xffffffffu, rs0, 2);
        rs1 += __shfl_xor_sync(0xffffffffu, rs1, 1);
        rs1 += __shfl_xor_sync(0xffffffffu, rs1, 2);
        l_r[0] = l_r[0] * al0 + rs0;
        l_r[1] = l_r[1] * al1 + rs1;
#pragma unroll
        for (int nt = 0; nt < 8; nt++) {
            O[nt][0] *= al0; O[nt][1] *= al0;
            O[nt][2] *= al1; O[nt][3] *= al1;
        }

        // P -> smem (tf32, warp-private rows)
        __syncwarp();
#pragma unroll
        for (int nt = 0; nt < 8; nt++) {
            int c0 = nt * 8 + t * 2;
            Ps[(rm     + g) * 68 + c0    ] = f2tf32(S[nt][0]);
            Ps[(rm     + g) * 68 + c0 + 1] = f2tf32(S[nt][1]);
            Ps[(rm + 8 + g) * 68 + c0    ] = f2tf32(S[nt][2]);
            Ps[(rm + 8 + g) * 68 + c0 + 1] = f2tf32(S[nt][3]);
        }
        __syncwarp();

        // O += P @ V
#pragma unroll
        for (int ks = 0; ks < 8; ks++) {
            const int kk = ks * 8;
            unsigned a0 = Ps[(rm     + g) * 68 + kk     + t];
            unsigned a1 = Ps[(rm + 8 + g) * 68 + kk     + t];
            unsigned a2 = Ps[(rm     + g) * 68 + kk + 4 + t];
            unsigned a3 = Ps[(rm + 8 + g) * 68 + kk + 4 + t];
#pragma unroll
            for (int nt = 0; nt < 8; nt++) {
                unsigned b0 = Vs[(kk     + t) * 68 + nt * 8 + g];
                unsigned b1 = Vs[(kk + 4 + t) * 68 + nt * 8 + g];
                mma8(O[nt], a0, a1, a2, a3, b0, b1);
            }
        }
    }

    // Epilogue -> g_ctx
    float inv0 = 1.0f / l_r[0], inv1 = 1.0f / l_r[1];
    int t0 = qb * QT + rm + g, t1 = t0 + 8;
#pragma unroll
    for (int nt = 0; nt < 8; nt++) {
        int col = h * DD + nt * 8 + t * 2;
        *(float2*)(g_ctx + ((size_t)b * TT + t0) * CC + col) =
            make_float2(O[nt][0] * inv0, O[nt][1] * inv0);
        *(float2*)(g_ctx + ((size_t)b * TT + t1) * CC + col) =
            make_float2(O[nt][2] * inv1, O[nt][3] * inv1);
    }
}

// ---------------------------------------------------------------------------
extern "C" void kernel_launch(void* const* d_in, const int* in_sizes, int n_in,
                              void* d_out, int out_size)
{
    const float* x      = (const float*)d_in[0];
    const int*   amask  = (const int*)  d_in[1];
    const float* Wqkv_w = (const float*)d_in[2];
    const float* Wqkv_b = (const float*)d_in[3];
    const float* Wo_w   = (const float*)d_in[4];
    const float* Wo_b   = (const float*)d_in[5];
    float* out = (float*)d_out;

    (void)in_sizes; (void)n_in; (void)out_size;

    const int attn_smem = (2 * 128 * 68 + 2 * 64 * 68 + 64) * 4;   // 104704 B
    cudaFuncSetAttribute(attn_mma_kernel,
                         cudaFuncAttributeMaxDynamicSharedMemorySize, attn_smem);

    mma_gemm_kernel<0><<<dim3(N1 / 64, MM / 128), 256>>>(x, Wqkv_w, Wqkv_b, nullptr);
    attn_mma_kernel<<<dim3(BB * HH, TT / QT), 256, attn_smem>>>(amask);
    mma_gemm_kernel<1><<<dim3(CC / 64, MM / 128), 256>>>(nullptr, Wo_w, Wo_b, out);
}

// round 8
// speedup vs baseline: 1.7811x; 1.0499x over previous
#include <cuda_runtime.h>
#include <cstdint>

#define BB 2
#define TT 2048
#define CC 768
#define HH 12
#define NLEFT 6
#define DD 64
#define MM (BB*TT)
#define N1 (3*CC)

#define NEGF (-3.402823466e38f)

// Scratch (device globals: allocation-free)
__device__ float g_q[BB*HH*TT*DD];
__device__ float g_k[BB*HH*TT*DD];
__device__ float g_v[BB*HH*TT*DD];
__device__ float g_ctx[BB*TT*CC];

__device__ __forceinline__ unsigned f2tf32(float f) {
    unsigned r;
    asm("cvt.rna.tf32.f32 %0, %1;" : "=r"(r) : "f"(f));
    return r;
}

__device__ __forceinline__ uint32_t smem_u32(const void* p) {
    uint32_t a;
    asm("{ .reg .u64 t; cvta.to.shared.u64 t, %1; cvt.u32.u64 %0, t; }"
        : "=r"(a) : "l"(p));
    return a;
}

// 4x (8x8 b16-view) matrices; for tf32 words: lane l <- row l/4, word l%4.
__device__ __forceinline__ void ldsm4(unsigned& r0, unsigned& r1,
                                      unsigned& r2, unsigned& r3, uint32_t addr) {
    asm volatile("ldmatrix.sync.aligned.m8n8.x4.shared.b16 {%0,%1,%2,%3}, [%4];"
                 : "=r"(r0), "=r"(r1), "=r"(r2), "=r"(r3) : "r"(addr));
}

// D += A(16x8,row) * B(8x8,col)  tf32 -> f32
__device__ __forceinline__ void mma8(float* d,
    unsigned a0, unsigned a1, unsigned a2, unsigned a3,
    unsigned b0, unsigned b1)
{
    asm volatile(
        "mma.sync.aligned.m16n8k8.row.col.f32.tf32.tf32.f32 "
        "{%0,%1,%2,%3}, {%4,%5,%6,%7}, {%8,%9}, {%0,%1,%2,%3};"
        : "+f"(d[0]), "+f"(d[1]), "+f"(d[2]), "+f"(d[3])
        : "r"(a0), "r"(a1), "r"(a2), "r"(a3), "r"(b0), "r"(b1));
}

// ---------------------------------------------------------------------------
// tf32 MMA GEMM (R3 structure, fragments via ldmatrix).
// BM=128, BN=64, BK=32. 256 thr = 8 warps (4M x 2N), warp tile 32x32.
// MODE 0: A = x, scatter to g_q/g_k/g_v.  MODE 1: A = g_ctx, write out.
// ---------------------------------------------------------------------------
template<int MODE>
__global__ __launch_bounds__(256) void mma_gemm_kernel(
    const float* __restrict__ A_in, const float* __restrict__ W,
    const float* __restrict__ bias, float* __restrict__ out)
{
    __shared__ unsigned As[128 * 36];
    __shared__ unsigned Bs[64 * 36];

    const float* Ag = (MODE == 0) ? A_in : (const float*)g_ctx;

    const int K = CC;
    const int tid  = threadIdx.x;
    const int lane = tid & 31, warp = tid >> 5;
    const int mw = warp >> 1, nw = warp & 1;
    const int m0 = blockIdx.y * 128, n0 = blockIdx.x * 64;
    const int g = lane >> 2, t = lane & 3;

    // ldmatrix per-lane row configs
    const int a_row = (lane & 7) + ((lane >> 3) & 1) * 8;  // A: m0..7/m8..15
    const int a_ws  = (lane >> 4) * 4;                     // A: words 0-3 / 4-7
    const int b_row = (lane & 7) + ((lane >> 4) << 3);     // B: nt pair rows
    const int b_ws  = ((lane >> 3) & 1) * 4;

    const uint32_t asb = smem_u32(As), bsb = smem_u32(Bs);
    const uint32_t aad0 = asb + (uint32_t)(((mw * 32 + a_row) * 36 + a_ws) << 2);
    const uint32_t aad1 = aad0 + 16 * 36 * 4;
    const uint32_t bad0 = bsb + (uint32_t)(((nw * 32 + b_row) * 36 + b_ws) << 2);
    const uint32_t bad1 = bad0 + 16 * 36 * 4;

    float acc[2][4][4];
#pragma unroll
    for (int mt = 0; mt < 2; mt++)
#pragma unroll
        for (int nt = 0; nt < 4; nt++)
#pragma unroll
            for (int c = 0; c < 4; c++) acc[mt][nt][c] = 0.f;

    for (int k0 = 0; k0 < K; k0 += 32) {
#pragma unroll
        for (int i = 0; i < 4; i++) {
            int idx = tid + i * 256;
            int row = idx >> 3, kq = (idx & 7) << 2;
            float4 v = *(const float4*)(Ag + (size_t)(m0 + row) * K + k0 + kq);
            As[row * 36 + kq + 0] = f2tf32(v.x);
            As[row * 36 + kq + 1] = f2tf32(v.y);
            As[row * 36 + kq + 2] = f2tf32(v.z);
            As[row * 36 + kq + 3] = f2tf32(v.w);
        }
#pragma unroll
        for (int i = 0; i < 2; i++) {
            int idx = tid + i * 256;
            int row = idx >> 3, kq = (idx & 7) << 2;
            float4 v = *(const float4*)(W + (size_t)(n0 + row) * K + k0 + kq);
            Bs[row * 36 + kq + 0] = f2tf32(v.x);
            Bs[row * 36 + kq + 1] = f2tf32(v.y);
            Bs[row * 36 + kq + 2] = f2tf32(v.z);
            Bs[row * 36 + kq + 3] = f2tf32(v.w);
        }
        __syncthreads();

#pragma unroll
        for (int ks = 0; ks < 4; ks++) {
            const uint32_t ko = ks * 32;   // 8 words
            unsigned a0[4], a1[4], bA[4], bB[4];
            ldsm4(a0[0], a0[1], a0[2], a0[3], aad0 + ko);
            ldsm4(a1[0], a1[1], a1[2], a1[3], aad1 + ko);
            ldsm4(bA[0], bA[1], bA[2], bA[3], bad0 + ko);  // b0/b1 nt0, b0/b1 nt1
            ldsm4(bB[0], bB[1], bB[2], bB[3], bad1 + ko);  // nt2, nt3
            mma8(acc[0][0], a0[0], a0[1], a0[2], a0[3], bA[0], bA[1]);
            mma8(acc[0][1], a0[0], a0[1], a0[2], a0[3], bA[2], bA[3]);
            mma8(acc[0][2], a0[0], a0[1], a0[2], a0[3], bB[0], bB[1]);
            mma8(acc[0][3], a0[0], a0[1], a0[2], a0[3], bB[2], bB[3]);
            mma8(acc[1][0], a1[0], a1[1], a1[2], a1[3], bA[0], bA[1]);
            mma8(acc[1][1], a1[0], a1[1], a1[2], a1[3], bA[2], bA[3]);
            mma8(acc[1][2], a1[0], a1[1], a1[2], a1[3], bB[0], bB[1]);
            mma8(acc[1][3], a1[0], a1[1], a1[2], a1[3], bB[2], bB[3]);
        }
        __syncthreads();
    }

    // Epilogue. C frag: rows g, g+8 ; cols t*2, t*2+1.
    if (MODE == 0) {
        const int s  = n0 / CC;
        const int hh = (n0 % CC) / DD;
        float* dst = (s == 0) ? g_q : ((s == 1) ? g_k : g_v);
#pragma unroll
        for (int mt = 0; mt < 2; mt++) {
            int m = m0 + mw * 32 + mt * 16 + g;
            int b0i = m >> 11, tok0 = m & 2047;
            int m1 = m + 8, b1i = m1 >> 11, tok1 = m1 & 2047;
#pragma unroll
            for (int nt = 0; nt < 4; nt++) {
                int dcol = nw * 32 + nt * 8 + t * 2;
                int n = n0 + dcol;
                float bv0 = bias[n], bv1 = bias[n + 1];
                float2 r0 = make_float2(acc[mt][nt][0] + bv0, acc[mt][nt][1] + bv1);
                float2 r1 = make_float2(acc[mt][nt][2] + bv0, acc[mt][nt][3] + bv1);
                *(float2*)(dst + ((size_t)(b0i * HH + hh) * TT + tok0) * DD + dcol) = r0;
                *(float2*)(dst + ((size_t)(b1i * HH + hh) * TT + tok1) * DD + dcol) = r1;
            }
        }
    } else {
#pragma unroll
        for (int mt = 0; mt < 2; mt++) {
            int m = m0 + mw * 32 + mt * 16 + g;
#pragma unroll
            for (int nt = 0; nt < 4; nt++) {
                int n = n0 + nw * 32 + nt * 8 + t * 2;
                float bv0 = bias[n], bv1 = bias[n + 1];
                float2 r0 = make_float2(acc[mt][nt][0] + bv0, acc[mt][nt][1] + bv1);
                float2 r1 = make_float2(acc[mt][nt][2] + bv0, acc[mt][nt][3] + bv1);
                *(float2*)(out + (size_t)m * CC + n) = r0;
                *(float2*)(out + (size_t)(m + 8) * CC + n) = r1;
            }
        }
    }
}

// ---------------------------------------------------------------------------
// tf32 MMA flash attention (R3 structure; Q/K/P fragments via ldmatrix).
// 128 thr = 4 warps; warp owns 16 q-rows x 64 k-cols. Q pre-scaled by 1/8.
// smem: Qs,Ks,Vs,Ps [64][68] tf32 + pm[64] f32.
// ---------------------------------------------------------------------------
__global__ __launch_bounds__(128) void attn_mma_kernel(const int* __restrict__ amask)
{
    extern __shared__ unsigned smu[];
    unsigned* Qs = smu;                 // [q][d]
    unsigned* Ks = smu + 64 * 68;       // [kcol][d]
    unsigned* Vs = smu + 2 * 64 * 68;   // [kseq][d]
    unsigned* Ps = smu + 3 * 64 * 68;   // [q][kseq]  (warp-private rows)
    float*    pm = (float*)(smu + 4 * 64 * 68);

    const int bh = blockIdx.x, qb = blockIdx.y;
    const int b = bh / HH, h = bh % HH;
    const bool left = (h < NLEFT);

    const float* Qg = g_q + (size_t)bh * TT * DD;
    const float* Kg = g_k + (size_t)bh * TT * DD;
    const float* Vg = g_v + (size_t)bh * TT * DD;

    const int tid = threadIdx.x;
    const int lane = tid & 31, warp = tid >> 5;
    const int g = lane >> 2, t = lane & 3;
    const int rm = warp * 16;

    // ldmatrix per-lane configs (stride 68)
    const int a_row = (lane & 7) + ((lane >> 3) & 1) * 8;
    const int a_ws  = (lane >> 4) * 4;
    const int b_row = (lane & 7) + ((lane >> 4) << 3);
    const int b_ws  = ((lane >> 3) & 1) * 4;

    const uint32_t qsb = smem_u32(Qs), ksb = smem_u32(Ks), psb = smem_u32(Ps);
    const uint32_t qad = qsb + (uint32_t)(((rm + a_row) * 68 + a_ws) << 2);
    const uint32_t pad = psb + (uint32_t)(((rm + a_row) * 68 + a_ws) << 2);
    uint32_t kad[4];
#pragma unroll
    for (int p = 0; p < 4; p++)
        kad[p] = ksb + (uint32_t)(((p * 16 + b_row) * 68 + b_ws) << 2);

    // Load Q (scaled by 1/8, exact)
#pragma unroll
    for (int i = 0; i < 8; i++) {
        int idx = tid + i * 128;
        int row = idx >> 4, d4 = (idx & 15) << 2;
        float4 v = *(const float4*)(Qg + (size_t)(qb * 64 + row) * DD + d4);
        Qs[row * 68 + d4 + 0] = f2tf32(v.x * 0.125f);
        Qs[row * 68 + d4 + 1] = f2tf32(v.y * 0.125f);
        Qs[row * 68 + d4 + 2] = f2tf32(v.z * 0.125f);
        Qs[row * 68 + d4 + 3] = f2tf32(v.w * 0.125f);
    }

    float m_r[2] = {NEGF, NEGF};
    float l_r[2] = {0.f, 0.f};
    float O[8][4];
#pragma unroll
    for (int nt = 0; nt < 8; nt++)
#pragma unroll
        for (int c = 0; c < 4; c++) O[nt][c] = 0.f;

    const int kb0 = left ? 0 : qb;
    const int kb1 = left ? qb : (TT / 64 - 1);
    const int qi0 = qb * 64 + rm + g, qi1 = qi0 + 8;

    for (int kb = kb0; kb <= kb1; kb++) {
        __syncthreads();                       // prev iter done with Ks/Vs
#pragma unroll
        for (int i = 0; i < 8; i++) {
            int idx = tid + i * 128;
            int row = idx >> 4, d4 = (idx & 15) << 2;
            float4 kv = *(const float4*)(Kg + (size_t)(kb * 64 + row) * DD + d4);
            Ks[row * 68 + d4 + 0] = f2tf32(kv.x);
            Ks[row * 68 + d4 + 1] = f2tf32(kv.y);
            Ks[row * 68 + d4 + 2] = f2tf32(kv.z);
            Ks[row * 68 + d4 + 3] = f2tf32(kv.w);
            float4 vv = *(const float4*)(Vg + (size_t)(kb * 64 + row) * DD + d4);
            Vs[row * 68 + d4 + 0] = f2tf32(vv.x);
            Vs[row * 68 + d4 + 1] = f2tf32(vv.y);
            Vs[row * 68 + d4 + 2] = f2tf32(vv.z);
            Vs[row * 68 + d4 + 3] = f2tf32(vv.w);
        }
        if (tid < 64)
            pm[tid] = amask[b * TT + kb * 64 + tid] ? 0.f : NEGF;
        __syncthreads();

        // S = Qs @ Ks^T  (warp: 16 rows x 64 cols)
        float S[8][4];
#pragma unroll
        for (int nt = 0; nt < 8; nt++)
#pragma unroll
            for (int c = 0; c < 4; c++) S[nt][c] = 0.f;

#pragma unroll
        for (int ks = 0; ks < 8; ks++) {
            const uint32_t ko = ks * 32;
            unsigned a0, a1, a2, a3;
            ldsm4(a0, a1, a2, a3, qad + ko);
#pragma unroll
            for (int p = 0; p < 4; p++) {
                unsigned k0, k1, k2, k3;
                ldsm4(k0, k1, k2, k3, kad[p] + ko);
                mma8(S[2 * p],     a0, a1, a2, a3, k0, k1);
                mma8(S[2 * p + 1], a0, a1, a2, a3, k2, k3);
            }
        }

        // Mask + online softmax (C frag cols = t*2, t*2+1; rows g, g+8)
        float mx0 = NEGF, mx1 = NEGF;
        const bool diag = (kb == qb);
#pragma unroll
        for (int nt = 0; nt < 8; nt++) {
            int c0 = nt * 8 + t * 2;
            float p0 = pm[c0], p1 = pm[c0 + 1];
            float s0 = S[nt][0] + p0, s1 = S[nt][1] + p1;
            float s2 = S[nt][2] + p0, s3 = S[nt][3] + p1;
            if (diag) {
                int k0i = kb * 64 + c0, k1i = k0i + 1;
                if (left) {
                    if (k0i > qi0) s0 = NEGF;
                    if (k1i > qi0) s1 = NEGF;
                    if (k0i > qi1) s2 = NEGF;
                    if (k1i > qi1) s3 = NEGF;
                } else {
                    if (k0i < qi0) s0 = NEGF;
                    if (k1i < qi0) s1 = NEGF;
                    if (k0i < qi1) s2 = NEGF;
                    if (k1i < qi1) s3 = NEGF;
                }
            }
            S[nt][0] = s0; S[nt][1] = s1; S[nt][2] = s2; S[nt][3] = s3;
            mx0 = fmaxf(mx0, fmaxf(s0, s1));
            mx1 = fmaxf(mx1, fmaxf(s2, s3));
        }
        mx0 = fmaxf(mx0, __shfl_xor_sync(0xffffffffu, mx0, 1));
        mx0 = fmaxf(mx0, __shfl_xor_sync(0xffffffffu, mx0, 2));
        mx1 = fmaxf(mx1, __shfl_xor_sync(0xffffffffu, mx1, 1));
        mx1 = fmaxf(mx1, __shfl_xor_sync(0xffffffffu, mx1, 2));

        float mn0 = fmaxf(m_r[0], mx0), mn1 = fmaxf(m_r[1], mx1);
        float al0 = __expf(m_r[0] - mn0), al1 = __expf(m_r[1] - mn1);
        m_r[0] = mn0; m_r[1] = mn1;

        float rs0 = 0.f, rs1 = 0.f;
#pragma unroll
        for (int nt = 0; nt < 8; nt++) {
            float e0 = __expf(S[nt][0] - mn0), e1 = __expf(S[nt][1] - mn0);
            float e2 = __expf(S[nt][2] - mn1), e3 = __expf(S[nt][3] - mn1);
            S[nt][0] = e0; S[nt][1] = e1; S[nt][2] = e2; S[nt][3] = e3;
            rs0 += e0 + e1; rs1 += e2 + e3;
        }
        rs0 += __shfl_xor_sync(0xffffffffu, rs0, 1);
        rs0 += __shfl_xor_sync(0xffffffffu, rs0, 2);
        rs1 += __shfl_xor_sync(0xffffffffu, rs1, 1);
        rs1 += __shfl_xor_sync(0xffffffffu, rs1, 2);
        l_r[0] = l_r[0] * al0 + rs0;
        l_r[1] = l_r[1] * al1 + rs1;
#pragma unroll
        for (int nt = 0; nt < 8; nt++) {
            O[nt][0] *= al0; O[nt][1] *= al0;
            O[nt][2] *= al1; O[nt][3] *= al1;
        }

        // P -> smem (tf32, warp-private rows)
        __syncwarp();
#pragma unroll
        for (int nt = 0; nt < 8; nt++) {
            int c0 = nt * 8 + t * 2;
            Ps[(rm     + g) * 68 + c0    ] = f2tf32(S[nt][0]);
            Ps[(rm     + g) * 68 + c0 + 1] = f2tf32(S[nt][1]);
            Ps[(rm + 8 + g) * 68 + c0    ] = f2tf32(S[nt][2]);
            Ps[(rm + 8 + g) * 68 + c0 + 1] = f2tf32(S[nt][3]);
        }
        __syncwarp();

        // O += P @ V  (P frag via ldmatrix; V frags scalar)
#pragma unroll
        for (int ks = 0; ks < 8; ks++) {
            const int kk = ks * 8;
            unsigned a0, a1, a2, a3;
            ldsm4(a0, a1, a2, a3, pad + ks * 32);
#pragma unroll
            for (int nt = 0; nt < 8; nt++) {
                unsigned b0 = Vs[(kk     + t) * 68 + nt * 8 + g];
                unsigned b1 = Vs[(kk + 4 + t) * 68 + nt * 8 + g];
                mma8(O[nt], a0, a1, a2, a3, b0, b1);
            }
        }
    }

    // Epilogue -> g_ctx
    float inv0 = 1.0f / l_r[0], inv1 = 1.0f / l_r[1];
    int t0 = qb * 64 + rm + g, t1 = t0 + 8;
#pragma unroll
    for (int nt = 0; nt < 8; nt++) {
        int col = h * DD + nt * 8 + t * 2;
        *(float2*)(g_ctx + ((size_t)b * TT + t0) * CC + col) =
            make_float2(O[nt][0] * inv0, O[nt][1] * inv0);
        *(float2*)(g_ctx + ((size_t)b * TT + t1) * CC + col) =
            make_float2(O[nt][2] * inv1, O[nt][3] * inv1);
    }
}

// ---------------------------------------------------------------------------
extern "C" void kernel_launch(void* const* d_in, const int* in_sizes, int n_in,
                              void* d_out, int out_size)
{
    const float* x      = (const float*)d_in[0];
    const int*   amask  = (const int*)  d_in[1];
    const float* Wqkv_w = (const float*)d_in[2];
    const float* Wqkv_b = (const float*)d_in[3];
    const float* Wo_w   = (const float*)d_in[4];
    const float* Wo_b   = (const float*)d_in[5];
    float* out = (float*)d_out;

    (void)in_sizes; (void)n_in; (void)out_size;

    const int attn_smem = 4 * 64 * 68 * 4 + 64 * 4;   // 69888 B
    cudaFuncSetAttribute(attn_mma_kernel,
                         cudaFuncAttributeMaxDynamicSharedMemorySize, attn_smem);

    mma_gemm_kernel<0><<<dim3(N1 / 64, MM / 128), 256>>>(x, Wqkv_w, Wqkv_b, nullptr);
    attn_mma_kernel<<<dim3(BB * HH, TT / 64), 128, attn_smem>>>(amask);
    mma_gemm_kernel<1><<<dim3(CC / 64, MM / 128), 256>>>(nullptr, Wo_w, Wo_b, out);
}

// round 10
// speedup vs baseline: 1.9209x; 1.0785x over previous
#include <cuda_runtime.h>
#include <cstdint>

#define BB 2
#define TT 2048
#define CC 768
#define HH 12
#define NLEFT 6
#define DD 64
#define MM (BB*TT)
#define N1 (3*CC)

#define NEGF (-3.402823466e38f)

// Scratch (device globals: allocation-free)
__device__ float g_q[BB*HH*TT*DD];
__device__ float g_k[BB*HH*TT*DD];
__device__ float g_v[BB*HH*TT*DD];
__device__ float g_ctx[BB*TT*CC];
// Pre-rounded (tf32) copies of GEMM inputs
__device__ float g_xr[MM*CC];
__device__ float g_w1r[N1*CC];
__device__ float g_w2r[CC*CC];

__device__ __forceinline__ unsigned f2tf32(float f) {
    unsigned r;
    asm("cvt.rna.tf32.f32 %0, %1;" : "=r"(r) : "f"(f));
    return r;
}
__device__ __forceinline__ float rnd(float f) { return __uint_as_float(f2tf32(f)); }

__device__ __forceinline__ uint32_t smem_u32(const void* p) {
    uint32_t a;
    asm("{ .reg .u64 t; cvta.to.shared.u64 t, %1; cvt.u32.u64 %0, t; }"
        : "=r"(a) : "l"(p));
    return a;
}
__device__ __forceinline__ void cpa16(uint32_t d, const void* s) {
    asm volatile("cp.async.cg.shared.global [%0], [%1], 16;" :: "r"(d), "l"(s));
}
#define CPA_COMMIT() asm volatile("cp.async.commit_group;" ::: "memory")
#define CPA_WAIT(n)  asm volatile("cp.async.wait_group %0;" :: "n"(n) : "memory")

__device__ __forceinline__ void ldsm4(unsigned& r0, unsigned& r1,
                                      unsigned& r2, unsigned& r3, uint32_t addr) {
    asm volatile("ldmatrix.sync.aligned.m8n8.x4.shared.b16 {%0,%1,%2,%3}, [%4];"
                 : "=r"(r0), "=r"(r1), "=r"(r2), "=r"(r3) : "r"(addr));
}
__device__ __forceinline__ void mma8(float* d,
    unsigned a0, unsigned a1, unsigned a2, unsigned a3,
    unsigned b0, unsigned b1)
{
    asm volatile(
        "mma.sync.aligned.m16n8k8.row.col.f32.tf32.tf32.f32 "
        "{%0,%1,%2,%3}, {%4,%5,%6,%7}, {%8,%9}, {%0,%1,%2,%3};"
        : "+f"(d[0]), "+f"(d[1]), "+f"(d[2]), "+f"(d[3])
        : "r"(a0), "r"(a1), "r"(a2), "r"(a3), "r"(b0), "r"(b1));
}

// ---------------------------------------------------------------------------
// Pre-round inputs to tf32 (idempotent wrt all downstream cvt.rna).
// ---------------------------------------------------------------------------
#define XN4  (MM*CC/4)
#define W1N4 (N1*CC/4)
#define W2N4 (CC*CC/4)
#define PRN4 (XN4 + W1N4 + W2N4)

__global__ __launch_bounds__(256) void preround_kernel(
    const float* __restrict__ x, const float* __restrict__ w1,
    const float* __restrict__ w2)
{
    int i = blockIdx.x * 256 + threadIdx.x;
    if (i >= PRN4) return;
    const float* src; float* dst; int j;
    if (i < XN4)              { src = x;  dst = g_xr;  j = i; }
    else if (i < XN4 + W1N4)  { src = w1; dst = g_w1r; j = i - XN4; }
    else                      { src = w2; dst = g_w2r; j = i - XN4 - W1N4; }
    float4 v = *(const float4*)(src + (size_t)j * 4);
    float4 o = make_float4(rnd(v.x), rnd(v.y), rnd(v.z), rnd(v.w));
    *(float4*)(dst + (size_t)j * 4) = o;
}

// ---------------------------------------------------------------------------
// tf32 MMA GEMM, cp.async double-buffered: C = A(MxK) @ W(NxK)^T + bias.
// BM=128, BN=64, BK=32. 256 thr = 8 warps (4M x 2N). A/W pre-rounded tf32,
// selected INSIDE the kernel (device symbols are not valid host args).
// MODE 0: A = g_xr, W = g_w1r, scatter tf32-rounded to g_q/g_k/g_v.
// MODE 1: A = g_ctx (rounded by attn), W = g_w2r, write out (full fp32).
// ---------------------------------------------------------------------------
#define GW_A   (128*36)
#define GW_B   (64*36)
#define GW_PR  (GW_A + GW_B)          // 6912 words / buffer
#define GEMM_SMEM (2 * GW_PR * 4)     // 55296 B
#define NCH (CC/32)                   // 24

template<int MODE>
__global__ __launch_bounds__(256) void mma_gemm_kernel(
    const float* __restrict__ bias, float* __restrict__ out)
{
    extern __shared__ unsigned sm[];

    const float* Ag = (MODE == 0) ? (const float*)g_xr  : (const float*)g_ctx;
    const float* W  = (MODE == 0) ? (const float*)g_w1r : (const float*)g_w2r;

    const int K = CC;
    const int tid  = threadIdx.x;
    const int lane = tid & 31, warp = tid >> 5;
    const int mw = warp >> 1, nw = warp & 1;
    const int m0 = blockIdx.y * 128, n0 = blockIdx.x * 64;
    const int g = lane >> 2, t = lane & 3;

    const uint32_t smb = smem_u32(sm);

    // ldmatrix per-lane row configs
    const int a_row = (lane & 7) + ((lane >> 3) & 1) * 8;
    const int a_ws  = (lane >> 4) * 4;
    const int b_row = (lane & 7) + ((lane >> 4) << 3);
    const int b_ws  = ((lane >> 3) & 1) * 4;

    const uint32_t aad0 = smb + (uint32_t)(((mw * 32 + a_row) * 36 + a_ws) << 2);
    const uint32_t aad1 = aad0 + 16 * 36 * 4;
    const uint32_t bad0 = smb + (uint32_t)((GW_A + (nw * 32 + b_row) * 36 + b_ws) << 2);
    const uint32_t bad1 = bad0 + 16 * 36 * 4;

    // Loader geometry
    const int lrow = tid >> 3;          // rows 0..31, +32 per i
    const int lkq  = (tid & 7) << 2;

    float acc[2][4][4];
#pragma unroll
    for (int mt = 0; mt < 2; mt++)
#pragma unroll
        for (int nt = 0; nt < 4; nt++)
#pragma unroll
            for (int c = 0; c < 4; c++) acc[mt][nt][c] = 0.f;

    // prefetch chunk 0 into buffer 0
    {
        uint32_t ab = smb, bb = smb + GW_A * 4;
#pragma unroll
        for (int i = 0; i < 4; i++) {
            int row = lrow + i * 32;
            cpa16(ab + (uint32_t)((row * 36 + lkq) << 2),
                  Ag + (size_t)(m0 + row) * K + lkq);
        }
#pragma unroll
        for (int i = 0; i < 2; i++) {
            int row = lrow + i * 32;
            cpa16(bb + (uint32_t)((row * 36 + lkq) << 2),
                  W + (size_t)(n0 + row) * K + lkq);
        }
        CPA_COMMIT();
    }

    for (int c = 0; c < NCH; c++) {
        const uint32_t bo = (uint32_t)(c & 1) * (GW_PR * 4);
        if (c + 1 < NCH) {
            const int k0n = (c + 1) * 32;
            const uint32_t nbo = (uint32_t)((c + 1) & 1) * (GW_PR * 4);
            uint32_t ab = smb + nbo, bb = smb + nbo + GW_A * 4;
#pragma unroll
            for (int i = 0; i < 4; i++) {
                int row = lrow + i * 32;
                cpa16(ab + (uint32_t)((row * 36 + lkq) << 2),
                      Ag + (size_t)(m0 + row) * K + k0n + lkq);
            }
#pragma unroll
            for (int i = 0; i < 2; i++) {
                int row = lrow + i * 32;
                cpa16(bb + (uint32_t)((row * 36 + lkq) << 2),
                      W + (size_t)(n0 + row) * K + k0n + lkq);
            }
            CPA_COMMIT();
            CPA_WAIT(1);
        } else {
            CPA_WAIT(0);
        }
        __syncthreads();

#pragma unroll
        for (int ks = 0; ks < 4; ks++) {
            const uint32_t ko = bo + ks * 32;
            unsigned a0[4], a1[4], bA[4], bBr[4];
            ldsm4(a0[0], a0[1], a0[2], a0[3], aad0 + ko);
            ldsm4(a1[0], a1[1], a1[2], a1[3], aad1 + ko);
            ldsm4(bA[0], bA[1], bA[2], bA[3], bad0 + ko);
            ldsm4(bBr[0], bBr[1], bBr[2], bBr[3], bad1 + ko);
            mma8(acc[0][0], a0[0], a0[1], a0[2], a0[3], bA[0], bA[1]);
            mma8(acc[0][1], a0[0], a0[1], a0[2], a0[3], bA[2], bA[3]);
            mma8(acc[0][2], a0[0], a0[1], a0[2], a0[3], bBr[0], bBr[1]);
            mma8(acc[0][3], a0[0], a0[1], a0[2], a0[3], bBr[2], bBr[3]);
            mma8(acc[1][0], a1[0], a1[1], a1[2], a1[3], bA[0], bA[1]);
            mma8(acc[1][1], a1[0], a1[1], a1[2], a1[3], bA[2], bA[3]);
            mma8(acc[1][2], a1[0], a1[1], a1[2], a1[3], bBr[0], bBr[1]);
            mma8(acc[1][3], a1[0], a1[1], a1[2], a1[3], bBr[2], bBr[3]);
        }
        __syncthreads();
    }

    // Epilogue. C frag: rows g, g+8 ; cols t*2, t*2+1.
    if (MODE == 0) {
        const int s  = n0 / CC;
        const int hh = (n0 % CC) / DD;
        float* dst = (s == 0) ? g_q : ((s == 1) ? g_k : g_v);
#pragma unroll
        for (int mt = 0; mt < 2; mt++) {
            int m = m0 + mw * 32 + mt * 16 + g;
            int b0i = m >> 11, tok0 = m & 2047;
            int m1 = m + 8, b1i = m1 >> 11, tok1 = m1 & 2047;
#pragma unroll
            for (int nt = 0; nt < 4; nt++) {
                int dcol = nw * 32 + nt * 8 + t * 2;
                int n = n0 + dcol;
                float bv0 = bias[n], bv1 = bias[n + 1];
                float2 r0 = make_float2(rnd(acc[mt][nt][0] + bv0), rnd(acc[mt][nt][1] + bv1));
                float2 r1 = make_float2(rnd(acc[mt][nt][2] + bv0), rnd(acc[mt][nt][3] + bv1));
                *(float2*)(dst + ((size_t)(b0i * HH + hh) * TT + tok0) * DD + dcol) = r0;
                *(float2*)(dst + ((size_t)(b1i * HH + hh) * TT + tok1) * DD + dcol) = r1;
            }
        }
    } else {
#pragma unroll
        for (int mt = 0; mt < 2; mt++) {
            int m = m0 + mw * 32 + mt * 16 + g;
#pragma unroll
            for (int nt = 0; nt < 4; nt++) {
                int n = n0 + nw * 32 + nt * 8 + t * 2;
                float bv0 = bias[n], bv1 = bias[n + 1];
                float2 r0 = make_float2(acc[mt][nt][0] + bv0, acc[mt][nt][1] + bv1);
                float2 r1 = make_float2(acc[mt][nt][2] + bv0, acc[mt][nt][3] + bv1);
                *(float2*)(out + (size_t)m * CC + n) = r0;
                *(float2*)(out + (size_t)(m + 8) * CC + n) = r1;
            }
        }
    }
}

// ---------------------------------------------------------------------------
// tf32 MMA flash attention (R8-proven; epilogue stores tf32-rounded ctx).
// 128 thr = 4 warps; warp owns 16 q-rows x 64 k-cols. Q pre-scaled by 1/8.
// ---------------------------------------------------------------------------
__global__ __launch_bounds__(128) void attn_mma_kernel(const int* __restrict__ amask)
{
    extern __shared__ unsigned smu[];
    unsigned* Qs = smu;                 // [q][d]
    unsigned* Ks = smu + 64 * 68;       // [kcol][d]
    unsigned* Vs = smu + 2 * 64 * 68;   // [kseq][d]
    unsigned* Ps = smu + 3 * 64 * 68;   // [q][kseq]  (warp-private rows)
    float*    pm = (float*)(smu + 4 * 64 * 68);

    const int bh = blockIdx.x, qb = blockIdx.y;
    const int b = bh / HH, h = bh % HH;
    const bool left = (h < NLEFT);

    const float* Qg = g_q + (size_t)bh * TT * DD;
    const float* Kg = g_k + (size_t)bh * TT * DD;
    const float* Vg = g_v + (size_t)bh * TT * DD;

    const int tid = threadIdx.x;
    const int lane = tid & 31, warp = tid >> 5;
    const int g = lane >> 2, t = lane & 3;
    const int rm = warp * 16;

    const int a_row = (lane & 7) + ((lane >> 3) & 1) * 8;
    const int a_ws  = (lane >> 4) * 4;
    const int b_row = (lane & 7) + ((lane >> 4) << 3);
    const int b_ws  = ((lane >> 3) & 1) * 4;

    const uint32_t qsb = smem_u32(Qs), ksb = smem_u32(Ks), psb = smem_u32(Ps);
    const uint32_t qad = qsb + (uint32_t)(((rm + a_row) * 68 + a_ws) << 2);
    const uint32_t padr = psb + (uint32_t)(((rm + a_row) * 68 + a_ws) << 2);
    uint32_t kad[4];
#pragma unroll
    for (int p = 0; p < 4; p++)
        kad[p] = ksb + (uint32_t)(((p * 16 + b_row) * 68 + b_ws) << 2);

    // Load Q (scaled by 1/8, exact; inputs already tf32-rounded)
#pragma unroll
    for (int i = 0; i < 8; i++) {
        int idx = tid + i * 128;
        int row = idx >> 4, d4 = (idx & 15) << 2;
        float4 v = *(const float4*)(Qg + (size_t)(qb * 64 + row) * DD + d4);
        Qs[row * 68 + d4 + 0] = f2tf32(v.x * 0.125f);
        Qs[row * 68 + d4 + 1] = f2tf32(v.y * 0.125f);
        Qs[row * 68 + d4 + 2] = f2tf32(v.z * 0.125f);
        Qs[row * 68 + d4 + 3] = f2tf32(v.w * 0.125f);
    }

    float m_r[2] = {NEGF, NEGF};
    float l_r[2] = {0.f, 0.f};
    float O[8][4];
#pragma unroll
    for (int nt = 0; nt < 8; nt++)
#pragma unroll
        for (int c = 0; c < 4; c++) O[nt][c] = 0.f;

    const int kb0 = left ? 0 : qb;
    const int kb1 = left ? qb : (TT / 64 - 1);
    const int qi0 = qb * 64 + rm + g, qi1 = qi0 + 8;

    for (int kb = kb0; kb <= kb1; kb++) {
        __syncthreads();
#pragma unroll
        for (int i = 0; i < 8; i++) {
            int idx = tid + i * 128;
            int row = idx >> 4, d4 = (idx & 15) << 2;
            float4 kv = *(const float4*)(Kg + (size_t)(kb * 64 + row) * DD + d4);
            Ks[row * 68 + d4 + 0] = f2tf32(kv.x);
            Ks[row * 68 + d4 + 1] = f2tf32(kv.y);
            Ks[row * 68 + d4 + 2] = f2tf32(kv.z);
            Ks[row * 68 + d4 + 3] = f2tf32(kv.w);
            float4 vv = *(const float4*)(Vg + (size_t)(kb * 64 + row) * DD + d4);
            Vs[row * 68 + d4 + 0] = f2tf32(vv.x);
            Vs[row * 68 + d4 + 1] = f2tf32(vv.y);
            Vs[row * 68 + d4 + 2] = f2tf32(vv.z);
            Vs[row * 68 + d4 + 3] = f2tf32(vv.w);
        }
        if (tid < 64)
            pm[tid] = amask[b * TT + kb * 64 + tid] ? 0.f : NEGF;
        __syncthreads();

        float S[8][4];
#pragma unroll
        for (int nt = 0; nt < 8; nt++)
#pragma unroll
            for (int c = 0; c < 4; c++) S[nt][c] = 0.f;

#pragma unroll
        for (int ks = 0; ks < 8; ks++) {
            const uint32_t ko = ks * 32;
            unsigned a0, a1, a2, a3;
            ldsm4(a0, a1, a2, a3, qad + ko);
#pragma unroll
            for (int p = 0; p < 4; p++) {
                unsigned k0, k1, k2, k3;
                ldsm4(k0, k1, k2, k3, kad[p] + ko);
                mma8(S[2 * p],     a0, a1, a2, a3, k0, k1);
                mma8(S[2 * p + 1], a0, a1, a2, a3, k2, k3);
            }
        }

        float mx0 = NEGF, mx1 = NEGF;
        const bool diag = (kb == qb);
#pragma unroll
        for (int nt = 0; nt < 8; nt++) {
            int c0 = nt * 8 + t * 2;
            float p0 = pm[c0], p1 = pm[c0 + 1];
            float s0 = S[nt][0] + p0, s1 = S[nt][1] + p1;
            float s2 = S[nt][2] + p0, s3 = S[nt][3] + p1;
            if (diag) {
                int k0i = kb * 64 + c0, k1i = k0i + 1;
                if (left) {
                    if (k0i > qi0) s0 = NEGF;
                    if (k1i > qi0) s1 = NEGF;
                    if (k0i > qi1) s2 = NEGF;
                    if (k1i > qi1) s3 = NEGF;
                } else {
                    if (k0i < qi0) s0 = NEGF;
                    if (k1i < qi0) s1 = NEGF;
                    if (k0i < qi1) s2 = NEGF;
                    if (k1i < qi1) s3 = NEGF;
                }
            }
            S[nt][0] = s0; S[nt][1] = s1; S[nt][2] = s2; S[nt][3] = s3;
            mx0 = fmaxf(mx0, fmaxf(s0, s1));
            mx1 = fmaxf(mx1, fmaxf(s2, s3));
        }
        mx0 = fmaxf(mx0, __shfl_xor_sync(0xffffffffu, mx0, 1));
        mx0 = fmaxf(mx0, __shfl_xor_sync(0xffffffffu, mx0, 2));
        mx1 = fmaxf(mx1, __shfl_xor_sync(0xffffffffu, mx1, 1));
        mx1 = fmaxf(mx1, __shfl_xor_sync(0xffffffffu, mx1, 2));

        float mn0 = fmaxf(m_r[0], mx0), mn1 = fmaxf(m_r[1], mx1);
        float al0 = __expf(m_r[0] - mn0), al1 = __expf(m_r[1] - mn1);
        m_r[0] = mn0; m_r[1] = mn1;

        float rs0 = 0.f, rs1 = 0.f;
#pragma unroll
        for (int nt = 0; nt < 8; nt++) {
            float e0 = __expf(S[nt][0] - mn0), e1 = __expf(S[nt][1] - mn0);
            float e2 = __expf(S[nt][2] - mn1), e3 = __expf(S[nt][3] - mn1);
            S[nt][0] = e0; S[nt][1] = e1; S[nt][2] = e2; S[nt][3] = e3;
            rs0 += e0 + e1; rs1 += e2 + e3;
        }
        rs0 += __shfl_xor_sync(0xffffffffu, rs0, 1);
        rs0 += __shfl_xor_sync(0xffffffffu, rs0, 2);
        rs1 += __shfl_xor_sync(0xffffffffu, rs1, 1);
        rs1 += __shfl_xor_sync(0xffffffffu, rs1, 2);
        l_r[0] = l_r[0] * al0 + rs0;
        l_r[1] = l_r[1] * al1 + rs1;
#pragma unroll
        for (int nt = 0; nt < 8; nt++) {
            O[nt][0] *= al0; O[nt][1] *= al0;
            O[nt][2] *= al1; O[nt][3] *= al1;
        }

        __syncwarp();
#pragma unroll
        for (int nt = 0; nt < 8; nt++) {
            int c0 = nt * 8 + t * 2;
            Ps[(rm     + g) * 68 + c0    ] = f2tf32(S[nt][0]);
            Ps[(rm     + g) * 68 + c0 + 1] = f2tf32(S[nt][1]);
            Ps[(rm + 8 + g) * 68 + c0    ] = f2tf32(S[nt][2]);
            Ps[(rm + 8 + g) * 68 + c0 + 1] = f2tf32(S[nt][3]);
        }
        __syncwarp();

#pragma unroll
        for (int ks = 0; ks < 8; ks++) {
            const int kk = ks * 8;
            unsigned a0, a1, a2, a3;
            ldsm4(a0, a1, a2, a3, padr + ks * 32);
#pragma unroll
            for (int nt = 0; nt < 8; nt++) {
                unsigned b0 = Vs[(kk     + t) * 68 + nt * 8 + g];
                unsigned b1 = Vs[(kk + 4 + t) * 68 + nt * 8 + g];
                mma8(O[nt], a0, a1, a2, a3, b0, b1);
            }
        }
    }

    // Epilogue -> g_ctx (tf32-rounded: out-proj GEMM reads it raw via cp.async)
    float inv0 = 1.0f / l_r[0], inv1 = 1.0f / l_r[1];
    int t0 = qb * 64 + rm + g, t1 = t0 + 8;
#pragma unroll
    for (int nt = 0; nt < 8; nt++) {
        int col = h * DD + nt * 8 + t * 2;
        *(float2*)(g_ctx + ((size_t)b * TT + t0) * CC + col) =
            make_float2(rnd(O[nt][0] * inv0), rnd(O[nt][1] * inv0));
        *(float2*)(g_ctx + ((size_t)b * TT + t1) * CC + col) =
            make_float2(rnd(O[nt][2] * inv1), rnd(O[nt][3] * inv1));
    }
}

// ---------------------------------------------------------------------------
extern "C" void kernel_launch(void* const* d_in, const int* in_sizes, int n_in,
                              void* d_out, int out_size)
{
    const float* x      = (const float*)d_in[0];
    const int*   amask  = (const int*)  d_in[1];
    const float* Wqkv_w = (const float*)d_in[2];
    const float* Wqkv_b = (const float*)d_in[3];
    const float* Wo_w   = (const float*)d_in[4];
    const float* Wo_b   = (const float*)d_in[5];
    float* out = (float*)d_out;

    (void)in_sizes; (void)n_in; (void)out_size;

    const int attn_smem = 4 * 64 * 68 * 4 + 64 * 4;   // 69888 B
    cudaFuncSetAttribute(attn_mma_kernel,
                         cudaFuncAttributeMaxDynamicSharedMemorySize, attn_smem);
    cudaFuncSetAttribute(mma_gemm_kernel<0>,
                         cudaFuncAttributeMaxDynamicSharedMemorySize, GEMM_SMEM);
    cudaFuncSetAttribute(mma_gemm_kernel<1>,
                         cudaFuncAttributeMaxDynamicSharedMemorySize, GEMM_SMEM);

    preround_kernel<<<(PRN4 + 255) / 256, 256>>>(x, Wqkv_w, Wo_w);
    mma_gemm_kernel<0><<<dim3(N1 / 64, MM / 128), 256, GEMM_SMEM>>>(Wqkv_b, nullptr);
    attn_mma_kernel<<<dim3(BB * HH, TT / 64), 128, attn_smem>>>(amask);
    mma_gemm_kernel<1><<<dim3(CC / 64, MM / 128), 256, GEMM_SMEM>>>(Wo_b, out);
}

// round 11
// speedup vs baseline: 2.0550x; 1.0698x over previous
#include <cuda_runtime.h>
#include <cstdint>

#define BB 2
#define TT 2048
#define CC 768
#define HH 12
#define NLEFT 6
#define DD 64
#define MM (BB*TT)
#define N1 (3*CC)

#define NEGF (-3.402823466e38f)

// Scratch (device globals: allocation-free)
__device__ float g_q[BB*HH*TT*DD];
__device__ float g_k[BB*HH*TT*DD];
__device__ float g_v[BB*HH*TT*DD];
__device__ float g_ctx[BB*TT*CC];
// Pre-rounded (tf32) copies of GEMM inputs
__device__ float g_xr[MM*CC];
__device__ float g_w1r[N1*CC];
__device__ float g_w2r[CC*CC];

__device__ __forceinline__ unsigned f2tf32(float f) {
    unsigned r;
    asm("cvt.rna.tf32.f32 %0, %1;" : "=r"(r) : "f"(f));
    return r;
}
__device__ __forceinline__ float rnd(float f) { return __uint_as_float(f2tf32(f)); }

__device__ __forceinline__ uint32_t smem_u32(const void* p) {
    uint32_t a;
    asm("{ .reg .u64 t; cvta.to.shared.u64 t, %1; cvt.u32.u64 %0, t; }"
        : "=r"(a) : "l"(p));
    return a;
}
__device__ __forceinline__ void cpa16(uint32_t d, const void* s) {
    asm volatile("cp.async.cg.shared.global [%0], [%1], 16;" :: "r"(d), "l"(s));
}
#define CPA_COMMIT() asm volatile("cp.async.commit_group;" ::: "memory")
#define CPA_WAIT(n)  asm volatile("cp.async.wait_group %0;" :: "n"(n) : "memory")

__device__ __forceinline__ void ldsm4(unsigned& r0, unsigned& r1,
                                      unsigned& r2, unsigned& r3, uint32_t addr) {
    asm volatile("ldmatrix.sync.aligned.m8n8.x4.shared.b16 {%0,%1,%2,%3}, [%4];"
                 : "=r"(r0), "=r"(r1), "=r"(r2), "=r"(r3) : "r"(addr));
}
__device__ __forceinline__ void mma8(float* d,
    unsigned a0, unsigned a1, unsigned a2, unsigned a3,
    unsigned b0, unsigned b1)
{
    asm volatile(
        "mma.sync.aligned.m16n8k8.row.col.f32.tf32.tf32.f32 "
        "{%0,%1,%2,%3}, {%4,%5,%6,%7}, {%8,%9}, {%0,%1,%2,%3};"
        : "+f"(d[0]), "+f"(d[1]), "+f"(d[2]), "+f"(d[3])
        : "r"(a0), "r"(a1), "r"(a2), "r"(a3), "r"(b0), "r"(b1));
}

// ---------------------------------------------------------------------------
// Pre-round inputs to tf32 (idempotent wrt all downstream cvt.rna).
// ---------------------------------------------------------------------------
#define XN4  (MM*CC/4)
#define W1N4 (N1*CC/4)
#define W2N4 (CC*CC/4)
#define PRN4 (XN4 + W1N4 + W2N4)

__global__ __launch_bounds__(256) void preround_kernel(
    const float* __restrict__ x, const float* __restrict__ w1,
    const float* __restrict__ w2)
{
    int i = blockIdx.x * 256 + threadIdx.x;
    if (i >= PRN4) return;
    const float* src; float* dst; int j;
    if (i < XN4)              { src = x;  dst = g_xr;  j = i; }
    else if (i < XN4 + W1N4)  { src = w1; dst = g_w1r; j = i - XN4; }
    else                      { src = w2; dst = g_w2r; j = i - XN4 - W1N4; }
    float4 v = *(const float4*)(src + (size_t)j * 4);
    float4 o = make_float4(rnd(v.x), rnd(v.y), rnd(v.z), rnd(v.w));
    *(float4*)(dst + (size_t)j * 4) = o;
}

// ---------------------------------------------------------------------------
// tf32 MMA GEMM, cp.async double-buffered (R10-proven, unchanged).
// ---------------------------------------------------------------------------
#define GW_A   (128*36)
#define GW_B   (64*36)
#define GW_PR  (GW_A + GW_B)
#define GEMM_SMEM (2 * GW_PR * 4)
#define NCH (CC/32)

template<int MODE>
__global__ __launch_bounds__(256) void mma_gemm_kernel(
    const float* __restrict__ bias, float* __restrict__ out)
{
    extern __shared__ unsigned sm[];

    const float* Ag = (MODE == 0) ? (const float*)g_xr  : (const float*)g_ctx;
    const float* W  = (MODE == 0) ? (const float*)g_w1r : (const float*)g_w2r;

    const int K = CC;
    const int tid  = threadIdx.x;
    const int lane = tid & 31, warp = tid >> 5;
    const int mw = warp >> 1, nw = warp & 1;
    const int m0 = blockIdx.y * 128, n0 = blockIdx.x * 64;
    const int g = lane >> 2, t = lane & 3;

    const uint32_t smb = smem_u32(sm);

    const int a_row = (lane & 7) + ((lane >> 3) & 1) * 8;
    const int a_ws  = (lane >> 4) * 4;
    const int b_row = (lane & 7) + ((lane >> 4) << 3);
    const int b_ws  = ((lane >> 3) & 1) * 4;

    const uint32_t aad0 = smb + (uint32_t)(((mw * 32 + a_row) * 36 + a_ws) << 2);
    const uint32_t aad1 = aad0 + 16 * 36 * 4;
    const uint32_t bad0 = smb + (uint32_t)((GW_A + (nw * 32 + b_row) * 36 + b_ws) << 2);
    const uint32_t bad1 = bad0 + 16 * 36 * 4;

    const int lrow = tid >> 3;
    const int lkq  = (tid & 7) << 2;

    float acc[2][4][4];
#pragma unroll
    for (int mt = 0; mt < 2; mt++)
#pragma unroll
        for (int nt = 0; nt < 4; nt++)
#pragma unroll
            for (int c = 0; c < 4; c++) acc[mt][nt][c] = 0.f;

    {
        uint32_t ab = smb, bb = smb + GW_A * 4;
#pragma unroll
        for (int i = 0; i < 4; i++) {
            int row = lrow + i * 32;
            cpa16(ab + (uint32_t)((row * 36 + lkq) << 2),
                  Ag + (size_t)(m0 + row) * K + lkq);
        }
#pragma unroll
        for (int i = 0; i < 2; i++) {
            int row = lrow + i * 32;
            cpa16(bb + (uint32_t)((row * 36 + lkq) << 2),
                  W + (size_t)(n0 + row) * K + lkq);
        }
        CPA_COMMIT();
    }

    for (int c = 0; c < NCH; c++) {
        const uint32_t bo = (uint32_t)(c & 1) * (GW_PR * 4);
        if (c + 1 < NCH) {
            const int k0n = (c + 1) * 32;
            const uint32_t nbo = (uint32_t)((c + 1) & 1) * (GW_PR * 4);
            uint32_t ab = smb + nbo, bb = smb + nbo + GW_A * 4;
#pragma unroll
            for (int i = 0; i < 4; i++) {
                int row = lrow + i * 32;
                cpa16(ab + (uint32_t)((row * 36 + lkq) << 2),
                      Ag + (size_t)(m0 + row) * K + k0n + lkq);
            }
#pragma unroll
            for (int i = 0; i < 2; i++) {
                int row = lrow + i * 32;
                cpa16(bb + (uint32_t)((row * 36 + lkq) << 2),
                      W + (size_t)(n0 + row) * K + k0n + lkq);
            }
            CPA_COMMIT();
            CPA_WAIT(1);
        } else {
            CPA_WAIT(0);
        }
        __syncthreads();

#pragma unroll
        for (int ks = 0; ks < 4; ks++) {
            const uint32_t ko = bo + ks * 32;
            unsigned a0[4], a1[4], bA[4], bBr[4];
            ldsm4(a0[0], a0[1], a0[2], a0[3], aad0 + ko);
            ldsm4(a1[0], a1[1], a1[2], a1[3], aad1 + ko);
            ldsm4(bA[0], bA[1], bA[2], bA[3], bad0 + ko);
            ldsm4(bBr[0], bBr[1], bBr[2], bBr[3], bad1 + ko);
            mma8(acc[0][0], a0[0], a0[1], a0[2], a0[3], bA[0], bA[1]);
            mma8(acc[0][1], a0[0], a0[1], a0[2], a0[3], bA[2], bA[3]);
            mma8(acc[0][2], a0[0], a0[1], a0[2], a0[3], bBr[0], bBr[1]);
            mma8(acc[0][3], a0[0], a0[1], a0[2], a0[3], bBr[2], bBr[3]);
            mma8(acc[1][0], a1[0], a1[1], a1[2], a1[3], bA[0], bA[1]);
            mma8(acc[1][1], a1[0], a1[1], a1[2], a1[3], bA[2], bA[3]);
            mma8(acc[1][2], a1[0], a1[1], a1[2], a1[3], bBr[0], bBr[1]);
            mma8(acc[1][3], a1[0], a1[1], a1[2], a1[3], bBr[2], bBr[3]);
        }
        __syncthreads();
    }

    if (MODE == 0) {
        const int s  = n0 / CC;
        const int hh = (n0 % CC) / DD;
        float* dst = (s == 0) ? g_q : ((s == 1) ? g_k : g_v);
#pragma unroll
        for (int mt = 0; mt < 2; mt++) {
            int m = m0 + mw * 32 + mt * 16 + g;
            int b0i = m >> 11, tok0 = m & 2047;
            int m1 = m + 8, b1i = m1 >> 11, tok1 = m1 & 2047;
#pragma unroll
            for (int nt = 0; nt < 4; nt++) {
                int dcol = nw * 32 + nt * 8 + t * 2;
                int n = n0 + dcol;
                float bv0 = bias[n], bv1 = bias[n + 1];
                float2 r0 = make_float2(rnd(acc[mt][nt][0] + bv0), rnd(acc[mt][nt][1] + bv1));
                float2 r1 = make_float2(rnd(acc[mt][nt][2] + bv0), rnd(acc[mt][nt][3] + bv1));
                *(float2*)(dst + ((size_t)(b0i * HH + hh) * TT + tok0) * DD + dcol) = r0;
                *(float2*)(dst + ((size_t)(b1i * HH + hh) * TT + tok1) * DD + dcol) = r1;
            }
        }
    } else {
#pragma unroll
        for (int mt = 0; mt < 2; mt++) {
            int m = m0 + mw * 32 + mt * 16 + g;
#pragma unroll
            for (int nt = 0; nt < 4; nt++) {
                int n = n0 + nw * 32 + nt * 8 + t * 2;
                float bv0 = bias[n], bv1 = bias[n + 1];
                float2 r0 = make_float2(acc[mt][nt][0] + bv0, acc[mt][nt][1] + bv1);
                float2 r1 = make_float2(acc[mt][nt][2] + bv0, acc[mt][nt][3] + bv1);
                *(float2*)(out + (size_t)m * CC + n) = r0;
                *(float2*)(out + (size_t)(m + 8) * CC + n) = r1;
            }
        }
    }
}

// ---------------------------------------------------------------------------
// tf32 MMA flash attention with cp.async double-buffered K/V.
// K/V are tf32-rounded in gmem, so raw byte copies are numerically exact.
// pm precomputed for the whole 2048-token row (8 KB smem).
// smem layout (words): Qs[0] KV0{K,V}[4352,8704] KV1[13056,17408]
//                      Ps[21760] pmall[26112..28160]  => 112640 B
// ---------------------------------------------------------------------------
#define AQ   0
#define AK0  4352
#define AV0  8704
#define AK1  13056
#define AV1  17408
#define APS  21760
#define APM  26112
#define ATTN_SMEM ((28160) * 4)

__global__ __launch_bounds__(128) void attn_mma_kernel(const int* __restrict__ amask)
{
    extern __shared__ unsigned smu[];
    unsigned* Qs = smu + AQ;
    unsigned* Ps = smu + APS;
    float*    pmall = (float*)(smu + APM);

    const int bh = blockIdx.x, qb = blockIdx.y;
    const int b = bh / HH, h = bh % HH;
    const bool left = (h < NLEFT);

    const float* Qg = g_q + (size_t)bh * TT * DD;
    const float* Kg = g_k + (size_t)bh * TT * DD;
    const float* Vg = g_v + (size_t)bh * TT * DD;

    const int tid = threadIdx.x;
    const int lane = tid & 31, warp = tid >> 5;
    const int g = lane >> 2, t = lane & 3;
    const int rm = warp * 16;

    const int a_row = (lane & 7) + ((lane >> 3) & 1) * 8;
    const int a_ws  = (lane >> 4) * 4;
    const int b_row = (lane & 7) + ((lane >> 4) << 3);
    const int b_ws  = ((lane >> 3) & 1) * 4;

    const uint32_t smb = smem_u32(smu);
    const uint32_t qad  = smb + (uint32_t)(((rm + a_row) * 68 + a_ws + AQ)  << 2);
    const uint32_t padr = smb + (uint32_t)(((rm + a_row) * 68 + a_ws + APS) << 2);
    uint32_t kad[4];
#pragma unroll
    for (int p = 0; p < 4; p++)
        kad[p] = smb + (uint32_t)((AK0 + (p * 16 + b_row) * 68 + b_ws) << 2);

    // Loader geometry for K/V cp.async (per thread: 8 rows' worth each)
    const int lrow0 = tid >> 4;           // +8 per i
    const int ld4   = (tid & 15) << 2;

    // Q load (scaled by 1/8, exact; inputs already tf32-rounded)
#pragma unroll
    for (int i = 0; i < 8; i++) {
        int row = lrow0 + i * 8;
        float4 v = *(const float4*)(Qg + (size_t)(qb * 64 + row) * DD + ld4);
        Qs[row * 68 + ld4 + 0] = f2tf32(v.x * 0.125f);
        Qs[row * 68 + ld4 + 1] = f2tf32(v.y * 0.125f);
        Qs[row * 68 + ld4 + 2] = f2tf32(v.z * 0.125f);
        Qs[row * 68 + ld4 + 3] = f2tf32(v.w * 0.125f);
    }
    // Precompute padding penalties for the whole row
#pragma unroll
    for (int i = 0; i < 16; i++) {
        int idx = tid + i * 128;
        pmall[idx] = amask[b * TT + idx] ? 0.f : NEGF;
    }

    float m_r[2] = {NEGF, NEGF};
    float l_r[2] = {0.f, 0.f};
    float O[8][4];
#pragma unroll
    for (int nt = 0; nt < 8; nt++)
#pragma unroll
        for (int c = 0; c < 4; c++) O[nt][c] = 0.f;

    const int kb0 = left ? 0 : qb;
    const int kb1 = left ? qb : (TT / 64 - 1);
    const int qi0 = qb * 64 + rm + g, qi1 = qi0 + 8;

    // Prologue: prefetch kb0 into buffer 0
    {
        const float* Kp = Kg + (size_t)kb0 * 64 * DD;
        const float* Vp = Vg + (size_t)kb0 * 64 * DD;
        uint32_t kb_ = smb + AK0 * 4, vb_ = smb + AV0 * 4;
#pragma unroll
        for (int i = 0; i < 8; i++) {
            int row = lrow0 + i * 8;
            uint32_t off = (uint32_t)((row * 68 + ld4) << 2);
            cpa16(kb_ + off, Kp + row * DD + ld4);
            cpa16(vb_ + off, Vp + row * DD + ld4);
        }
        CPA_COMMIT();
    }

    for (int kb = kb0, it = 0; kb <= kb1; kb++, it++) {
        const int buf = it & 1;
        const uint32_t bufoff = (uint32_t)buf * ((AK1 - AK0) * 4);
        __syncthreads();                 // prev iter compute done (buf^1 free)
        if (kb + 1 <= kb1) {
            const float* Kp = Kg + (size_t)(kb + 1) * 64 * DD;
            const float* Vp = Vg + (size_t)(kb + 1) * 64 * DD;
            const uint32_t nbo = (uint32_t)(buf ^ 1) * ((AK1 - AK0) * 4);
            uint32_t kb_ = smb + AK0 * 4 + nbo, vb_ = smb + AV0 * 4 + nbo;
#pragma unroll
            for (int i = 0; i < 8; i++) {
                int row = lrow0 + i * 8;
                uint32_t off = (uint32_t)((row * 68 + ld4) << 2);
                cpa16(kb_ + off, Kp + row * DD + ld4);
                cpa16(vb_ + off, Vp + row * DD + ld4);
            }
            CPA_COMMIT();
            CPA_WAIT(1);
        } else {
            CPA_WAIT(0);
        }
        __syncthreads();                 // kb's K/V visible to all warps

        const unsigned* Vsb = smu + AV0 + buf * (AK1 - AK0);

        // S = Qs @ Ks^T
        float S[8][4];
#pragma unroll
        for (int nt = 0; nt < 8; nt++)
#pragma unroll
            for (int c = 0; c < 4; c++) S[nt][c] = 0.f;

#pragma unroll
        for (int ks = 0; ks < 8; ks++) {
            const uint32_t ko = ks * 32;
            unsigned a0, a1, a2, a3;
            ldsm4(a0, a1, a2, a3, qad + ko);
#pragma unroll
            for (int p = 0; p < 4; p++) {
                unsigned k0, k1, k2, k3;
                ldsm4(k0, k1, k2, k3, kad[p] + bufoff + ko);
                mma8(S[2 * p],     a0, a1, a2, a3, k0, k1);
                mma8(S[2 * p + 1], a0, a1, a2, a3, k2, k3);
            }
        }

        // Mask + online softmax
        float mx0 = NEGF, mx1 = NEGF;
        const bool diag = (kb == qb);
        const int kbase = kb * 64;
#pragma unroll
        for (int nt = 0; nt < 8; nt++) {
            int c0 = nt * 8 + t * 2;
            float p0 = pmall[kbase + c0], p1 = pmall[kbase + c0 + 1];
            float s0 = S[nt][0] + p0, s1 = S[nt][1] + p1;
            float s2 = S[nt][2] + p0, s3 = S[nt][3] + p1;
            if (diag) {
                int k0i = kbase + c0, k1i = k0i + 1;
                if (left) {
                    if (k0i > qi0) s0 = NEGF;
                    if (k1i > qi0) s1 = NEGF;
                    if (k0i > qi1) s2 = NEGF;
                    if (k1i > qi1) s3 = NEGF;
                } else {
                    if (k0i < qi0) s0 = NEGF;
                    if (k1i < qi0) s1 = NEGF;
                    if (k0i < qi1) s2 = NEGF;
                    if (k1i < qi1) s3 = NEGF;
                }
            }
            S[nt][0] = s0; S[nt][1] = s1; S[nt][2] = s2; S[nt][3] = s3;
            mx0 = fmaxf(mx0, fmaxf(s0, s1));
            mx1 = fmaxf(mx1, fmaxf(s2, s3));
        }
        mx0 = fmaxf(mx0, __shfl_xor_sync(0xffffffffu, mx0, 1));
        mx0 = fmaxf(mx0, __shfl_xor_sync(0xffffffffu, mx0, 2));
        mx1 = fmaxf(mx1, __shfl_xor_sync(0xffffffffu, mx1, 1));
        mx1 = fmaxf(mx1, __shfl_xor_sync(0xffffffffu, mx1, 2));

        float mn0 = fmaxf(m_r[0], mx0), mn1 = fmaxf(m_r[1], mx1);
        float al0 = __expf(m_r[0] - mn0), al1 = __expf(m_r[1] - mn1);
        m_r[0] = mn0; m_r[1] = mn1;

        float rs0 = 0.f, rs1 = 0.f;
#pragma unroll
        for (int nt = 0; nt < 8; nt++) {
            float e0 = __expf(S[nt][0] - mn0), e1 = __expf(S[nt][1] - mn0);
            float e2 = __expf(S[nt][2] - mn1), e3 = __expf(S[nt][3] - mn1);
            S[nt][0] = e0; S[nt][1] = e1; S[nt][2] = e2; S[nt][3] = e3;
            rs0 += e0 + e1; rs1 += e2 + e3;
        }
        rs0 += __shfl_xor_sync(0xffffffffu, rs0, 1);
        rs0 += __shfl_xor_sync(0xffffffffu, rs0, 2);
        rs1 += __shfl_xor_sync(0xffffffffu, rs1, 1);
        rs1 += __shfl_xor_sync(0xffffffffu, rs1, 2);
        l_r[0] = l_r[0] * al0 + rs0;
        l_r[1] = l_r[1] * al1 + rs1;
#pragma unroll
        for (int nt = 0; nt < 8; nt++) {
            O[nt][0] *= al0; O[nt][1] *= al0;
            O[nt][2] *= al1; O[nt][3] *= al1;
        }

        // P -> smem (warp-private rows)
        __syncwarp();
#pragma unroll
        for (int nt = 0; nt < 8; nt++) {
            int c0 = nt * 8 + t * 2;
            Ps[(rm     + g) * 68 + c0    ] = f2tf32(S[nt][0]);
            Ps[(rm     + g) * 68 + c0 + 1] = f2tf32(S[nt][1]);
            Ps[(rm + 8 + g) * 68 + c0    ] = f2tf32(S[nt][2]);
            Ps[(rm + 8 + g) * 68 + c0 + 1] = f2tf32(S[nt][3]);
        }
        __syncwarp();

        // O += P @ V
#pragma unroll
        for (int ks = 0; ks < 8; ks++) {
            const int kk = ks * 8;
            unsigned a0, a1, a2, a3;
            ldsm4(a0, a1, a2, a3, padr + ks * 32);
#pragma unroll
            for (int nt = 0; nt < 8; nt++) {
                unsigned b0 = Vsb[(kk     + t) * 68 + nt * 8 + g];
                unsigned b1 = Vsb[(kk + 4 + t) * 68 + nt * 8 + g];
                mma8(O[nt], a0, a1, a2, a3, b0, b1);
            }
        }
    }

    // Epilogue -> g_ctx (tf32-rounded: out-proj GEMM reads it raw)
    float inv0 = 1.0f / l_r[0], inv1 = 1.0f / l_r[1];
    int t0 = qb * 64 + rm + g, t1 = t0 + 8;
#pragma unroll
    for (int nt = 0; nt < 8; nt++) {
        int col = h * DD + nt * 8 + t * 2;
        *(float2*)(g_ctx + ((size_t)b * TT + t0) * CC + col) =
            make_float2(rnd(O[nt][0] * inv0), rnd(O[nt][1] * inv0));
        *(float2*)(g_ctx + ((size_t)b * TT + t1) * CC + col) =
            make_float2(rnd(O[nt][2] * inv1), rnd(O[nt][3] * inv1));
    }
}

// ---------------------------------------------------------------------------
extern "C" void kernel_launch(void* const* d_in, const int* in_sizes, int n_in,
                              void* d_out, int out_size)
{
    const float* x      = (const float*)d_in[0];
    const int*   amask  = (const int*)  d_in[1];
    const float* Wqkv_w = (const float*)d_in[2];
    const float* Wqkv_b = (const float*)d_in[3];
    const float* Wo_w   = (const float*)d_in[4];
    const float* Wo_b   = (const float*)d_in[5];
    float* out = (float*)d_out;

    (void)in_sizes; (void)n_in; (void)out_size;

    cudaFuncSetAttribute(attn_mma_kernel,
                         cudaFuncAttributeMaxDynamicSharedMemorySize, ATTN_SMEM);
    cudaFuncSetAttribute(mma_gemm_kernel<0>,
                         cudaFuncAttributeMaxDynamicSharedMemorySize, GEMM_SMEM);
    cudaFuncSetAttribute(mma_gemm_kernel<1>,
                         cudaFuncAttributeMaxDynamicSharedMemorySize, GEMM_SMEM);

    preround_kernel<<<(PRN4 + 255) / 256, 256>>>(x, Wqkv_w, Wo_w);
    mma_gemm_kernel<0><<<dim3(N1 / 64, MM / 128), 256, GEMM_SMEM>>>(Wqkv_b, nullptr);
    attn_mma_kernel<<<dim3(BB * HH, TT / 64), 128, ATTN_SMEM>>>(amask);
    mma_gemm_kernel<1><<<dim3(CC / 64, MM / 128), 256, GEMM_SMEM>>>(Wo_b, out);
}

// round 12
// speedup vs baseline: 2.3306x; 1.1342x over previous
#include <cuda_runtime.h>
#include <cstdint>

#define BB 2
#define TT 2048
#define CC 768
#define HH 12
#define NLEFT 6
#define DD 64
#define MM (BB*TT)
#define N1 (3*CC)

#define NEGF (-3.402823466e38f)

// Scratch (device globals: allocation-free)
__device__ float g_q[BB*HH*TT*DD];
__device__ float g_k[BB*HH*TT*DD];
__device__ float g_v[BB*HH*TT*DD];
__device__ float g_ctx[BB*TT*CC];
// Pre-rounded (tf32) copies of GEMM inputs
__device__ float g_xr[MM*CC];
__device__ float g_w1r[N1*CC];
__device__ float g_w2r[CC*CC];

__device__ __forceinline__ unsigned f2tf32(float f) {
    unsigned r;
    asm("cvt.rna.tf32.f32 %0, %1;" : "=r"(r) : "f"(f));
    return r;
}
__device__ __forceinline__ float rnd(float f) { return __uint_as_float(f2tf32(f)); }

__device__ __forceinline__ uint32_t smem_u32(const void* p) {
    uint32_t a;
    asm("{ .reg .u64 t; cvta.to.shared.u64 t, %1; cvt.u32.u64 %0, t; }"
        : "=r"(a) : "l"(p));
    return a;
}
__device__ __forceinline__ void cpa16(uint32_t d, const void* s) {
    asm volatile("cp.async.cg.shared.global [%0], [%1], 16;" :: "r"(d), "l"(s));
}
#define CPA_COMMIT() asm volatile("cp.async.commit_group;" ::: "memory")
#define CPA_WAIT(n)  asm volatile("cp.async.wait_group %0;" :: "n"(n) : "memory")

__device__ __forceinline__ void ldsm4(unsigned& r0, unsigned& r1,
                                      unsigned& r2, unsigned& r3, uint32_t addr) {
    asm volatile("ldmatrix.sync.aligned.m8n8.x4.shared.b16 {%0,%1,%2,%3}, [%4];"
                 : "=r"(r0), "=r"(r1), "=r"(r2), "=r"(r3) : "r"(addr));
}
__device__ __forceinline__ void mma8(float* d,
    unsigned a0, unsigned a1, unsigned a2, unsigned a3,
    unsigned b0, unsigned b1)
{
    asm volatile(
        "mma.sync.aligned.m16n8k8.row.col.f32.tf32.tf32.f32 "
        "{%0,%1,%2,%3}, {%4,%5,%6,%7}, {%8,%9}, {%0,%1,%2,%3};"
        : "+f"(d[0]), "+f"(d[1]), "+f"(d[2]), "+f"(d[3])
        : "r"(a0), "r"(a1), "r"(a2), "r"(a3), "r"(b0), "r"(b1));
}

// ---------------------------------------------------------------------------
// Pre-round inputs to tf32 (idempotent wrt all downstream cvt.rna).
// ---------------------------------------------------------------------------
#define XN4  (MM*CC/4)
#define W1N4 (N1*CC/4)
#define W2N4 (CC*CC/4)
#define PRN4 (XN4 + W1N4 + W2N4)

__global__ __launch_bounds__(256) void preround_kernel(
    const float* __restrict__ x, const float* __restrict__ w1,
    const float* __restrict__ w2)
{
    int i = blockIdx.x * 256 + threadIdx.x;
    if (i >= PRN4) return;
    const float* src; float* dst; int j;
    if (i < XN4)              { src = x;  dst = g_xr;  j = i; }
    else if (i < XN4 + W1N4)  { src = w1; dst = g_w1r; j = i - XN4; }
    else                      { src = w2; dst = g_w2r; j = i - XN4 - W1N4; }
    float4 v = *(const float4*)(src + (size_t)j * 4);
    float4 o = make_float4(rnd(v.x), rnd(v.y), rnd(v.z), rnd(v.w));
    *(float4*)(dst + (size_t)j * 4) = o;
}

// ---------------------------------------------------------------------------
// tf32 MMA GEMM, cp.async double-buffered (R10-proven, unchanged).
// ---------------------------------------------------------------------------
#define GW_A   (128*36)
#define GW_B   (64*36)
#define GW_PR  (GW_A + GW_B)
#define GEMM_SMEM (2 * GW_PR * 4)
#define NCH (CC/32)

template<int MODE>
__global__ __launch_bounds__(256) void mma_gemm_kernel(
    const float* __restrict__ bias, float* __restrict__ out)
{
    extern __shared__ unsigned sm[];

    const float* Ag = (MODE == 0) ? (const float*)g_xr  : (const float*)g_ctx;
    const float* W  = (MODE == 0) ? (const float*)g_w1r : (const float*)g_w2r;

    const int K = CC;
    const int tid  = threadIdx.x;
    const int lane = tid & 31, warp = tid >> 5;
    const int mw = warp >> 1, nw = warp & 1;
    const int m0 = blockIdx.y * 128, n0 = blockIdx.x * 64;
    const int g = lane >> 2, t = lane & 3;

    const uint32_t smb = smem_u32(sm);

    const int a_row = (lane & 7) + ((lane >> 3) & 1) * 8;
    const int a_ws  = (lane >> 4) * 4;
    const int b_row = (lane & 7) + ((lane >> 4) << 3);
    const int b_ws  = ((lane >> 3) & 1) * 4;

    const uint32_t aad0 = smb + (uint32_t)(((mw * 32 + a_row) * 36 + a_ws) << 2);
    const uint32_t aad1 = aad0 + 16 * 36 * 4;
    const uint32_t bad0 = smb + (uint32_t)((GW_A + (nw * 32 + b_row) * 36 + b_ws) << 2);
    const uint32_t bad1 = bad0 + 16 * 36 * 4;

    const int lrow = tid >> 3;
    const int lkq  = (tid & 7) << 2;

    float acc[2][4][4];
#pragma unroll
    for (int mt = 0; mt < 2; mt++)
#pragma unroll
        for (int nt = 0; nt < 4; nt++)
#pragma unroll
            for (int c = 0; c < 4; c++) acc[mt][nt][c] = 0.f;

    {
        uint32_t ab = smb, bb = smb + GW_A * 4;
#pragma unroll
        for (int i = 0; i < 4; i++) {
            int row = lrow + i * 32;
            cpa16(ab + (uint32_t)((row * 36 + lkq) << 2),
                  Ag + (size_t)(m0 + row) * K + lkq);
        }
#pragma unroll
        for (int i = 0; i < 2; i++) {
            int row = lrow + i * 32;
            cpa16(bb + (uint32_t)((row * 36 + lkq) << 2),
                  W + (size_t)(n0 + row) * K + lkq);
        }
        CPA_COMMIT();
    }

    for (int c = 0; c < NCH; c++) {
        const uint32_t bo = (uint32_t)(c & 1) * (GW_PR * 4);
        if (c + 1 < NCH) {
            const int k0n = (c + 1) * 32;
            const uint32_t nbo = (uint32_t)((c + 1) & 1) * (GW_PR * 4);
            uint32_t ab = smb + nbo, bb = smb + nbo + GW_A * 4;
#pragma unroll
            for (int i = 0; i < 4; i++) {
                int row = lrow + i * 32;
                cpa16(ab + (uint32_t)((row * 36 + lkq) << 2),
                      Ag + (size_t)(m0 + row) * K + k0n + lkq);
            }
#pragma unroll
            for (int i = 0; i < 2; i++) {
                int row = lrow + i * 32;
                cpa16(bb + (uint32_t)((row * 36 + lkq) << 2),
                      W + (size_t)(n0 + row) * K + k0n + lkq);
            }
            CPA_COMMIT();
            CPA_WAIT(1);
        } else {
            CPA_WAIT(0);
        }
        __syncthreads();

#pragma unroll
        for (int ks = 0; ks < 4; ks++) {
            const uint32_t ko = bo + ks * 32;
            unsigned a0[4], a1[4], bA[4], bBr[4];
            ldsm4(a0[0], a0[1], a0[2], a0[3], aad0 + ko);
            ldsm4(a1[0], a1[1], a1[2], a1[3], aad1 + ko);
            ldsm4(bA[0], bA[1], bA[2], bA[3], bad0 + ko);
            ldsm4(bBr[0], bBr[1], bBr[2], bBr[3], bad1 + ko);
            mma8(acc[0][0], a0[0], a0[1], a0[2], a0[3], bA[0], bA[1]);
            mma8(acc[0][1], a0[0], a0[1], a0[2], a0[3], bA[2], bA[3]);
            mma8(acc[0][2], a0[0], a0[1], a0[2], a0[3], bBr[0], bBr[1]);
            mma8(acc[0][3], a0[0], a0[1], a0[2], a0[3], bBr[2], bBr[3]);
            mma8(acc[1][0], a1[0], a1[1], a1[2], a1[3], bA[0], bA[1]);
            mma8(acc[1][1], a1[0], a1[1], a1[2], a1[3], bA[2], bA[3]);
            mma8(acc[1][2], a1[0], a1[1], a1[2], a1[3], bBr[0], bBr[1]);
            mma8(acc[1][3], a1[0], a1[1], a1[2], a1[3], bBr[2], bBr[3]);
        }
        __syncthreads();
    }

    if (MODE == 0) {
        const int s  = n0 / CC;
        const int hh = (n0 % CC) / DD;
        float* dst = (s == 0) ? g_q : ((s == 1) ? g_k : g_v);
#pragma unroll
        for (int mt = 0; mt < 2; mt++) {
            int m = m0 + mw * 32 + mt * 16 + g;
            int b0i = m >> 11, tok0 = m & 2047;
            int m1 = m + 8, b1i = m1 >> 11, tok1 = m1 & 2047;
#pragma unroll
            for (int nt = 0; nt < 4; nt++) {
                int dcol = nw * 32 + nt * 8 + t * 2;
                int n = n0 + dcol;
                float bv0 = bias[n], bv1 = bias[n + 1];
                float2 r0 = make_float2(rnd(acc[mt][nt][0] + bv0), rnd(acc[mt][nt][1] + bv1));
                float2 r1 = make_float2(rnd(acc[mt][nt][2] + bv0), rnd(acc[mt][nt][3] + bv1));
                *(float2*)(dst + ((size_t)(b0i * HH + hh) * TT + tok0) * DD + dcol) = r0;
                *(float2*)(dst + ((size_t)(b1i * HH + hh) * TT + tok1) * DD + dcol) = r1;
            }
        }
    } else {
#pragma unroll
        for (int mt = 0; mt < 2; mt++) {
            int m = m0 + mw * 32 + mt * 16 + g;
#pragma unroll
            for (int nt = 0; nt < 4; nt++) {
                int n = n0 + nw * 32 + nt * 8 + t * 2;
                float bv0 = bias[n], bv1 = bias[n + 1];
                float2 r0 = make_float2(acc[mt][nt][0] + bv0, acc[mt][nt][1] + bv1);
                float2 r1 = make_float2(acc[mt][nt][2] + bv0, acc[mt][nt][3] + bv1);
                *(float2*)(out + (size_t)m * CC + n) = r0;
                *(float2*)(out + (size_t)(m + 8) * CC + n) = r1;
            }
        }
    }
}

// ---------------------------------------------------------------------------
// tf32 MMA flash attention, k-split warp pairs. 256 thr = 8 warps.
// Warp (qgrp = w&3, kh = w>>2) owns 16 q-rows x 32 k-cols (its half).
// Independent online softmax per warp; (O, m, l) merged across the warp pair
// at CTA end via smem scratch overlaid on dead Ps+pm region.
// K/V cp.async double-buffered (raw; gmem values are tf32-rounded).
// LPT: longest-work CTAs launch first (qb remap per head direction).
// smem words: Q[0] K0[4352] V0[8704] K1[13056] V1[17408] Ps[21760]
//             pm[26112..28160); merge scratch overlays [21760..28160).
// ---------------------------------------------------------------------------
#define AQ   0
#define AK0  4352
#define AV0  8704
#define AK1  13056
#define AV1  17408
#define APS  21760
#define APM  26112
#define ATTN_SMEM ((28160) * 4)

__global__ __launch_bounds__(256) void attn_mma_kernel(const int* __restrict__ amask)
{
    extern __shared__ unsigned smu[];
    unsigned* Qs = smu + AQ;
    unsigned* Ps = smu + APS;
    float*    pmall = (float*)(smu + APM);

    const int bh = blockIdx.x;
    const int b = bh / HH, h = bh % HH;
    const bool left = (h < NLEFT);
    const int qb = left ? (TT / 64 - 1 - blockIdx.y) : blockIdx.y;   // LPT

    const float* Qg = g_q + (size_t)bh * TT * DD;
    const float* Kg = g_k + (size_t)bh * TT * DD;
    const float* Vg = g_v + (size_t)bh * TT * DD;

    const int tid = threadIdx.x;
    const int lane = tid & 31, warp = tid >> 5;
    const int g = lane >> 2, t = lane & 3;
    const int qgrp = warp & 3, kh = warp >> 2;
    const int rm = qgrp * 16;
    const int kc0 = kh * 32;                 // warp's k-col base

    const int a_row = (lane & 7) + ((lane >> 3) & 1) * 8;
    const int a_ws  = (lane >> 4) * 4;
    const int b_row = (lane & 7) + ((lane >> 4) << 3);
    const int b_ws  = ((lane >> 3) & 1) * 4;

    const uint32_t smb = smem_u32(smu);
    const uint32_t qad  = smb + (uint32_t)(((rm + a_row) * 68 + a_ws + AQ)  << 2);
    const uint32_t padr = smb + (uint32_t)(((rm + a_row) * 68 + kc0 + a_ws + APS) << 2);
    uint32_t kad[2];
#pragma unroll
    for (int p = 0; p < 2; p++)
        kad[p] = smb + (uint32_t)((AK0 + (kc0 + p * 16 + b_row) * 68 + b_ws) << 2);

    // Loader geometry (256 threads): K/V 1024 float4/buffer -> 4 per thread.
    const int lrow0 = tid >> 4;              // 0..15, +16 per i
    const int ld4   = (tid & 15) << 2;

    // Q load (scaled by 1/8, exact; inputs already tf32-rounded)
#pragma unroll
    for (int i = 0; i < 4; i++) {
        int row = lrow0 + i * 16;
        float4 v = *(const float4*)(Qg + (size_t)(qb * 64 + row) * DD + ld4);
        Qs[row * 68 + ld4 + 0] = f2tf32(v.x * 0.125f);
        Qs[row * 68 + ld4 + 1] = f2tf32(v.y * 0.125f);
        Qs[row * 68 + ld4 + 2] = f2tf32(v.z * 0.125f);
        Qs[row * 68 + ld4 + 3] = f2tf32(v.w * 0.125f);
    }
    // Padding penalties for the whole row
#pragma unroll
    for (int i = 0; i < 8; i++) {
        int idx = tid + i * 256;
        pmall[idx] = amask[b * TT + idx] ? 0.f : NEGF;
    }

    float m_r[2] = {NEGF, NEGF};
    float l_r[2] = {0.f, 0.f};
    float O[8][4];
#pragma unroll
    for (int nt = 0; nt < 8; nt++)
#pragma unroll
        for (int c = 0; c < 4; c++) O[nt][c] = 0.f;

    const int kb0 = left ? 0 : qb;
    const int kb1 = left ? qb : (TT / 64 - 1);
    const int qi0 = qb * 64 + rm + g, qi1 = qi0 + 8;
    // Diag-block halves that are entirely causally masked for this warp:
    const bool skipdiag = left ? (kh == 1 && rm < 32) : (kh == 0 && rm >= 32);

    // Prologue: prefetch kb0 into buffer 0
    {
        const float* Kp = Kg + (size_t)kb0 * 64 * DD;
        const float* Vp = Vg + (size_t)kb0 * 64 * DD;
        uint32_t kb_ = smb + AK0 * 4, vb_ = smb + AV0 * 4;
#pragma unroll
        for (int i = 0; i < 4; i++) {
            int row = lrow0 + i * 16;
            uint32_t off = (uint32_t)((row * 68 + ld4) << 2);
            cpa16(kb_ + off, Kp + row * DD + ld4);
            cpa16(vb_ + off, Vp + row * DD + ld4);
        }
        CPA_COMMIT();
    }

    for (int kb = kb0, it = 0; kb <= kb1; kb++, it++) {
        const int buf = it & 1;
        const uint32_t bufoff = (uint32_t)buf * ((AK1 - AK0) * 4);
        __syncthreads();                 // prev iter compute done (buf^1 free)
        if (kb + 1 <= kb1) {
            const float* Kp = Kg + (size_t)(kb + 1) * 64 * DD;
            const float* Vp = Vg + (size_t)(kb + 1) * 64 * DD;
            const uint32_t nbo = (uint32_t)(buf ^ 1) * ((AK1 - AK0) * 4);
            uint32_t kb_ = smb + AK0 * 4 + nbo, vb_ = smb + AV0 * 4 + nbo;
#pragma unroll
            for (int i = 0; i < 4; i++) {
                int row = lrow0 + i * 16;
                uint32_t off = (uint32_t)((row * 68 + ld4) << 2);
                cpa16(kb_ + off, Kp + row * DD + ld4);
                cpa16(vb_ + off, Vp + row * DD + ld4);
            }
            CPA_COMMIT();
            CPA_WAIT(1);
        } else {
            CPA_WAIT(0);
        }
        __syncthreads();                 // kb's K/V visible to all warps

        const bool diag = (kb == qb);
        if (diag && skipdiag) continue;  // barriers already passed; safe

        const unsigned* Vsb = smu + AV0 + buf * (AK1 - AK0);

        // S = Q @ K^T  (warp: 16 rows x its 32 cols)
        float S[4][4];
#pragma unroll
        for (int nt = 0; nt < 4; nt++)
#pragma unroll
            for (int c = 0; c < 4; c++) S[nt][c] = 0.f;

#pragma unroll
        for (int ks = 0; ks < 8; ks++) {
            const uint32_t ko = ks * 32;
            unsigned a0, a1, a2, a3;
            ldsm4(a0, a1, a2, a3, qad + ko);
#pragma unroll
            for (int p = 0; p < 2; p++) {
                unsigned k0, k1, k2, k3;
                ldsm4(k0, k1, k2, k3, kad[p] + bufoff + ko);
                mma8(S[2 * p],     a0, a1, a2, a3, k0, k1);
                mma8(S[2 * p + 1], a0, a1, a2, a3, k2, k3);
            }
        }

        // Mask + online softmax over this warp's 32 cols
        float mx0 = NEGF, mx1 = NEGF;
        const int kbase = kb * 64;
#pragma unroll
        for (int nt = 0; nt < 4; nt++) {
            int c0 = kc0 + nt * 8 + t * 2;
            float p0 = pmall[kbase + c0], p1 = pmall[kbase + c0 + 1];
            float s0 = S[nt][0] + p0, s1 = S[nt][1] + p1;
            float s2 = S[nt][2] + p0, s3 = S[nt][3] + p1;
            if (diag) {
                int k0i = kbase + c0, k1i = k0i + 1;
                if (left) {
                    if (k0i > qi0) s0 = NEGF;
                    if (k1i > qi0) s1 = NEGF;
                    if (k0i > qi1) s2 = NEGF;
                    if (k1i > qi1) s3 = NEGF;
                } else {
                    if (k0i < qi0) s0 = NEGF;
                    if (k1i < qi0) s1 = NEGF;
                    if (k0i < qi1) s2 = NEGF;
                    if (k1i < qi1) s3 = NEGF;
                }
            }
            S[nt][0] = s0; S[nt][1] = s1; S[nt][2] = s2; S[nt][3] = s3;
            mx0 = fmaxf(mx0, fmaxf(s0, s1));
            mx1 = fmaxf(mx1, fmaxf(s2, s3));
        }
        mx0 = fmaxf(mx0, __shfl_xor_sync(0xffffffffu, mx0, 1));
        mx0 = fmaxf(mx0, __shfl_xor_sync(0xffffffffu, mx0, 2));
        mx1 = fmaxf(mx1, __shfl_xor_sync(0xffffffffu, mx1, 1));
        mx1 = fmaxf(mx1, __shfl_xor_sync(0xffffffffu, mx1, 2));

        float mn0 = fmaxf(m_r[0], mx0), mn1 = fmaxf(m_r[1], mx1);
        float al0 = __expf(m_r[0] - mn0), al1 = __expf(m_r[1] - mn1);
        m_r[0] = mn0; m_r[1] = mn1;

        float rs0 = 0.f, rs1 = 0.f;
#pragma unroll
        for (int nt = 0; nt < 4; nt++) {
            float e0 = __expf(S[nt][0] - mn0), e1 = __expf(S[nt][1] - mn0);
            float e2 = __expf(S[nt][2] - mn1), e3 = __expf(S[nt][3] - mn1);
            S[nt][0] = e0; S[nt][1] = e1; S[nt][2] = e2; S[nt][3] = e3;
            rs0 += e0 + e1; rs1 += e2 + e3;
        }
        rs0 += __shfl_xor_sync(0xffffffffu, rs0, 1);
        rs0 += __shfl_xor_sync(0xffffffffu, rs0, 2);
        rs1 += __shfl_xor_sync(0xffffffffu, rs1, 1);
        rs1 += __shfl_xor_sync(0xffffffffu, rs1, 2);
        l_r[0] = l_r[0] * al0 + rs0;
        l_r[1] = l_r[1] * al1 + rs1;
#pragma unroll
        for (int nt = 0; nt < 8; nt++) {
            O[nt][0] *= al0; O[nt][1] *= al0;
            O[nt][2] *= al1; O[nt][3] *= al1;
        }

        // P -> smem (warp-private rows x warp-private cols)
        __syncwarp();
#pragma unroll
        for (int nt = 0; nt < 4; nt++) {
            int c0 = kc0 + nt * 8 + t * 2;
            Ps[(rm     + g) * 68 + c0    ] = f2tf32(S[nt][0]);
            Ps[(rm     + g) * 68 + c0 + 1] = f2tf32(S[nt][1]);
            Ps[(rm + 8 + g) * 68 + c0    ] = f2tf32(S[nt][2]);
            Ps[(rm + 8 + g) * 68 + c0 + 1] = f2tf32(S[nt][3]);
        }
        __syncwarp();

        // O += P(16 x its 32) @ V(its 32 x 64)
#pragma unroll
        for (int ks = 0; ks < 4; ks++) {
            const int kk = kc0 + ks * 8;
            unsigned a0, a1, a2, a3;
            ldsm4(a0, a1, a2, a3, padr + ks * 32);
#pragma unroll
            for (int nt = 0; nt < 8; nt++) {
                unsigned b0 = Vsb[(kk     + t) * 68 + nt * 8 + g];
                unsigned b1 = Vsb[(kk + 4 + t) * 68 + nt * 8 + g];
                mma8(O[nt], a0, a1, a2, a3, b0, b1);
            }
        }
    }

    // ----- Merge warp pair (kh=0 <- kh=1) and write ctx -----
    __syncthreads();                     // all compute done; Ps/pm dead
    float* sc = (float*)(smu + APS);     // scratch [4 warps][32 lanes][37]
    if (kh == 1) {
        int base = (qgrp * 32 + lane) * 37;
#pragma unroll
        for (int nt = 0; nt < 8; nt++) {
            sc[base + nt * 4 + 0] = O[nt][0];
            sc[base + nt * 4 + 1] = O[nt][1];
            sc[base + nt * 4 + 2] = O[nt][2];
            sc[base + nt * 4 + 3] = O[nt][3];
        }
        sc[base + 32] = m_r[0]; sc[base + 33] = m_r[1];
        sc[base + 34] = l_r[0]; sc[base + 35] = l_r[1];
    }
    __syncthreads();
    if (kh == 0) {
        int base = (qgrp * 32 + lane) * 37;
        float mb0 = sc[base + 32], mb1 = sc[base + 33];
        float lb0 = sc[base + 34], lb1 = sc[base + 35];
        float M0 = fmaxf(m_r[0], mb0), M1 = fmaxf(m_r[1], mb1);
        float sa0 = __expf(m_r[0] - M0), sb0 = __expf(mb0 - M0);
        float sa1 = __expf(m_r[1] - M1), sb1 = __expf(mb1 - M1);
        float L0 = l_r[0] * sa0 + lb0 * sb0;
        float L1 = l_r[1] * sa1 + lb1 * sb1;
        float inv0 = 1.0f / L0, inv1 = 1.0f / L1;
        int t0 = qb * 64 + rm + g, t1 = t0 + 8;
#pragma unroll
        for (int nt = 0; nt < 8; nt++) {
            float o0 = O[nt][0] * sa0 + sc[base + nt * 4 + 0] * sb0;
            float o1 = O[nt][1] * sa0 + sc[base + nt * 4 + 1] * sb0;
            float o2 = O[nt][2] * sa1 + sc[base + nt * 4 + 2] * sb1;
            float o3 = O[nt][3] * sa1 + sc[base + nt * 4 + 3] * sb1;
            int col = h * DD + nt * 8 + t * 2;
            *(float2*)(g_ctx + ((size_t)b * TT + t0) * CC + col) =
                make_float2(rnd(o0 * inv0), rnd(o1 * inv0));
            *(float2*)(g_ctx + ((size_t)b * TT + t1) * CC + col) =
                make_float2(rnd(o2 * inv1), rnd(o3 * inv1));
        }
    }
}

// ---------------------------------------------------------------------------
extern "C" void kernel_launch(void* const* d_in, const int* in_sizes, int n_in,
                              void* d_out, int out_size)
{
    const float* x      = (const float*)d_in[0];
    const int*   amask  = (const int*)  d_in[1];
    const float* Wqkv_w = (const float*)d_in[2];
    const float* Wqkv_b = (const float*)d_in[3];
    const float* Wo_w   = (const float*)d_in[4];
    const float* Wo_b   = (const float*)d_in[5];
    float* out = (float*)d_out;

    (void)in_sizes; (void)n_in; (void)out_size;

    cudaFuncSetAttribute(attn_mma_kernel,
                         cudaFuncAttributeMaxDynamicSharedMemorySize, ATTN_SMEM);
    cudaFuncSetAttribute(mma_gemm_kernel<0>,
                         cudaFuncAttributeMaxDynamicSharedMemorySize, GEMM_SMEM);
    cudaFuncSetAttribute(mma_gemm_kernel<1>,
                         cudaFuncAttributeMaxDynamicSharedMemorySize, GEMM_SMEM);

    preround_kernel<<<(PRN4 + 255) / 256, 256>>>(x, Wqkv_w, Wo_w);
    mma_gemm_kernel<0><<<dim3(N1 / 64, MM / 128), 256, GEMM_SMEM>>>(Wqkv_b, nullptr);
    attn_mma_kernel<<<dim3(BB * HH, TT / 64), 256, ATTN_SMEM>>>(amask);
    mma_gemm_kernel<1><<<dim3(CC / 64, MM / 128), 256, GEMM_SMEM>>>(Wo_b, out);
}

// round 13
// speedup vs baseline: 2.3459x; 1.0066x over previous
#include <cuda_runtime.h>
#include <cstdint>

#define BB 2
#define TT 2048
#define CC 768
#define HH 12
#define NLEFT 6
#define DD 64
#define MM (BB*TT)
#define N1 (3*CC)

#define NEGF (-3.402823466e38f)

// Scratch (device globals: allocation-free)
__device__ float g_q[BB*HH*TT*DD];
__device__ float g_k[BB*HH*TT*DD];
__device__ float g_v[BB*HH*TT*DD];
__device__ float g_ctx[BB*TT*CC];
// Pre-rounded (tf32) copies of GEMM inputs
__device__ float g_xr[MM*CC];
__device__ float g_w1r[N1*CC];
__device__ float g_w2r[CC*CC];

__device__ __forceinline__ unsigned f2tf32(float f) {
    unsigned r;
    asm("cvt.rna.tf32.f32 %0, %1;" : "=r"(r) : "f"(f));
    return r;
}
__device__ __forceinline__ float rnd(float f) { return __uint_as_float(f2tf32(f)); }

__device__ __forceinline__ uint32_t smem_u32(const void* p) {
    uint32_t a;
    asm("{ .reg .u64 t; cvta.to.shared.u64 t, %1; cvt.u32.u64 %0, t; }"
        : "=r"(a) : "l"(p));
    return a;
}
__device__ __forceinline__ void cpa16(uint32_t d, const void* s) {
    asm volatile("cp.async.cg.shared.global [%0], [%1], 16;" :: "r"(d), "l"(s));
}
#define CPA_COMMIT() asm volatile("cp.async.commit_group;" ::: "memory")
#define CPA_WAIT(n)  asm volatile("cp.async.wait_group %0;" :: "n"(n) : "memory")

__device__ __forceinline__ void ldsm4(unsigned& r0, unsigned& r1,
                                      unsigned& r2, unsigned& r3, uint32_t addr) {
    asm volatile("ldmatrix.sync.aligned.m8n8.x4.shared.b16 {%0,%1,%2,%3}, [%4];"
                 : "=r"(r0), "=r"(r1), "=r"(r2), "=r"(r3) : "r"(addr));
}
__device__ __forceinline__ void mma8(float* d,
    unsigned a0, unsigned a1, unsigned a2, unsigned a3,
    unsigned b0, unsigned b1)
{
    asm volatile(
        "mma.sync.aligned.m16n8k8.row.col.f32.tf32.tf32.f32 "
        "{%0,%1,%2,%3}, {%4,%5,%6,%7}, {%8,%9}, {%0,%1,%2,%3};"
        : "+f"(d[0]), "+f"(d[1]), "+f"(d[2]), "+f"(d[3])
        : "r"(a0), "r"(a1), "r"(a2), "r"(a3), "r"(b0), "r"(b1));
}

// ---------------------------------------------------------------------------
// Pre-round inputs to tf32 (idempotent wrt all downstream cvt.rna).
// ---------------------------------------------------------------------------
#define XN4  (MM*CC/4)
#define W1N4 (N1*CC/4)
#define W2N4 (CC*CC/4)
#define PRN4 (XN4 + W1N4 + W2N4)

__global__ __launch_bounds__(256) void preround_kernel(
    const float* __restrict__ x, const float* __restrict__ w1,
    const float* __restrict__ w2)
{
    int i = blockIdx.x * 256 + threadIdx.x;
    if (i >= PRN4) return;
    const float* src; float* dst; int j;
    if (i < XN4)              { src = x;  dst = g_xr;  j = i; }
    else if (i < XN4 + W1N4)  { src = w1; dst = g_w1r; j = i - XN4; }
    else                      { src = w2; dst = g_w2r; j = i - XN4 - W1N4; }
    float4 v = *(const float4*)(src + (size_t)j * 4);
    float4 o = make_float4(rnd(v.x), rnd(v.y), rnd(v.z), rnd(v.w));
    *(float4*)(dst + (size_t)j * 4) = o;
}

// ---------------------------------------------------------------------------
// tf32 MMA GEMM, cp.async 2-stage, SINGLE barrier per chunk:
//   wait(0) -> syncthreads -> prefetch(c+1, other buf) -> compute(c).
// The one barrier proves chunk-c data visible AND compute(c-1) (last reader
// of the buffer prefetch overwrites) finished.
// ---------------------------------------------------------------------------
#define GW_A   (128*36)
#define GW_B   (64*36)
#define GW_PR  (GW_A + GW_B)
#define GEMM_SMEM (2 * GW_PR * 4)
#define NCH (CC/32)

template<int MODE>
__global__ __launch_bounds__(256) void mma_gemm_kernel(
    const float* __restrict__ bias, float* __restrict__ out)
{
    extern __shared__ unsigned sm[];

    const float* Ag = (MODE == 0) ? (const float*)g_xr  : (const float*)g_ctx;
    const float* W  = (MODE == 0) ? (const float*)g_w1r : (const float*)g_w2r;

    const int K = CC;
    const int tid  = threadIdx.x;
    const int lane = tid & 31, warp = tid >> 5;
    const int mw = warp >> 1, nw = warp & 1;
    const int m0 = blockIdx.y * 128, n0 = blockIdx.x * 64;
    const int g = lane >> 2, t = lane & 3;

    const uint32_t smb = smem_u32(sm);

    const int a_row = (lane & 7) + ((lane >> 3) & 1) * 8;
    const int a_ws  = (lane >> 4) * 4;
    const int b_row = (lane & 7) + ((lane >> 4) << 3);
    const int b_ws  = ((lane >> 3) & 1) * 4;

    const uint32_t aad0 = smb + (uint32_t)(((mw * 32 + a_row) * 36 + a_ws) << 2);
    const uint32_t aad1 = aad0 + 16 * 36 * 4;
    const uint32_t bad0 = smb + (uint32_t)((GW_A + (nw * 32 + b_row) * 36 + b_ws) << 2);
    const uint32_t bad1 = bad0 + 16 * 36 * 4;

    const int lrow = tid >> 3;
    const int lkq  = (tid & 7) << 2;

    float acc[2][4][4];
#pragma unroll
    for (int mt = 0; mt < 2; mt++)
#pragma unroll
        for (int nt = 0; nt < 4; nt++)
#pragma unroll
            for (int c = 0; c < 4; c++) acc[mt][nt][c] = 0.f;

    {   // prefetch chunk 0 into buffer 0
        uint32_t ab = smb, bb = smb + GW_A * 4;
#pragma unroll
        for (int i = 0; i < 4; i++) {
            int row = lrow + i * 32;
            cpa16(ab + (uint32_t)((row * 36 + lkq) << 2),
                  Ag + (size_t)(m0 + row) * K + lkq);
        }
#pragma unroll
        for (int i = 0; i < 2; i++) {
            int row = lrow + i * 32;
            cpa16(bb + (uint32_t)((row * 36 + lkq) << 2),
                  W + (size_t)(n0 + row) * K + lkq);
        }
        CPA_COMMIT();
    }

    for (int c = 0; c < NCH; c++) {
        const uint32_t bo = (uint32_t)(c & 1) * (GW_PR * 4);
        CPA_WAIT(0);
        __syncthreads();                 // chunk c visible; buf^1 free
        if (c + 1 < NCH) {
            const int k0n = (c + 1) * 32;
            const uint32_t nbo = (uint32_t)((c + 1) & 1) * (GW_PR * 4);
            uint32_t ab = smb + nbo, bb = smb + nbo + GW_A * 4;
#pragma unroll
            for (int i = 0; i < 4; i++) {
                int row = lrow + i * 32;
                cpa16(ab + (uint32_t)((row * 36 + lkq) << 2),
                      Ag + (size_t)(m0 + row) * K + k0n + lkq);
            }
#pragma unroll
            for (int i = 0; i < 2; i++) {
                int row = lrow + i * 32;
                cpa16(bb + (uint32_t)((row * 36 + lkq) << 2),
                      W + (size_t)(n0 + row) * K + k0n + lkq);
            }
            CPA_COMMIT();
        }

#pragma unroll
        for (int ks = 0; ks < 4; ks++) {
            const uint32_t ko = bo + ks * 32;
            unsigned a0[4], a1[4], bA[4], bBr[4];
            ldsm4(a0[0], a0[1], a0[2], a0[3], aad0 + ko);
            ldsm4(a1[0], a1[1], a1[2], a1[3], aad1 + ko);
            ldsm4(bA[0], bA[1], bA[2], bA[3], bad0 + ko);
            ldsm4(bBr[0], bBr[1], bBr[2], bBr[3], bad1 + ko);
            mma8(acc[0][0], a0[0], a0[1], a0[2], a0[3], bA[0], bA[1]);
            mma8(acc[0][1], a0[0], a0[1], a0[2], a0[3], bA[2], bA[3]);
            mma8(acc[0][2], a0[0], a0[1], a0[2], a0[3], bBr[0], bBr[1]);
            mma8(acc[0][3], a0[0], a0[1], a0[2], a0[3], bBr[2], bBr[3]);
            mma8(acc[1][0], a1[0], a1[1], a1[2], a1[3], bA[0], bA[1]);
            mma8(acc[1][1], a1[0], a1[1], a1[2], a1[3], bA[2], bA[3]);
            mma8(acc[1][2], a1[0], a1[1], a1[2], a1[3], bBr[0], bBr[1]);
            mma8(acc[1][3], a1[0], a1[1], a1[2], a1[3], bBr[2], bBr[3]);
        }
    }

    if (MODE == 0) {
        const int s  = n0 / CC;
        const int hh = (n0 % CC) / DD;
        float* dst = (s == 0) ? g_q : ((s == 1) ? g_k : g_v);
#pragma unroll
        for (int mt = 0; mt < 2; mt++) {
            int m = m0 + mw * 32 + mt * 16 + g;
            int b0i = m >> 11, tok0 = m & 2047;
            int m1 = m + 8, b1i = m1 >> 11, tok1 = m1 & 2047;
#pragma unroll
            for (int nt = 0; nt < 4; nt++) {
                int dcol = nw * 32 + nt * 8 + t * 2;
                int n = n0 + dcol;
                float bv0 = bias[n], bv1 = bias[n + 1];
                float2 r0 = make_float2(rnd(acc[mt][nt][0] + bv0), rnd(acc[mt][nt][1] + bv1));
                float2 r1 = make_float2(rnd(acc[mt][nt][2] + bv0), rnd(acc[mt][nt][3] + bv1));
                *(float2*)(dst + ((size_t)(b0i * HH + hh) * TT + tok0) * DD + dcol) = r0;
                *(float2*)(dst + ((size_t)(b1i * HH + hh) * TT + tok1) * DD + dcol) = r1;
            }
        }
    } else {
#pragma unroll
        for (int mt = 0; mt < 2; mt++) {
            int m = m0 + mw * 32 + mt * 16 + g;
#pragma unroll
            for (int nt = 0; nt < 4; nt++) {
                int n = n0 + nw * 32 + nt * 8 + t * 2;
                float bv0 = bias[n], bv1 = bias[n + 1];
                float2 r0 = make_float2(acc[mt][nt][0] + bv0, acc[mt][nt][1] + bv1);
                float2 r1 = make_float2(acc[mt][nt][2] + bv0, acc[mt][nt][3] + bv1);
                *(float2*)(out + (size_t)m * CC + n) = r0;
                *(float2*)(out + (size_t)(m + 8) * CC + n) = r1;
            }
        }
    }
}

// ---------------------------------------------------------------------------
// tf32 MMA flash attention, k-split warp pairs + single barrier per k-block.
// ---------------------------------------------------------------------------
#define AQ   0
#define AK0  4352
#define AV0  8704
#define AK1  13056
#define AV1  17408
#define APS  21760
#define APM  26112
#define ATTN_SMEM ((28160) * 4)

__global__ __launch_bounds__(256) void attn_mma_kernel(const int* __restrict__ amask)
{
    extern __shared__ unsigned smu[];
    unsigned* Qs = smu + AQ;
    unsigned* Ps = smu + APS;
    float*    pmall = (float*)(smu + APM);

    const int bh = blockIdx.x;
    const int b = bh / HH, h = bh % HH;
    const bool left = (h < NLEFT);
    const int qb = left ? (TT / 64 - 1 - blockIdx.y) : blockIdx.y;   // LPT

    const float* Qg = g_q + (size_t)bh * TT * DD;
    const float* Kg = g_k + (size_t)bh * TT * DD;
    const float* Vg = g_v + (size_t)bh * TT * DD;

    const int tid = threadIdx.x;
    const int lane = tid & 31, warp = tid >> 5;
    const int g = lane >> 2, t = lane & 3;
    const int qgrp = warp & 3, kh = warp >> 2;
    const int rm = qgrp * 16;
    const int kc0 = kh * 32;

    const int a_row = (lane & 7) + ((lane >> 3) & 1) * 8;
    const int a_ws  = (lane >> 4) * 4;
    const int b_row = (lane & 7) + ((lane >> 4) << 3);
    const int b_ws  = ((lane >> 3) & 1) * 4;

    const uint32_t smb = smem_u32(smu);
    const uint32_t qad  = smb + (uint32_t)(((rm + a_row) * 68 + a_ws + AQ)  << 2);
    const uint32_t padr = smb + (uint32_t)(((rm + a_row) * 68 + kc0 + a_ws + APS) << 2);
    uint32_t kad[2];
#pragma unroll
    for (int p = 0; p < 2; p++)
        kad[p] = smb + (uint32_t)((AK0 + (kc0 + p * 16 + b_row) * 68 + b_ws) << 2);

    const int lrow0 = tid >> 4;
    const int ld4   = (tid & 15) << 2;

    // Q load (scaled by 1/8, exact; inputs already tf32-rounded)
#pragma unroll
    for (int i = 0; i < 4; i++) {
        int row = lrow0 + i * 16;
        float4 v = *(const float4*)(Qg + (size_t)(qb * 64 + row) * DD + ld4);
        Qs[row * 68 + ld4 + 0] = f2tf32(v.x * 0.125f);
        Qs[row * 68 + ld4 + 1] = f2tf32(v.y * 0.125f);
        Qs[row * 68 + ld4 + 2] = f2tf32(v.z * 0.125f);
        Qs[row * 68 + ld4 + 3] = f2tf32(v.w * 0.125f);
    }
#pragma unroll
    for (int i = 0; i < 8; i++) {
        int idx = tid + i * 256;
        pmall[idx] = amask[b * TT + idx] ? 0.f : NEGF;
    }

    float m_r[2] = {NEGF, NEGF};
    float l_r[2] = {0.f, 0.f};
    float O[8][4];
#pragma unroll
    for (int nt = 0; nt < 8; nt++)
#pragma unroll
        for (int c = 0; c < 4; c++) O[nt][c] = 0.f;

    const int kb0 = left ? 0 : qb;
    const int kb1 = left ? qb : (TT / 64 - 1);
    const int qi0 = qb * 64 + rm + g, qi1 = qi0 + 8;
    const bool skipdiag = left ? (kh == 1 && rm < 32) : (kh == 0 && rm >= 32);

    {   // prologue: prefetch kb0 into buffer 0
        const float* Kp = Kg + (size_t)kb0 * 64 * DD;
        const float* Vp = Vg + (size_t)kb0 * 64 * DD;
        uint32_t kb_ = smb + AK0 * 4, vb_ = smb + AV0 * 4;
#pragma unroll
        for (int i = 0; i < 4; i++) {
            int row = lrow0 + i * 16;
            uint32_t off = (uint32_t)((row * 68 + ld4) << 2);
            cpa16(kb_ + off, Kp + row * DD + ld4);
            cpa16(vb_ + off, Vp + row * DD + ld4);
        }
        CPA_COMMIT();
    }

    for (int kb = kb0, it = 0; kb <= kb1; kb++, it++) {
        const int buf = it & 1;
        const uint32_t bufoff = (uint32_t)buf * ((AK1 - AK0) * 4);
        CPA_WAIT(0);
        __syncthreads();                 // kb visible; other buffer free
        if (kb + 1 <= kb1) {
            const float* Kp = Kg + (size_t)(kb + 1) * 64 * DD;
            const float* Vp = Vg + (size_t)(kb + 1) * 64 * DD;
            const uint32_t nbo = (uint32_t)(buf ^ 1) * ((AK1 - AK0) * 4);
            uint32_t kb_ = smb + AK0 * 4 + nbo, vb_ = smb + AV0 * 4 + nbo;
#pragma unroll
            for (int i = 0; i < 4; i++) {
                int row = lrow0 + i * 16;
                uint32_t off = (uint32_t)((row * 68 + ld4) << 2);
                cpa16(kb_ + off, Kp + row * DD + ld4);
                cpa16(vb_ + off, Vp + row * DD + ld4);
            }
            CPA_COMMIT();
        }

        const bool diag = (kb == qb);
        if (diag && skipdiag) continue;  // prefetch already issued; safe

        const unsigned* Vsb = smu + AV0 + buf * (AK1 - AK0);

        // S = Q @ K^T  (warp: 16 rows x its 32 cols)
        float S[4][4];
#pragma unroll
        for (int nt = 0; nt < 4; nt++)
#pragma unroll
            for (int c = 0; c < 4; c++) S[nt][c] = 0.f;

#pragma unroll
        for (int ks = 0; ks < 8; ks++) {
            const uint32_t ko = ks * 32;
            unsigned a0, a1, a2, a3;
            ldsm4(a0, a1, a2, a3, qad + ko);
#pragma unroll
            for (int p = 0; p < 2; p++) {
                unsigned k0, k1, k2, k3;
                ldsm4(k0, k1, k2, k3, kad[p] + bufoff + ko);
                mma8(S[2 * p],     a0, a1, a2, a3, k0, k1);
                mma8(S[2 * p + 1], a0, a1, a2, a3, k2, k3);
            }
        }

        // Mask + online softmax over this warp's 32 cols
        float mx0 = NEGF, mx1 = NEGF;
        const int kbase = kb * 64;
#pragma unroll
        for (int nt = 0; nt < 4; nt++) {
            int c0 = kc0 + nt * 8 + t * 2;
            float p0 = pmall[kbase + c0], p1 = pmall[kbase + c0 + 1];
            float s0 = S[nt][0] + p0, s1 = S[nt][1] + p1;
            float s2 = S[nt][2] + p0, s3 = S[nt][3] + p1;
            if (diag) {
                int k0i = kbase + c0, k1i = k0i + 1;
                if (left) {
                    if (k0i > qi0) s0 = NEGF;
                    if (k1i > qi0) s1 = NEGF;
                    if (k0i > qi1) s2 = NEGF;
                    if (k1i > qi1) s3 = NEGF;
                } else {
                    if (k0i < qi0) s0 = NEGF;
                    if (k1i < qi0) s1 = NEGF;
                    if (k0i < qi1) s2 = NEGF;
                    if (k1i < qi1) s3 = NEGF;
                }
            }
            S[nt][0] = s0; S[nt][1] = s1; S[nt][2] = s2; S[nt][3] = s3;
            mx0 = fmaxf(mx0, fmaxf(s0, s1));
            mx1 = fmaxf(mx1, fmaxf(s2, s3));
        }
        mx0 = fmaxf(mx0, __shfl_xor_sync(0xffffffffu, mx0, 1));
        mx0 = fmaxf(mx0, __shfl_xor_sync(0xffffffffu, mx0, 2));
        mx1 = fmaxf(mx1, __shfl_xor_sync(0xffffffffu, mx1, 1));
        mx1 = fmaxf(mx1, __shfl_xor_sync(0xffffffffu, mx1, 2));

        float mn0 = fmaxf(m_r[0], mx0), mn1 = fmaxf(m_r[1], mx1);
        float al0 = __expf(m_r[0] - mn0), al1 = __expf(m_r[1] - mn1);
        m_r[0] = mn0; m_r[1] = mn1;

        float rs0 = 0.f, rs1 = 0.f;
#pragma unroll
        for (int nt = 0; nt < 4; nt++) {
            float e0 = __expf(S[nt][0] - mn0), e1 = __expf(S[nt][1] - mn0);
            float e2 = __expf(S[nt][2] - mn1), e3 = __expf(S[nt][3] - mn1);
            S[nt][0] = e0; S[nt][1] = e1; S[nt][2] = e2; S[nt][3] = e3;
            rs0 += e0 + e1; rs1 += e2 + e3;
        }
        rs0 += __shfl_xor_sync(0xffffffffu, rs0, 1);
        rs0 += __shfl_xor_sync(0xffffffffu, rs0, 2);
        rs1 += __shfl_xor_sync(0xffffffffu, rs1, 1);
        rs1 += __shfl_xor_sync(0xffffffffu, rs1, 2);
        l_r[0] = l_r[0] * al0 + rs0;
        l_r[1] = l_r[1] * al1 + rs1;
#pragma unroll
        for (int nt = 0; nt < 8; nt++) {
            O[nt][0] *= al0; O[nt][1] *= al0;
            O[nt][2] *= al1; O[nt][3] *= al1;
        }

        // P -> smem (warp-private rows x warp-private cols)
        __syncwarp();
#pragma unroll
        for (int nt = 0; nt < 4; nt++) {
            int c0 = kc0 + nt * 8 + t * 2;
            Ps[(rm     + g) * 68 + c0    ] = f2tf32(S[nt][0]);
            Ps[(rm     + g) * 68 + c0 + 1] = f2tf32(S[nt][1]);
            Ps[(rm + 8 + g) * 68 + c0    ] = f2tf32(S[nt][2]);
            Ps[(rm + 8 + g) * 68 + c0 + 1] = f2tf32(S[nt][3]);
        }
        __syncwarp();

        // O += P(16 x its 32) @ V(its 32 x 64)
#pragma unroll
        for (int ks = 0; ks < 4; ks++) {
            const int kk = kc0 + ks * 8;
            unsigned a0, a1, a2, a3;
            ldsm4(a0, a1, a2, a3, padr + ks * 32);
#pragma unroll
            for (int nt = 0; nt < 8; nt++) {
                unsigned b0 = Vsb[(kk     + t) * 68 + nt * 8 + g];
                unsigned b1 = Vsb[(kk + 4 + t) * 68 + nt * 8 + g];
                mma8(O[nt], a0, a1, a2, a3, b0, b1);
            }
        }
    }

    // ----- Merge warp pair (kh=0 <- kh=1) and write ctx -----
    __syncthreads();                     // all compute done; Ps/pm dead
    float* sc = (float*)(smu + APS);     // scratch [4 warps][32 lanes][37]
    if (kh == 1) {
        int base = (qgrp * 32 + lane) * 37;
#pragma unroll
        for (int nt = 0; nt < 8; nt++) {
            sc[base + nt * 4 + 0] = O[nt][0];
            sc[base + nt * 4 + 1] = O[nt][1];
            sc[base + nt * 4 + 2] = O[nt][2];
            sc[base + nt * 4 + 3] = O[nt][3];
        }
        sc[base + 32] = m_r[0]; sc[base + 33] = m_r[1];
        sc[base + 34] = l_r[0]; sc[base + 35] = l_r[1];
    }
    __syncthreads();
    if (kh == 0) {
        int base = (qgrp * 32 + lane) * 37;
        float mb0 = sc[base + 32], mb1 = sc[base + 33];
        float lb0 = sc[base + 34], lb1 = sc[base + 35];
        float M0 = fmaxf(m_r[0], mb0), M1 = fmaxf(m_r[1], mb1);
        float sa0 = __expf(m_r[0] - M0), sb0 = __expf(mb0 - M0);
        float sa1 = __expf(m_r[1] - M1), sb1 = __expf(mb1 - M1);
        float L0 = l_r[0] * sa0 + lb0 * sb0;
        float L1 = l_r[1] * sa1 + lb1 * sb1;
        float inv0 = 1.0f / L0, inv1 = 1.0f / L1;
        int t0 = qb * 64 + rm + g, t1 = t0 + 8;
#pragma unroll
        for (int nt = 0; nt < 8; nt++) {
            float o0 = O[nt][0] * sa0 + sc[base + nt * 4 + 0] * sb0;
            float o1 = O[nt][1] * sa0 + sc[base + nt * 4 + 1] * sb0;
            float o2 = O[nt][2] * sa1 + sc[base + nt * 4 + 2] * sb1;
            float o3 = O[nt][3] * sa1 + sc[base + nt * 4 + 3] * sb1;
            int col = h * DD + nt * 8 + t * 2;
            *(float2*)(g_ctx + ((size_t)b * TT + t0) * CC + col) =
                make_float2(rnd(o0 * inv0), rnd(o1 * inv0));
            *(float2*)(g_ctx + ((size_t)b * TT + t1) * CC + col) =
                make_float2(rnd(o2 * inv1), rnd(o3 * inv1));
        }
    }
}

// ---------------------------------------------------------------------------
extern "C" void kernel_launch(void* const* d_in, const int* in_sizes, int n_in,
                              void* d_out, int out_size)
{
    const float* x      = (const float*)d_in[0];
    const int*   amask  = (const int*)  d_in[1];
    const float* Wqkv_w = (const float*)d_in[2];
    const float* Wqkv_b = (const float*)d_in[3];
    const float* Wo_w   = (const float*)d_in[4];
    const float* Wo_b   = (const float*)d_in[5];
    float* out = (float*)d_out;

    (void)in_sizes; (void)n_in; (void)out_size;

    cudaFuncSetAttribute(attn_mma_kernel,
                         cudaFuncAttributeMaxDynamicSharedMemorySize, ATTN_SMEM);
    cudaFuncSetAttribute(mma_gemm_kernel<0>,
                         cudaFuncAttributeMaxDynamicSharedMemorySize, GEMM_SMEM);
    cudaFuncSetAttribute(mma_gemm_kernel<1>,
                         cudaFuncAttributeMaxDynamicSharedMemorySize, GEMM_SMEM);

    preround_kernel<<<(PRN4 + 255) / 256, 256>>>(x, Wqkv_w, Wo_w);
    mma_gemm_kernel<0><<<dim3(N1 / 64, MM / 128), 256, GEMM_SMEM>>>(Wqkv_b, nullptr);
    attn_mma_kernel<<<dim3(BB * HH, TT / 64), 256, ATTN_SMEM>>>(amask);
    mma_gemm_kernel<1><<<dim3(CC / 64, MM / 128), 256, GEMM_SMEM>>>(Wo_b, out);
}

// round 14
// speedup vs baseline: 2.3530x; 1.0030x over previous
#include <cuda_runtime.h>
#include <cstdint>

#define BB 2
#define TT 2048
#define CC 768
#define HH 12
#define NLEFT 6
#define DD 64
#define MM (BB*TT)
#define N1 (3*CC)

#define NEGF (-3.402823466e38f)

// Scratch (device globals: allocation-free)
__device__ float g_q[BB*HH*TT*DD];
__device__ float g_k[BB*HH*TT*DD];
__device__ float g_v[BB*HH*TT*DD];
__device__ float g_ctx[BB*TT*CC];
// Pre-rounded (tf32) copies of GEMM inputs
__device__ float g_xr[MM*CC];
__device__ float g_w1r[N1*CC];
__device__ float g_w2r[CC*CC];

__device__ __forceinline__ unsigned f2tf32(float f) {
    unsigned r;
    asm("cvt.rna.tf32.f32 %0, %1;" : "=r"(r) : "f"(f));
    return r;
}
__device__ __forceinline__ float rnd(float f) { return __uint_as_float(f2tf32(f)); }

__device__ __forceinline__ uint32_t smem_u32(const void* p) {
    uint32_t a;
    asm("{ .reg .u64 t; cvta.to.shared.u64 t, %1; cvt.u32.u64 %0, t; }"
        : "=r"(a) : "l"(p));
    return a;
}
__device__ __forceinline__ void cpa16(uint32_t d, const void* s) {
    asm volatile("cp.async.cg.shared.global [%0], [%1], 16;" :: "r"(d), "l"(s));
}
#define CPA_COMMIT() asm volatile("cp.async.commit_group;" ::: "memory")
#define CPA_WAIT(n)  asm volatile("cp.async.wait_group %0;" :: "n"(n) : "memory")

__device__ __forceinline__ void ldsm4(unsigned& r0, unsigned& r1,
                                      unsigned& r2, unsigned& r3, uint32_t addr) {
    asm volatile("ldmatrix.sync.aligned.m8n8.x4.shared.b16 {%0,%1,%2,%3}, [%4];"
                 : "=r"(r0), "=r"(r1), "=r"(r2), "=r"(r3) : "r"(addr));
}
__device__ __forceinline__ void mma8(float* d,
    unsigned a0, unsigned a1, unsigned a2, unsigned a3,
    unsigned b0, unsigned b1)
{
    asm volatile(
        "mma.sync.aligned.m16n8k8.row.col.f32.tf32.tf32.f32 "
        "{%0,%1,%2,%3}, {%4,%5,%6,%7}, {%8,%9}, {%0,%1,%2,%3};"
        : "+f"(d[0]), "+f"(d[1]), "+f"(d[2]), "+f"(d[3])
        : "r"(a0), "r"(a1), "r"(a2), "r"(a3), "r"(b0), "r"(b1));
}

// ---------------------------------------------------------------------------
// Pre-round inputs to tf32 (idempotent wrt all downstream cvt.rna).
// ---------------------------------------------------------------------------
#define XN4  (MM*CC/4)
#define W1N4 (N1*CC/4)
#define W2N4 (CC*CC/4)
#define PRN4 (XN4 + W1N4 + W2N4)

__global__ __launch_bounds__(256) void preround_kernel(
    const float* __restrict__ x, const float* __restrict__ w1,
    const float* __restrict__ w2)
{
    int i = blockIdx.x * 256 + threadIdx.x;
    if (i >= PRN4) return;
    const float* src; float* dst; int j;
    if (i < XN4)              { src = x;  dst = g_xr;  j = i; }
    else if (i < XN4 + W1N4)  { src = w1; dst = g_w1r; j = i - XN4; }
    else                      { src = w2; dst = g_w2r; j = i - XN4 - W1N4; }
    float4 v = *(const float4*)(src + (size_t)j * 4);
    float4 o = make_float4(rnd(v.x), rnd(v.y), rnd(v.z), rnd(v.w));
    *(float4*)(dst + (size_t)j * 4) = o;
}

// ---------------------------------------------------------------------------
// tf32 MMA GEMM, 128x128 CTA tile, cp.async 2-stage single-barrier pipeline.
// 256 thr = 8 warps (4M x 2N), warp tile 32x64 -> 16 MMAs per 6 LDSM.x4.
// cp.async stages loads with ZERO registers (this is what R4 lacked).
// MODE 0: A = g_xr, W = g_w1r, scatter tf32-rounded to g_q/g_k/g_v.
// MODE 1: A = g_ctx, W = g_w2r, write out (full fp32).
// ---------------------------------------------------------------------------
#define GW_A   (128*36)
#define GW_PR  (2*GW_A)               // 9216 words / buffer
#define GEMM_SMEM (2 * GW_PR * 4)     // 73728 B
#define NCH (CC/32)

template<int MODE>
__global__ __launch_bounds__(256) void mma_gemm_kernel(
    const float* __restrict__ bias, float* __restrict__ out)
{
    extern __shared__ unsigned sm[];

    const float* Ag = (MODE == 0) ? (const float*)g_xr  : (const float*)g_ctx;
    const float* W  = (MODE == 0) ? (const float*)g_w1r : (const float*)g_w2r;

    const int K = CC;
    const int tid  = threadIdx.x;
    const int lane = tid & 31, warp = tid >> 5;
    const int mw = warp >> 1, nw = warp & 1;
    const int m0 = blockIdx.y * 128, n0 = blockIdx.x * 128;
    const int g = lane >> 2, t = lane & 3;

    const uint32_t smb = smem_u32(sm);

    const int a_row = (lane & 7) + ((lane >> 3) & 1) * 8;
    const int a_ws  = (lane >> 4) * 4;
    const int b_row = (lane & 7) + ((lane >> 4) << 3);
    const int b_ws  = ((lane >> 3) & 1) * 4;

    const uint32_t aad0 = smb + (uint32_t)(((mw * 32 + a_row) * 36 + a_ws) << 2);
    const uint32_t aad1 = aad0 + 16 * 36 * 4;
    uint32_t bad[4];
#pragma unroll
    for (int p = 0; p < 4; p++)
        bad[p] = smb + (uint32_t)((GW_A + (nw * 64 + p * 16 + b_row) * 36 + b_ws) << 2);

    const int lrow = tid >> 3;           // 0..31, +32 per i
    const int lkq  = (tid & 7) << 2;

    float acc[2][8][4];
#pragma unroll
    for (int mt = 0; mt < 2; mt++)
#pragma unroll
        for (int nt = 0; nt < 8; nt++)
#pragma unroll
            for (int c = 0; c < 4; c++) acc[mt][nt][c] = 0.f;

    {   // prefetch chunk 0 into buffer 0
        uint32_t ab = smb, bb = smb + GW_A * 4;
#pragma unroll
        for (int i = 0; i < 4; i++) {
            int row = lrow + i * 32;
            cpa16(ab + (uint32_t)((row * 36 + lkq) << 2),
                  Ag + (size_t)(m0 + row) * K + lkq);
            cpa16(bb + (uint32_t)((row * 36 + lkq) << 2),
                  W + (size_t)(n0 + row) * K + lkq);
        }
        CPA_COMMIT();
    }

    for (int c = 0; c < NCH; c++) {
        const uint32_t bo = (uint32_t)(c & 1) * (GW_PR * 4);
        CPA_WAIT(0);
        __syncthreads();                 // chunk c visible; buf^1 free
        if (c + 1 < NCH) {
            const int k0n = (c + 1) * 32;
            const uint32_t nbo = (uint32_t)((c + 1) & 1) * (GW_PR * 4);
            uint32_t ab = smb + nbo, bb = smb + nbo + GW_A * 4;
#pragma unroll
            for (int i = 0; i < 4; i++) {
                int row = lrow + i * 32;
                cpa16(ab + (uint32_t)((row * 36 + lkq) << 2),
                      Ag + (size_t)(m0 + row) * K + k0n + lkq);
                cpa16(bb + (uint32_t)((row * 36 + lkq) << 2),
                      W + (size_t)(n0 + row) * K + k0n + lkq);
            }
            CPA_COMMIT();
        }

#pragma unroll
        for (int ks = 0; ks < 4; ks++) {
            const uint32_t ko = bo + ks * 32;
            unsigned a0[4], a1[4];
            ldsm4(a0[0], a0[1], a0[2], a0[3], aad0 + ko);
            ldsm4(a1[0], a1[1], a1[2], a1[3], aad1 + ko);
#pragma unroll
            for (int p = 0; p < 4; p++) {
                unsigned bf[4];
                ldsm4(bf[0], bf[1], bf[2], bf[3], bad[p] + ko);
                mma8(acc[0][2*p],   a0[0], a0[1], a0[2], a0[3], bf[0], bf[1]);
                mma8(acc[0][2*p+1], a0[0], a0[1], a0[2], a0[3], bf[2], bf[3]);
                mma8(acc[1][2*p],   a1[0], a1[1], a1[2], a1[3], bf[0], bf[1]);
                mma8(acc[1][2*p+1], a1[0], a1[1], a1[2], a1[3], bf[2], bf[3]);
            }
        }
    }

    // Epilogue. C frag rows g, g+8; cols t*2, t*2+1. Warp n-span = one head.
    if (MODE == 0) {
        const int s  = n0 / CC;                     // 128 | 768
        const int hh = ((n0 % CC) >> 6) + nw;       // warp's head
        float* dst = (s == 0) ? g_q : ((s == 1) ? g_k : g_v);
#pragma unroll
        for (int mt = 0; mt < 2; mt++) {
            int m = m0 + mw * 32 + mt * 16 + g;
            int b0i = m >> 11, tok0 = m & 2047;
            int m1 = m + 8, b1i = m1 >> 11, tok1 = m1 & 2047;
#pragma unroll
            for (int nt = 0; nt < 8; nt++) {
                int dcol = nt * 8 + t * 2;          // 0..63 within head
                int n = n0 + nw * 64 + dcol;
                float bv0 = bias[n], bv1 = bias[n + 1];
                float2 r0 = make_float2(rnd(acc[mt][nt][0] + bv0), rnd(acc[mt][nt][1] + bv1));
                float2 r1 = make_float2(rnd(acc[mt][nt][2] + bv0), rnd(acc[mt][nt][3] + bv1));
                *(float2*)(dst + ((size_t)(b0i * HH + hh) * TT + tok0) * DD + dcol) = r0;
                *(float2*)(dst + ((size_t)(b1i * HH + hh) * TT + tok1) * DD + dcol) = r1;
            }
        }
    } else {
#pragma unroll
        for (int mt = 0; mt < 2; mt++) {
            int m = m0 + mw * 32 + mt * 16 + g;
#pragma unroll
            for (int nt = 0; nt < 8; nt++) {
                int n = n0 + nw * 64 + nt * 8 + t * 2;
                float bv0 = bias[n], bv1 = bias[n + 1];
                float2 r0 = make_float2(acc[mt][nt][0] + bv0, acc[mt][nt][1] + bv1);
                float2 r1 = make_float2(acc[mt][nt][2] + bv0, acc[mt][nt][3] + bv1);
                *(float2*)(out + (size_t)m * CC + n) = r0;
                *(float2*)(out + (size_t)(m + 8) * CC + n) = r1;
            }
        }
    }
}

// ---------------------------------------------------------------------------
// tf32 MMA flash attention (R13-proven, unchanged): k-split warp pairs,
// single barrier per k-block, cp.async K/V, LPT scheduling.
// ---------------------------------------------------------------------------
#define AQ   0
#define AK0  4352
#define AV0  8704
#define AK1  13056
#define AV1  17408
#define APS  21760
#define APM  26112
#define ATTN_SMEM ((28160) * 4)

__global__ __launch_bounds__(256) void attn_mma_kernel(const int* __restrict__ amask)
{
    extern __shared__ unsigned smu[];
    unsigned* Qs = smu + AQ;
    unsigned* Ps = smu + APS;
    float*    pmall = (float*)(smu + APM);

    const int bh = blockIdx.x;
    const int b = bh / HH, h = bh % HH;
    const bool left = (h < NLEFT);
    const int qb = left ? (TT / 64 - 1 - blockIdx.y) : blockIdx.y;   // LPT

    const float* Qg = g_q + (size_t)bh * TT * DD;
    const float* Kg = g_k + (size_t)bh * TT * DD;
    const float* Vg = g_v + (size_t)bh * TT * DD;

    const int tid = threadIdx.x;
    const int lane = tid & 31, warp = tid >> 5;
    const int g = lane >> 2, t = lane & 3;
    const int qgrp = warp & 3, kh = warp >> 2;
    const int rm = qgrp * 16;
    const int kc0 = kh * 32;

    const int a_row = (lane & 7) + ((lane >> 3) & 1) * 8;
    const int a_ws  = (lane >> 4) * 4;
    const int b_row = (lane & 7) + ((lane >> 4) << 3);
    const int b_ws  = ((lane >> 3) & 1) * 4;

    const uint32_t smb = smem_u32(smu);
    const uint32_t qad  = smb + (uint32_t)(((rm + a_row) * 68 + a_ws + AQ)  << 2);
    const uint32_t padr = smb + (uint32_t)(((rm + a_row) * 68 + kc0 + a_ws + APS) << 2);
    uint32_t kad[2];
#pragma unroll
    for (int p = 0; p < 2; p++)
        kad[p] = smb + (uint32_t)((AK0 + (kc0 + p * 16 + b_row) * 68 + b_ws) << 2);

    const int lrow0 = tid >> 4;
    const int ld4   = (tid & 15) << 2;

    // Q load (scaled by 1/8, exact; inputs already tf32-rounded)
#pragma unroll
    for (int i = 0; i < 4; i++) {
        int row = lrow0 + i * 16;
        float4 v = *(const float4*)(Qg + (size_t)(qb * 64 + row) * DD + ld4);
        Qs[row * 68 + ld4 + 0] = f2tf32(v.x * 0.125f);
        Qs[row * 68 + ld4 + 1] = f2tf32(v.y * 0.125f);
        Qs[row * 68 + ld4 + 2] = f2tf32(v.z * 0.125f);
        Qs[row * 68 + ld4 + 3] = f2tf32(v.w * 0.125f);
    }
#pragma unroll
    for (int i = 0; i < 8; i++) {
        int idx = tid + i * 256;
        pmall[idx] = amask[b * TT + idx] ? 0.f : NEGF;
    }

    float m_r[2] = {NEGF, NEGF};
    float l_r[2] = {0.f, 0.f};
    float O[8][4];
#pragma unroll
    for (int nt = 0; nt < 8; nt++)
#pragma unroll
        for (int c = 0; c < 4; c++) O[nt][c] = 0.f;

    const int kb0 = left ? 0 : qb;
    const int kb1 = left ? qb : (TT / 64 - 1);
    const int qi0 = qb * 64 + rm + g, qi1 = qi0 + 8;
    const bool skipdiag = left ? (kh == 1 && rm < 32) : (kh == 0 && rm >= 32);

    {   // prologue: prefetch kb0 into buffer 0
        const float* Kp = Kg + (size_t)kb0 * 64 * DD;
        const float* Vp = Vg + (size_t)kb0 * 64 * DD;
        uint32_t kb_ = smb + AK0 * 4, vb_ = smb + AV0 * 4;
#pragma unroll
        for (int i = 0; i < 4; i++) {
            int row = lrow0 + i * 16;
            uint32_t off = (uint32_t)((row * 68 + ld4) << 2);
            cpa16(kb_ + off, Kp + row * DD + ld4);
            cpa16(vb_ + off, Vp + row * DD + ld4);
        }
        CPA_COMMIT();
    }

    for (int kb = kb0, it = 0; kb <= kb1; kb++, it++) {
        const int buf = it & 1;
        const uint32_t bufoff = (uint32_t)buf * ((AK1 - AK0) * 4);
        CPA_WAIT(0);
        __syncthreads();                 // kb visible; other buffer free
        if (kb + 1 <= kb1) {
            const float* Kp = Kg + (size_t)(kb + 1) * 64 * DD;
            const float* Vp = Vg + (size_t)(kb + 1) * 64 * DD;
            const uint32_t nbo = (uint32_t)(buf ^ 1) * ((AK1 - AK0) * 4);
            uint32_t kb_ = smb + AK0 * 4 + nbo, vb_ = smb + AV0 * 4 + nbo;
#pragma unroll
            for (int i = 0; i < 4; i++) {
                int row = lrow0 + i * 16;
                uint32_t off = (uint32_t)((row * 68 + ld4) << 2);
                cpa16(kb_ + off, Kp + row * DD + ld4);
                cpa16(vb_ + off, Vp + row * DD + ld4);
            }
            CPA_COMMIT();
        }

        const bool diag = (kb == qb);
        if (diag && skipdiag) continue;  // prefetch already issued; safe

        const unsigned* Vsb = smu + AV0 + buf * (AK1 - AK0);

        // S = Q @ K^T  (warp: 16 rows x its 32 cols)
        float S[4][4];
#pragma unroll
        for (int nt = 0; nt < 4; nt++)
#pragma unroll
            for (int c = 0; c < 4; c++) S[nt][c] = 0.f;

#pragma unroll
        for (int ks = 0; ks < 8; ks++) {
            const uint32_t ko = ks * 32;
            unsigned a0, a1, a2, a3;
            ldsm4(a0, a1, a2, a3, qad + ko);
#pragma unroll
            for (int p = 0; p < 2; p++) {
                unsigned k0, k1, k2, k3;
                ldsm4(k0, k1, k2, k3, kad[p] + bufoff + ko);
                mma8(S[2 * p],     a0, a1, a2, a3, k0, k1);
                mma8(S[2 * p + 1], a0, a1, a2, a3, k2, k3);
            }
        }

        // Mask + online softmax over this warp's 32 cols
        float mx0 = NEGF, mx1 = NEGF;
        const int kbase = kb * 64;
#pragma unroll
        for (int nt = 0; nt < 4; nt++) {
            int c0 = kc0 + nt * 8 + t * 2;
            float p0 = pmall[kbase + c0], p1 = pmall[kbase + c0 + 1];
            float s0 = S[nt][0] + p0, s1 = S[nt][1] + p1;
            float s2 = S[nt][2] + p0, s3 = S[nt][3] + p1;
            if (diag) {
                int k0i = kbase + c0, k1i = k0i + 1;
                if (left) {
                    if (k0i > qi0) s0 = NEGF;
                    if (k1i > qi0) s1 = NEGF;
                    if (k0i > qi1) s2 = NEGF;
                    if (k1i > qi1) s3 = NEGF;
                } else {
                    if (k0i < qi0) s0 = NEGF;
                    if (k1i < qi0) s1 = NEGF;
                    if (k0i < qi1) s2 = NEGF;
                    if (k1i < qi1) s3 = NEGF;
                }
            }
            S[nt][0] = s0; S[nt][1] = s1; S[nt][2] = s2; S[nt][3] = s3;
            mx0 = fmaxf(mx0, fmaxf(s0, s1));
            mx1 = fmaxf(mx1, fmaxf(s2, s3));
        }
        mx0 = fmaxf(mx0, __shfl_xor_sync(0xffffffffu, mx0, 1));
        mx0 = fmaxf(mx0, __shfl_xor_sync(0xffffffffu, mx0, 2));
        mx1 = fmaxf(mx1, __shfl_xor_sync(0xffffffffu, mx1, 1));
        mx1 = fmaxf(mx1, __shfl_xor_sync(0xffffffffu, mx1, 2));

        float mn0 = fmaxf(m_r[0], mx0), mn1 = fmaxf(m_r[1], mx1);
        float al0 = __expf(m_r[0] - mn0), al1 = __expf(m_r[1] - mn1);
        m_r[0] = mn0; m_r[1] = mn1;

        float rs0 = 0.f, rs1 = 0.f;
#pragma unroll
        for (int nt = 0; nt < 4; nt++) {
            float e0 = __expf(S[nt][0] - mn0), e1 = __expf(S[nt][1] - mn0);
            float e2 = __expf(S[nt][2] - mn1), e3 = __expf(S[nt][3] - mn1);
            S[nt][0] = e0; S[nt][1] = e1; S[nt][2] = e2; S[nt][3] = e3;
            rs0 += e0 + e1; rs1 += e2 + e3;
        }
        rs0 += __shfl_xor_sync(0xffffffffu, rs0, 1);
        rs0 += __shfl_xor_sync(0xffffffffu, rs0, 2);
        rs1 += __shfl_xor_sync(0xffffffffu, rs1, 1);
        rs1 += __shfl_xor_sync(0xffffffffu, rs1, 2);
        l_r[0] = l_r[0] * al0 + rs0;
        l_r[1] = l_r[1] * al1 + rs1;
#pragma unroll
        for (int nt = 0; nt < 8; nt++) {
            O[nt][0] *= al0; O[nt][1] *= al0;
            O[nt][2] *= al1; O[nt][3] *= al1;
        }

        // P -> smem (warp-private rows x warp-private cols)
        __syncwarp();
#pragma unroll
        for (int nt = 0; nt < 4; nt++) {
            int c0 = kc0 + nt * 8 + t * 2;
            Ps[(rm     + g) * 68 + c0    ] = f2tf32(S[nt][0]);
            Ps[(rm     + g) * 68 + c0 + 1] = f2tf32(S[nt][1]);
            Ps[(rm + 8 + g) * 68 + c0    ] = f2tf32(S[nt][2]);
            Ps[(rm + 8 + g) * 68 + c0 + 1] = f2tf32(S[nt][3]);
        }
        __syncwarp();

        // O += P(16 x its 32) @ V(its 32 x 64)
#pragma unroll
        for (int ks = 0; ks < 4; ks++) {
            const int kk = kc0 + ks * 8;
            unsigned a0, a1, a2, a3;
            ldsm4(a0, a1, a2, a3, padr + ks * 32);
#pragma unroll
            for (int nt = 0; nt < 8; nt++) {
                unsigned b0 = Vsb[(kk     + t) * 68 + nt * 8 + g];
                unsigned b1 = Vsb[(kk + 4 + t) * 68 + nt * 8 + g];
                mma8(O[nt], a0, a1, a2, a3, b0, b1);
            }
        }
    }

    // ----- Merge warp pair (kh=0 <- kh=1) and write ctx -----
    __syncthreads();                     // all compute done; Ps/pm dead
    float* sc = (float*)(smu + APS);     // scratch [4 warps][32 lanes][37]
    if (kh == 1) {
        int base = (qgrp * 32 + lane) * 37;
#pragma unroll
        for (int nt = 0; nt < 8; nt++) {
            sc[base + nt * 4 + 0] = O[nt][0];
            sc[base + nt * 4 + 1] = O[nt][1];
            sc[base + nt * 4 + 2] = O[nt][2];
            sc[base + nt * 4 + 3] = O[nt][3];
        }
        sc[base + 32] = m_r[0]; sc[base + 33] = m_r[1];
        sc[base + 34] = l_r[0]; sc[base + 35] = l_r[1];
    }
    __syncthreads();
    if (kh == 0) {
        int base = (qgrp * 32 + lane) * 37;
        float mb0 = sc[base + 32], mb1 = sc[base + 33];
        float lb0 = sc[base + 34], lb1 = sc[base + 35];
        float M0 = fmaxf(m_r[0], mb0), M1 = fmaxf(m_r[1], mb1);
        float sa0 = __expf(m_r[0] - M0), sb0 = __expf(mb0 - M0);
        float sa1 = __expf(m_r[1] - M1), sb1 = __expf(mb1 - M1);
        float L0 = l_r[0] * sa0 + lb0 * sb0;
        float L1 = l_r[1] * sa1 + lb1 * sb1;
        float inv0 = 1.0f / L0, inv1 = 1.0f / L1;
        int t0 = qb * 64 + rm + g, t1 = t0 + 8;
#pragma unroll
        for (int nt = 0; nt < 8; nt++) {
            float o0 = O[nt][0] * sa0 + sc[base + nt * 4 + 0] * sb0;
            float o1 = O[nt][1] * sa0 + sc[base + nt * 4 + 1] * sb0;
            float o2 = O[nt][2] * sa1 + sc[base + nt * 4 + 2] * sb1;
            float o3 = O[nt][3] * sa1 + sc[base + nt * 4 + 3] * sb1;
            int col = h * DD + nt * 8 + t * 2;
            *(float2*)(g_ctx + ((size_t)b * TT + t0) * CC + col) =
                make_float2(rnd(o0 * inv0), rnd(o1 * inv0));
            *(float2*)(g_ctx + ((size_t)b * TT + t1) * CC + col) =
                make_float2(rnd(o2 * inv1), rnd(o3 * inv1));
        }
    }
}

// ---------------------------------------------------------------------------
extern "C" void kernel_launch(void* const* d_in, const int* in_sizes, int n_in,
                              void* d_out, int out_size)
{
    const float* x      = (const float*)d_in[0];
    const int*   amask  = (const int*)  d_in[1];
    const float* Wqkv_w = (const float*)d_in[2];
    const float* Wqkv_b = (const float*)d_in[3];
    const float* Wo_w   = (const float*)d_in[4];
    const float* Wo_b   = (const float*)d_in[5];
    float* out = (float*)d_out;

    (void)in_sizes; (void)n_in; (void)out_size;

    cudaFuncSetAttribute(attn_mma_kernel,
                         cudaFuncAttributeMaxDynamicSharedMemorySize, ATTN_SMEM);
    cudaFuncSetAttribute(mma_gemm_kernel<0>,
                         cudaFuncAttributeMaxDynamicSharedMemorySize, GEMM_SMEM);
    cudaFuncSetAttribute(mma_gemm_kernel<1>,
                         cudaFuncAttributeMaxDynamicSharedMemorySize, GEMM_SMEM);

    preround_kernel<<<(PRN4 + 255) / 256, 256>>>(x, Wqkv_w, Wo_w);
    mma_gemm_kernel<0><<<dim3(N1 / 128, MM / 128), 256, GEMM_SMEM>>>(Wqkv_b, nullptr);
    attn_mma_kernel<<<dim3(BB * HH, TT / 64), 256, ATTN_SMEM>>>(amask);
    mma_gemm_kernel<1><<<dim3(CC / 128, MM / 128), 256, GEMM_SMEM>>>(Wo_b, out);
}

// round 15
// speedup vs baseline: 2.4141x; 1.0260x over previous
#include <cuda_runtime.h>
#include <cstdint>

#define BB 2
#define TT 2048
#define CC 768
#define HH 12
#define NLEFT 6
#define DD 64
#define MM (BB*TT)
#define N1 (3*CC)

#define NEGF (-3.402823466e38f)

// Scratch (device globals: allocation-free)
__device__ float g_q[BB*HH*TT*DD];
__device__ float g_k[BB*HH*TT*DD];
__device__ float g_v[BB*HH*TT*DD];
__device__ float g_ctx[BB*TT*CC];
// Pre-rounded (tf32) copies of GEMM inputs
__device__ float g_xr[MM*CC];
__device__ float g_w1r[N1*CC];
__device__ float g_w2r[CC*CC];

__device__ __forceinline__ unsigned f2tf32(float f) {
    unsigned r;
    asm("cvt.rna.tf32.f32 %0, %1;" : "=r"(r) : "f"(f));
    return r;
}
__device__ __forceinline__ float rnd(float f) { return __uint_as_float(f2tf32(f)); }

__device__ __forceinline__ uint32_t smem_u32(const void* p) {
    uint32_t a;
    asm("{ .reg .u64 t; cvta.to.shared.u64 t, %1; cvt.u32.u64 %0, t; }"
        : "=r"(a) : "l"(p));
    return a;
}
__device__ __forceinline__ void cpa16(uint32_t d, const void* s) {
    asm volatile("cp.async.cg.shared.global [%0], [%1], 16;" :: "r"(d), "l"(s));
}
#define CPA_COMMIT() asm volatile("cp.async.commit_group;" ::: "memory")
#define CPA_WAIT(n)  asm volatile("cp.async.wait_group %0;" :: "n"(n) : "memory")

__device__ __forceinline__ void ldsm4(unsigned& r0, unsigned& r1,
                                      unsigned& r2, unsigned& r3, uint32_t addr) {
    asm volatile("ldmatrix.sync.aligned.m8n8.x4.shared.b16 {%0,%1,%2,%3}, [%4];"
                 : "=r"(r0), "=r"(r1), "=r"(r2), "=r"(r3) : "r"(addr));
}
__device__ __forceinline__ void mma8(float* d,
    unsigned a0, unsigned a1, unsigned a2, unsigned a3,
    unsigned b0, unsigned b1)
{
    asm volatile(
        "mma.sync.aligned.m16n8k8.row.col.f32.tf32.tf32.f32 "
        "{%0,%1,%2,%3}, {%4,%5,%6,%7}, {%8,%9}, {%0,%1,%2,%3};"
        : "+f"(d[0]), "+f"(d[1]), "+f"(d[2]), "+f"(d[3])
        : "r"(a0), "r"(a1), "r"(a2), "r"(a3), "r"(b0), "r"(b1));
}

// ---------------------------------------------------------------------------
// Pre-round inputs to tf32 (idempotent wrt all downstream cvt.rna).
// ---------------------------------------------------------------------------
#define XN4  (MM*CC/4)
#define W1N4 (N1*CC/4)
#define W2N4 (CC*CC/4)
#define PRN4 (XN4 + W1N4 + W2N4)

__global__ __launch_bounds__(256) void preround_kernel(
    const float* __restrict__ x, const float* __restrict__ w1,
    const float* __restrict__ w2)
{
    int i = blockIdx.x * 256 + threadIdx.x;
    if (i >= PRN4) return;
    const float* src; float* dst; int j;
    if (i < XN4)              { src = x;  dst = g_xr;  j = i; }
    else if (i < XN4 + W1N4)  { src = w1; dst = g_w1r; j = i - XN4; }
    else                      { src = w2; dst = g_w2r; j = i - XN4 - W1N4; }
    float4 v = *(const float4*)(src + (size_t)j * 4);
    float4 o = make_float4(rnd(v.x), rnd(v.y), rnd(v.z), rnd(v.w));
    *(float4*)(dst + (size_t)j * 4) = o;
}

#define NCH (CC/32)

// ---------------------------------------------------------------------------
// QKV GEMM: 128x128 tile (R14-proven for this stage; grid 576 keeps chip fed).
// 256 thr = 8 warps (4M x 2N), warp tile 32x64.
// ---------------------------------------------------------------------------
#define GW_A   (128*36)
#define W_PR   (2*GW_A)
#define WIDE_SMEM (2 * W_PR * 4)      // 73728 B

__global__ __launch_bounds__(256) void qkv_gemm_kernel(const float* __restrict__ bias)
{
    extern __shared__ unsigned sm[];

    const float* Ag = (const float*)g_xr;
    const float* W  = (const float*)g_w1r;

    const int K = CC;
    const int tid  = threadIdx.x;
    const int lane = tid & 31, warp = tid >> 5;
    const int mw = warp >> 1, nw = warp & 1;
    const int m0 = blockIdx.y * 128, n0 = blockIdx.x * 128;
    const int g = lane >> 2, t = lane & 3;

    const uint32_t smb = smem_u32(sm);

    const int a_row = (lane & 7) + ((lane >> 3) & 1) * 8;
    const int a_ws  = (lane >> 4) * 4;
    const int b_row = (lane & 7) + ((lane >> 4) << 3);
    const int b_ws  = ((lane >> 3) & 1) * 4;

    const uint32_t aad0 = smb + (uint32_t)(((mw * 32 + a_row) * 36 + a_ws) << 2);
    const uint32_t aad1 = aad0 + 16 * 36 * 4;
    uint32_t bad[4];
#pragma unroll
    for (int p = 0; p < 4; p++)
        bad[p] = smb + (uint32_t)((GW_A + (nw * 64 + p * 16 + b_row) * 36 + b_ws) << 2);

    const int lrow = tid >> 3;
    const int lkq  = (tid & 7) << 2;

    float acc[2][8][4];
#pragma unroll
    for (int mt = 0; mt < 2; mt++)
#pragma unroll
        for (int nt = 0; nt < 8; nt++)
#pragma unroll
            for (int c = 0; c < 4; c++) acc[mt][nt][c] = 0.f;

    {
        uint32_t ab = smb, bb = smb + GW_A * 4;
#pragma unroll
        for (int i = 0; i < 4; i++) {
            int row = lrow + i * 32;
            cpa16(ab + (uint32_t)((row * 36 + lkq) << 2),
                  Ag + (size_t)(m0 + row) * K + lkq);
            cpa16(bb + (uint32_t)((row * 36 + lkq) << 2),
                  W + (size_t)(n0 + row) * K + lkq);
        }
        CPA_COMMIT();
    }

    for (int c = 0; c < NCH; c++) {
        const uint32_t bo = (uint32_t)(c & 1) * (W_PR * 4);
        CPA_WAIT(0);
        __syncthreads();
        if (c + 1 < NCH) {
            const int k0n = (c + 1) * 32;
            const uint32_t nbo = (uint32_t)((c + 1) & 1) * (W_PR * 4);
            uint32_t ab = smb + nbo, bb = smb + nbo + GW_A * 4;
#pragma unroll
            for (int i = 0; i < 4; i++) {
                int row = lrow + i * 32;
                cpa16(ab + (uint32_t)((row * 36 + lkq) << 2),
                      Ag + (size_t)(m0 + row) * K + k0n + lkq);
                cpa16(bb + (uint32_t)((row * 36 + lkq) << 2),
                      W + (size_t)(n0 + row) * K + k0n + lkq);
            }
            CPA_COMMIT();
        }

#pragma unroll
        for (int ks = 0; ks < 4; ks++) {
            const uint32_t ko = bo + ks * 32;
            unsigned a0[4], a1[4];
            ldsm4(a0[0], a0[1], a0[2], a0[3], aad0 + ko);
            ldsm4(a1[0], a1[1], a1[2], a1[3], aad1 + ko);
#pragma unroll
            for (int p = 0; p < 4; p++) {
                unsigned bf[4];
                ldsm4(bf[0], bf[1], bf[2], bf[3], bad[p] + ko);
                mma8(acc[0][2*p],   a0[0], a0[1], a0[2], a0[3], bf[0], bf[1]);
                mma8(acc[0][2*p+1], a0[0], a0[1], a0[2], a0[3], bf[2], bf[3]);
                mma8(acc[1][2*p],   a1[0], a1[1], a1[2], a1[3], bf[0], bf[1]);
                mma8(acc[1][2*p+1], a1[0], a1[1], a1[2], a1[3], bf[2], bf[3]);
            }
        }
    }

    const int s  = n0 / CC;
    const int hh = ((n0 % CC) >> 6) + nw;
    float* dst = (s == 0) ? g_q : ((s == 1) ? g_k : g_v);
#pragma unroll
    for (int mt = 0; mt < 2; mt++) {
        int m = m0 + mw * 32 + mt * 16 + g;
        int b0i = m >> 11, tok0 = m & 2047;
        int m1 = m + 8, b1i = m1 >> 11, tok1 = m1 & 2047;
#pragma unroll
        for (int nt = 0; nt < 8; nt++) {
            int dcol = nt * 8 + t * 2;
            int n = n0 + nw * 64 + dcol;
            float bv0 = bias[n], bv1 = bias[n + 1];
            float2 r0 = make_float2(rnd(acc[mt][nt][0] + bv0), rnd(acc[mt][nt][1] + bv1));
            float2 r1 = make_float2(rnd(acc[mt][nt][2] + bv0), rnd(acc[mt][nt][3] + bv1));
            *(float2*)(dst + ((size_t)(b0i * HH + hh) * TT + tok0) * DD + dcol) = r0;
            *(float2*)(dst + ((size_t)(b1i * HH + hh) * TT + tok1) * DD + dcol) = r1;
        }
    }
}

// ---------------------------------------------------------------------------
// Out-proj GEMM: 128x64 tile (R13-proven for this stage; grid 384, regs 62).
// 256 thr = 8 warps (4M x 2N), warp tile 32x32.
// ---------------------------------------------------------------------------
#define NW_A   (128*36)
#define NW_B   (64*36)
#define NW_PR  (NW_A + NW_B)
#define NARROW_SMEM (2 * NW_PR * 4)   // 55296 B

__global__ __launch_bounds__(256) void out_gemm_kernel(
    const float* __restrict__ bias, float* __restrict__ out)
{
    extern __shared__ unsigned sm[];

    const float* Ag = (const float*)g_ctx;
    const float* W  = (const float*)g_w2r;

    const int K = CC;
    const int tid  = threadIdx.x;
    const int lane = tid & 31, warp = tid >> 5;
    const int mw = warp >> 1, nw = warp & 1;
    const int m0 = blockIdx.y * 128, n0 = blockIdx.x * 64;
    const int g = lane >> 2, t = lane & 3;

    const uint32_t smb = smem_u32(sm);

    const int a_row = (lane & 7) + ((lane >> 3) & 1) * 8;
    const int a_ws  = (lane >> 4) * 4;
    const int b_row = (lane & 7) + ((lane >> 4) << 3);
    const int b_ws  = ((lane >> 3) & 1) * 4;

    const uint32_t aad0 = smb + (uint32_t)(((mw * 32 + a_row) * 36 + a_ws) << 2);
    const uint32_t aad1 = aad0 + 16 * 36 * 4;
    const uint32_t bad0 = smb + (uint32_t)((NW_A + (nw * 32 + b_row) * 36 + b_ws) << 2);
    const uint32_t bad1 = bad0 + 16 * 36 * 4;

    const int lrow = tid >> 3;
    const int lkq  = (tid & 7) << 2;

    float acc[2][4][4];
#pragma unroll
    for (int mt = 0; mt < 2; mt++)
#pragma unroll
        for (int nt = 0; nt < 4; nt++)
#pragma unroll
            for (int c = 0; c < 4; c++) acc[mt][nt][c] = 0.f;

    {
        uint32_t ab = smb, bb = smb + NW_A * 4;
#pragma unroll
        for (int i = 0; i < 4; i++) {
            int row = lrow + i * 32;
            cpa16(ab + (uint32_t)((row * 36 + lkq) << 2),
                  Ag + (size_t)(m0 + row) * K + lkq);
        }
#pragma unroll
        for (int i = 0; i < 2; i++) {
            int row = lrow + i * 32;
            cpa16(bb + (uint32_t)((row * 36 + lkq) << 2),
                  W + (size_t)(n0 + row) * K + lkq);
        }
        CPA_COMMIT();
    }

    for (int c = 0; c < NCH; c++) {
        const uint32_t bo = (uint32_t)(c & 1) * (NW_PR * 4);
        CPA_WAIT(0);
        __syncthreads();
        if (c + 1 < NCH) {
            const int k0n = (c + 1) * 32;
            const uint32_t nbo = (uint32_t)((c + 1) & 1) * (NW_PR * 4);
            uint32_t ab = smb + nbo, bb = smb + nbo + NW_A * 4;
#pragma unroll
            for (int i = 0; i < 4; i++) {
                int row = lrow + i * 32;
                cpa16(ab + (uint32_t)((row * 36 + lkq) << 2),
                      Ag + (size_t)(m0 + row) * K + k0n + lkq);
            }
#pragma unroll
            for (int i = 0; i < 2; i++) {
                int row = lrow + i * 32;
                cpa16(bb + (uint32_t)((row * 36 + lkq) << 2),
                      W + (size_t)(n0 + row) * K + k0n + lkq);
            }
            CPA_COMMIT();
        }

#pragma unroll
        for (int ks = 0; ks < 4; ks++) {
            const uint32_t ko = bo + ks * 32;
            unsigned a0[4], a1[4], bA[4], bBr[4];
            ldsm4(a0[0], a0[1], a0[2], a0[3], aad0 + ko);
            ldsm4(a1[0], a1[1], a1[2], a1[3], aad1 + ko);
            ldsm4(bA[0], bA[1], bA[2], bA[3], bad0 + ko);
            ldsm4(bBr[0], bBr[1], bBr[2], bBr[3], bad1 + ko);
            mma8(acc[0][0], a0[0], a0[1], a0[2], a0[3], bA[0], bA[1]);
            mma8(acc[0][1], a0[0], a0[1], a0[2], a0[3], bA[2], bA[3]);
            mma8(acc[0][2], a0[0], a0[1], a0[2], a0[3], bBr[0], bBr[1]);
            mma8(acc[0][3], a0[0], a0[1], a0[2], a0[3], bBr[2], bBr[3]);
            mma8(acc[1][0], a1[0], a1[1], a1[2], a1[3], bA[0], bA[1]);
            mma8(acc[1][1], a1[0], a1[1], a1[2], a1[3], bA[2], bA[3]);
            mma8(acc[1][2], a1[0], a1[1], a1[2], a1[3], bBr[0], bBr[1]);
            mma8(acc[1][3], a1[0], a1[1], a1[2], a1[3], bBr[2], bBr[3]);
        }
    }

#pragma unroll
    for (int mt = 0; mt < 2; mt++) {
        int m = m0 + mw * 32 + mt * 16 + g;
#pragma unroll
        for (int nt = 0; nt < 4; nt++) {
            int n = n0 + nw * 32 + nt * 8 + t * 2;
            float bv0 = bias[n], bv1 = bias[n + 1];
            float2 r0 = make_float2(acc[mt][nt][0] + bv0, acc[mt][nt][1] + bv1);
            float2 r1 = make_float2(acc[mt][nt][2] + bv0, acc[mt][nt][3] + bv1);
            *(float2*)(out + (size_t)m * CC + n) = r0;
            *(float2*)(out + (size_t)(m + 8) * CC + n) = r1;
        }
    }
}

// ---------------------------------------------------------------------------
// tf32 MMA flash attention (R13-proven, unchanged): k-split warp pairs,
// single barrier per k-block, cp.async K/V, LPT scheduling.
// ---------------------------------------------------------------------------
#define AQ   0
#define AK0  4352
#define AV0  8704
#define AK1  13056
#define AV1  17408
#define APS  21760
#define APM  26112
#define ATTN_SMEM ((28160) * 4)

__global__ __launch_bounds__(256) void attn_mma_kernel(const int* __restrict__ amask)
{
    extern __shared__ unsigned smu[];
    unsigned* Qs = smu + AQ;
    unsigned* Ps = smu + APS;
    float*    pmall = (float*)(smu + APM);

    const int bh = blockIdx.x;
    const int b = bh / HH, h = bh % HH;
    const bool left = (h < NLEFT);
    const int qb = left ? (TT / 64 - 1 - blockIdx.y) : blockIdx.y;   // LPT

    const float* Qg = g_q + (size_t)bh * TT * DD;
    const float* Kg = g_k + (size_t)bh * TT * DD;
    const float* Vg = g_v + (size_t)bh * TT * DD;

    const int tid = threadIdx.x;
    const int lane = tid & 31, warp = tid >> 5;
    const int g = lane >> 2, t = lane & 3;
    const int qgrp = warp & 3, kh = warp >> 2;
    const int rm = qgrp * 16;
    const int kc0 = kh * 32;

    const int a_row = (lane & 7) + ((lane >> 3) & 1) * 8;
    const int a_ws  = (lane >> 4) * 4;
    const int b_row = (lane & 7) + ((lane >> 4) << 3);
    const int b_ws  = ((lane >> 3) & 1) * 4;

    const uint32_t smb = smem_u32(smu);
    const uint32_t qad  = smb + (uint32_t)(((rm + a_row) * 68 + a_ws + AQ)  << 2);
    const uint32_t padr = smb + (uint32_t)(((rm + a_row) * 68 + kc0 + a_ws + APS) << 2);
    uint32_t kad[2];
#pragma unroll
    for (int p = 0; p < 2; p++)
        kad[p] = smb + (uint32_t)((AK0 + (kc0 + p * 16 + b_row) * 68 + b_ws) << 2);

    const int lrow0 = tid >> 4;
    const int ld4   = (tid & 15) << 2;

    // Q load (scaled by 1/8, exact; inputs already tf32-rounded)
#pragma unroll
    for (int i = 0; i < 4; i++) {
        int row = lrow0 + i * 16;
        float4 v = *(const float4*)(Qg + (size_t)(qb * 64 + row) * DD + ld4);
        Qs[row * 68 + ld4 + 0] = f2tf32(v.x * 0.125f);
        Qs[row * 68 + ld4 + 1] = f2tf32(v.y * 0.125f);
        Qs[row * 68 + ld4 + 2] = f2tf32(v.z * 0.125f);
        Qs[row * 68 + ld4 + 3] = f2tf32(v.w * 0.125f);
    }
#pragma unroll
    for (int i = 0; i < 8; i++) {
        int idx = tid + i * 256;
        pmall[idx] = amask[b * TT + idx] ? 0.f : NEGF;
    }

    float m_r[2] = {NEGF, NEGF};
    float l_r[2] = {0.f, 0.f};
    float O[8][4];
#pragma unroll
    for (int nt = 0; nt < 8; nt++)
#pragma unroll
        for (int c = 0; c < 4; c++) O[nt][c] = 0.f;

    const int kb0 = left ? 0 : qb;
    const int kb1 = left ? qb : (TT / 64 - 1);
    const int qi0 = qb * 64 + rm + g, qi1 = qi0 + 8;
    const bool skipdiag = left ? (kh == 1 && rm < 32) : (kh == 0 && rm >= 32);

    {   // prologue: prefetch kb0 into buffer 0
        const float* Kp = Kg + (size_t)kb0 * 64 * DD;
        const float* Vp = Vg + (size_t)kb0 * 64 * DD;
        uint32_t kb_ = smb + AK0 * 4, vb_ = smb + AV0 * 4;
#pragma unroll
        for (int i = 0; i < 4; i++) {
            int row = lrow0 + i * 16;
            uint32_t off = (uint32_t)((row * 68 + ld4) << 2);
            cpa16(kb_ + off, Kp + row * DD + ld4);
            cpa16(vb_ + off, Vp + row * DD + ld4);
        }
        CPA_COMMIT();
    }

    for (int kb = kb0, it = 0; kb <= kb1; kb++, it++) {
        const int buf = it & 1;
        const uint32_t bufoff = (uint32_t)buf * ((AK1 - AK0) * 4);
        CPA_WAIT(0);
        __syncthreads();                 // kb visible; other buffer free
        if (kb + 1 <= kb1) {
            const float* Kp = Kg + (size_t)(kb + 1) * 64 * DD;
            const float* Vp = Vg + (size_t)(kb + 1) * 64 * DD;
            const uint32_t nbo = (uint32_t)(buf ^ 1) * ((AK1 - AK0) * 4);
            uint32_t kb_ = smb + AK0 * 4 + nbo, vb_ = smb + AV0 * 4 + nbo;
#pragma unroll
            for (int i = 0; i < 4; i++) {
                int row = lrow0 + i * 16;
                uint32_t off = (uint32_t)((row * 68 + ld4) << 2);
                cpa16(kb_ + off, Kp + row * DD + ld4);
                cpa16(vb_ + off, Vp + row * DD + ld4);
            }
            CPA_COMMIT();
        }

        const bool diag = (kb == qb);
        if (diag && skipdiag) continue;  // prefetch already issued; safe

        const unsigned* Vsb = smu + AV0 + buf * (AK1 - AK0);

        // S = Q @ K^T  (warp: 16 rows x its 32 cols)
        float S[4][4];
#pragma unroll
        for (int nt = 0; nt < 4; nt++)
#pragma unroll
            for (int c = 0; c < 4; c++) S[nt][c] = 0.f;

#pragma unroll
        for (int ks = 0; ks < 8; ks++) {
            const uint32_t ko = ks * 32;
            unsigned a0, a1, a2, a3;
            ldsm4(a0, a1, a2, a3, qad + ko);
#pragma unroll
            for (int p = 0; p < 2; p++) {
                unsigned k0, k1, k2, k3;
                ldsm4(k0, k1, k2, k3, kad[p] + bufoff + ko);
                mma8(S[2 * p],     a0, a1, a2, a3, k0, k1);
                mma8(S[2 * p + 1], a0, a1, a2, a3, k2, k3);
            }
        }

        // Mask + online softmax over this warp's 32 cols
        float mx0 = NEGF, mx1 = NEGF;
        const int kbase = kb * 64;
#pragma unroll
        for (int nt = 0; nt < 4; nt++) {
            int c0 = kc0 + nt * 8 + t * 2;
            float p0 = pmall[kbase + c0], p1 = pmall[kbase + c0 + 1];
            float s0 = S[nt][0] + p0, s1 = S[nt][1] + p1;
            float s2 = S[nt][2] + p0, s3 = S[nt][3] + p1;
            if (diag) {
                int k0i = kbase + c0, k1i = k0i + 1;
                if (left) {
                    if (k0i > qi0) s0 = NEGF;
                    if (k1i > qi0) s1 = NEGF;
                    if (k0i > qi1) s2 = NEGF;
                    if (k1i > qi1) s3 = NEGF;
                } else {
                    if (k0i < qi0) s0 = NEGF;
                    if (k1i < qi0) s1 = NEGF;
                    if (k0i < qi1) s2 = NEGF;
                    if (k1i < qi1) s3 = NEGF;
                }
            }
            S[nt][0] = s0; S[nt][1] = s1; S[nt][2] = s2; S[nt][3] = s3;
            mx0 = fmaxf(mx0, fmaxf(s0, s1));
            mx1 = fmaxf(mx1, fmaxf(s2, s3));
        }
        mx0 = fmaxf(mx0, __shfl_xor_sync(0xffffffffu, mx0, 1));
        mx0 = fmaxf(mx0, __shfl_xor_sync(0xffffffffu, mx0, 2));
        mx1 = fmaxf(mx1, __shfl_xor_sync(0xffffffffu, mx1, 1));
        mx1 = fmaxf(mx1, __shfl_xor_sync(0xffffffffu, mx1, 2));

        float mn0 = fmaxf(m_r[0], mx0), mn1 = fmaxf(m_r[1], mx1);
        float al0 = __expf(m_r[0] - mn0), al1 = __expf(m_r[1] - mn1);
        m_r[0] = mn0; m_r[1] = mn1;

        float rs0 = 0.f, rs1 = 0.f;
#pragma unroll
        for (int nt = 0; nt < 4; nt++) {
            float e0 = __expf(S[nt][0] - mn0), e1 = __expf(S[nt][1] - mn0);
            float e2 = __expf(S[nt][2] - mn1), e3 = __expf(S[nt][3] - mn1);
            S[nt][0] = e0; S[nt][1] = e1; S[nt][2] = e2; S[nt][3] = e3;
            rs0 += e0 + e1; rs1 += e2 + e3;
        }
        rs0 += __shfl_xor_sync(0xffffffffu, rs0, 1);
        rs0 += __shfl_xor_sync(0xffffffffu, rs0, 2);
        rs1 += __shfl_xor_sync(0xffffffffu, rs1, 1);
        rs1 += __shfl_xor_sync(0xffffffffu, rs1, 2);
        l_r[0] = l_r[0] * al0 + rs0;
        l_r[1] = l_r[1] * al1 + rs1;
#pragma unroll
        for (int nt = 0; nt < 8; nt++) {
            O[nt][0] *= al0; O[nt][1] *= al0;
            O[nt][2] *= al1; O[nt][3] *= al1;
        }

        // P -> smem (warp-private rows x warp-private cols)
        __syncwarp();
#pragma unroll
        for (int nt = 0; nt < 4; nt++) {
            int c0 = kc0 + nt * 8 + t * 2;
            Ps[(rm     + g) * 68 + c0    ] = f2tf32(S[nt][0]);
            Ps[(rm     + g) * 68 + c0 + 1] = f2tf32(S[nt][1]);
            Ps[(rm + 8 + g) * 68 + c0    ] = f2tf32(S[nt][2]);
            Ps[(rm + 8 + g) * 68 + c0 + 1] = f2tf32(S[nt][3]);
        }
        __syncwarp();

        // O += P(16 x its 32) @ V(its 32 x 64)
#pragma unroll
        for (int ks = 0; ks < 4; ks++) {
            const int kk = kc0 + ks * 8;
            unsigned a0, a1, a2, a3;
            ldsm4(a0, a1, a2, a3, padr + ks * 32);
#pragma unroll
            for (int nt = 0; nt < 8; nt++) {
                unsigned b0 = Vsb[(kk     + t) * 68 + nt * 8 + g];
                unsigned b1 = Vsb[(kk + 4 + t) * 68 + nt * 8 + g];
                mma8(O[nt], a0, a1, a2, a3, b0, b1);
            }
        }
    }

    // ----- Merge warp pair (kh=0 <- kh=1) and write ctx -----
    __syncthreads();                     // all compute done; Ps/pm dead
    float* sc = (float*)(smu + APS);     // scratch [4 warps][32 lanes][37]
    if (kh == 1) {
        int base = (qgrp * 32 + lane) * 37;
#pragma unroll
        for (int nt = 0; nt < 8; nt++) {
            sc[base + nt * 4 + 0] = O[nt][0];
            sc[base + nt * 4 + 1] = O[nt][1];
            sc[base + nt * 4 + 2] = O[nt][2];
            sc[base + nt * 4 + 3] = O[nt][3];
        }
        sc[base + 32] = m_r[0]; sc[base + 33] = m_r[1];
        sc[base + 34] = l_r[0]; sc[base + 35] = l_r[1];
    }
    __syncthreads();
    if (kh == 0) {
        int base = (qgrp * 32 + lane) * 37;
        float mb0 = sc[base + 32], mb1 = sc[base + 33];
        float lb0 = sc[base + 34], lb1 = sc[base + 35];
        float M0 = fmaxf(m_r[0], mb0), M1 = fmaxf(m_r[1], mb1);
        float sa0 = __expf(m_r[0] - M0), sb0 = __expf(mb0 - M0);
        float sa1 = __expf(m_r[1] - M1), sb1 = __expf(mb1 - M1);
        float L0 = l_r[0] * sa0 + lb0 * sb0;
        float L1 = l_r[1] * sa1 + lb1 * sb1;
        float inv0 = 1.0f / L0, inv1 = 1.0f / L1;
        int t0 = qb * 64 + rm + g, t1 = t0 + 8;
#pragma unroll
        for (int nt = 0; nt < 8; nt++) {
            float o0 = O[nt][0] * sa0 + sc[base + nt * 4 + 0] * sb0;
            float o1 = O[nt][1] * sa0 + sc[base + nt * 4 + 1] * sb0;
            float o2 = O[nt][2] * sa1 + sc[base + nt * 4 + 2] * sb1;
            float o3 = O[nt][3] * sa1 + sc[base + nt * 4 + 3] * sb1;
            int col = h * DD + nt * 8 + t * 2;
            *(float2*)(g_ctx + ((size_t)b * TT + t0) * CC + col) =
                make_float2(rnd(o0 * inv0), rnd(o1 * inv0));
            *(float2*)(g_ctx + ((size_t)b * TT + t1) * CC + col) =
                make_float2(rnd(o2 * inv1), rnd(o3 * inv1));
        }
    }
}

// ---------------------------------------------------------------------------
extern "C" void kernel_launch(void* const* d_in, const int* in_sizes, int n_in,
                              void* d_out, int out_size)
{
    const float* x      = (const float*)d_in[0];
    const int*   amask  = (const int*)  d_in[1];
    const float* Wqkv_w = (const float*)d_in[2];
    const float* Wqkv_b = (const float*)d_in[3];
    const float* Wo_w   = (const float*)d_in[4];
    const float* Wo_b   = (const float*)d_in[5];
    float* out = (float*)d_out;

    (void)in_sizes; (void)n_in; (void)out_size;

    cudaFuncSetAttribute(attn_mma_kernel,
                         cudaFuncAttributeMaxDynamicSharedMemorySize, ATTN_SMEM);
    cudaFuncSetAttribute(qkv_gemm_kernel,
                         cudaFuncAttributeMaxDynamicSharedMemorySize, WIDE_SMEM);
    cudaFuncSetAttribute(out_gemm_kernel,
                         cudaFuncAttributeMaxDynamicSharedMemorySize, NARROW_SMEM);

    preround_kernel<<<(PRN4 + 255) / 256, 256>>>(x, Wqkv_w, Wo_w);
    qkv_gemm_kernel<<<dim3(N1 / 128, MM / 128), 256, WIDE_SMEM>>>(Wqkv_b);
    attn_mma_kernel<<<dim3(BB * HH, TT / 64), 256, ATTN_SMEM>>>(amask);
    out_gemm_kernel<<<dim3(CC / 64, MM / 128), 256, NARROW_SMEM>>>(Wo_b, out);
}

// round 16
// speedup vs baseline: 2.7450x; 1.1371x over previous
#include <cuda_runtime.h>
#include <cstdint>

#define BB 2
#define TT 2048
#define CC 768
#define HH 12
#define NLEFT 6
#define DD 64
#define MM (BB*TT)
#define N1 (3*CC)

#define NEGF (-3.402823466e38f)

// Scratch (device globals: allocation-free)
__device__ float g_q[BB*HH*TT*DD];
__device__ float g_k[BB*HH*TT*DD];
__device__ float g_v[BB*HH*DD*TT];   // TRANSPOSED: [B,H,D,T]
__device__ float g_ctx[BB*TT*CC];
// Pre-rounded (tf32) copies of GEMM inputs
__device__ float g_xr[MM*CC];
__device__ float g_w1r[N1*CC];
__device__ float g_w2r[CC*CC];

__device__ __forceinline__ unsigned f2tf32(float f) {
    unsigned r;
    asm("cvt.rna.tf32.f32 %0, %1;" : "=r"(r) : "f"(f));
    return r;
}
__device__ __forceinline__ float rnd(float f) { return __uint_as_float(f2tf32(f)); }

__device__ __forceinline__ uint32_t smem_u32(const void* p) {
    uint32_t a;
    asm("{ .reg .u64 t; cvta.to.shared.u64 t, %1; cvt.u32.u64 %0, t; }"
        : "=r"(a) : "l"(p));
    return a;
}
__device__ __forceinline__ void cpa16(uint32_t d, const void* s) {
    asm volatile("cp.async.cg.shared.global [%0], [%1], 16;" :: "r"(d), "l"(s));
}
#define CPA_COMMIT() asm volatile("cp.async.commit_group;" ::: "memory")
#define CPA_WAIT(n)  asm volatile("cp.async.wait_group %0;" :: "n"(n) : "memory")

__device__ __forceinline__ void ldsm4(unsigned& r0, unsigned& r1,
                                      unsigned& r2, unsigned& r3, uint32_t addr) {
    asm volatile("ldmatrix.sync.aligned.m8n8.x4.shared.b16 {%0,%1,%2,%3}, [%4];"
                 : "=r"(r0), "=r"(r1), "=r"(r2), "=r"(r3) : "r"(addr));
}
__device__ __forceinline__ void mma8(float* d,
    unsigned a0, unsigned a1, unsigned a2, unsigned a3,
    unsigned b0, unsigned b1)
{
    asm volatile(
        "mma.sync.aligned.m16n8k8.row.col.f32.tf32.tf32.f32 "
        "{%0,%1,%2,%3}, {%4,%5,%6,%7}, {%8,%9}, {%0,%1,%2,%3};"
        : "+f"(d[0]), "+f"(d[1]), "+f"(d[2]), "+f"(d[3])
        : "r"(a0), "r"(a1), "r"(a2), "r"(a3), "r"(b0), "r"(b1));
}

// ---------------------------------------------------------------------------
// Pre-round inputs to tf32 (idempotent wrt all downstream cvt.rna).
// ---------------------------------------------------------------------------
#define XN4  (MM*CC/4)
#define W1N4 (N1*CC/4)
#define W2N4 (CC*CC/4)
#define PRN4 (XN4 + W1N4 + W2N4)

__global__ __launch_bounds__(256) void preround_kernel(
    const float* __restrict__ x, const float* __restrict__ w1,
    const float* __restrict__ w2)
{
    int i = blockIdx.x * 256 + threadIdx.x;
    if (i >= PRN4) return;
    const float* src; float* dst; int j;
    if (i < XN4)              { src = x;  dst = g_xr;  j = i; }
    else if (i < XN4 + W1N4)  { src = w1; dst = g_w1r; j = i - XN4; }
    else                      { src = w2; dst = g_w2r; j = i - XN4 - W1N4; }
    float4 v = *(const float4*)(src + (size_t)j * 4);
    float4 o = make_float4(rnd(v.x), rnd(v.y), rnd(v.z), rnd(v.w));
    *(float4*)(dst + (size_t)j * 4) = o;
}

#define NCH (CC/32)

// ---------------------------------------------------------------------------
// QKV GEMM: 128x128 tile (R14/R15-proven). V written TRANSPOSED [B,H,D,T].
// ---------------------------------------------------------------------------
#define GW_A   (128*36)
#define W_PR   (2*GW_A)
#define WIDE_SMEM (2 * W_PR * 4)      // 73728 B

__global__ __launch_bounds__(256) void qkv_gemm_kernel(const float* __restrict__ bias)
{
    extern __shared__ unsigned sm[];

    const float* Ag = (const float*)g_xr;
    const float* W  = (const float*)g_w1r;

    const int K = CC;
    const int tid  = threadIdx.x;
    const int lane = tid & 31, warp = tid >> 5;
    const int mw = warp >> 1, nw = warp & 1;
    const int m0 = blockIdx.y * 128, n0 = blockIdx.x * 128;
    const int g = lane >> 2, t = lane & 3;

    const uint32_t smb = smem_u32(sm);

    const int a_row = (lane & 7) + ((lane >> 3) & 1) * 8;
    const int a_ws  = (lane >> 4) * 4;
    const int b_row = (lane & 7) + ((lane >> 4) << 3);
    const int b_ws  = ((lane >> 3) & 1) * 4;

    const uint32_t aad0 = smb + (uint32_t)(((mw * 32 + a_row) * 36 + a_ws) << 2);
    const uint32_t aad1 = aad0 + 16 * 36 * 4;
    uint32_t bad[4];
#pragma unroll
    for (int p = 0; p < 4; p++)
        bad[p] = smb + (uint32_t)((GW_A + (nw * 64 + p * 16 + b_row) * 36 + b_ws) << 2);

    const int lrow = tid >> 3;
    const int lkq  = (tid & 7) << 2;

    float acc[2][8][4];
#pragma unroll
    for (int mt = 0; mt < 2; mt++)
#pragma unroll
        for (int nt = 0; nt < 8; nt++)
#pragma unroll
            for (int c = 0; c < 4; c++) acc[mt][nt][c] = 0.f;

    {
        uint32_t ab = smb, bb = smb + GW_A * 4;
#pragma unroll
        for (int i = 0; i < 4; i++) {
            int row = lrow + i * 32;
            cpa16(ab + (uint32_t)((row * 36 + lkq) << 2),
                  Ag + (size_t)(m0 + row) * K + lkq);
            cpa16(bb + (uint32_t)((row * 36 + lkq) << 2),
                  W + (size_t)(n0 + row) * K + lkq);
        }
        CPA_COMMIT();
    }

    for (int c = 0; c < NCH; c++) {
        const uint32_t bo = (uint32_t)(c & 1) * (W_PR * 4);
        CPA_WAIT(0);
        __syncthreads();
        if (c + 1 < NCH) {
            const int k0n = (c + 1) * 32;
            const uint32_t nbo = (uint32_t)((c + 1) & 1) * (W_PR * 4);
            uint32_t ab = smb + nbo, bb = smb + nbo + GW_A * 4;
#pragma unroll
            for (int i = 0; i < 4; i++) {
                int row = lrow + i * 32;
                cpa16(ab + (uint32_t)((row * 36 + lkq) << 2),
                      Ag + (size_t)(m0 + row) * K + k0n + lkq);
                cpa16(bb + (uint32_t)((row * 36 + lkq) << 2),
                      W + (size_t)(n0 + row) * K + k0n + lkq);
            }
            CPA_COMMIT();
        }

#pragma unroll
        for (int ks = 0; ks < 4; ks++) {
            const uint32_t ko = bo + ks * 32;
            unsigned a0[4], a1[4];
            ldsm4(a0[0], a0[1], a0[2], a0[3], aad0 + ko);
            ldsm4(a1[0], a1[1], a1[2], a1[3], aad1 + ko);
#pragma unroll
            for (int p = 0; p < 4; p++) {
                unsigned bf[4];
                ldsm4(bf[0], bf[1], bf[2], bf[3], bad[p] + ko);
                mma8(acc[0][2*p],   a0[0], a0[1], a0[2], a0[3], bf[0], bf[1]);
                mma8(acc[0][2*p+1], a0[0], a0[1], a0[2], a0[3], bf[2], bf[3]);
                mma8(acc[1][2*p],   a1[0], a1[1], a1[2], a1[3], bf[0], bf[1]);
                mma8(acc[1][2*p+1], a1[0], a1[1], a1[2], a1[3], bf[2], bf[3]);
            }
        }
    }

    const int s  = n0 / CC;
    const int hh = ((n0 % CC) >> 6) + nw;
    if (s == 2) {
        // V: transposed store g_v[(b*HH+hh)*DD + dcol][tok]
#pragma unroll
        for (int mt = 0; mt < 2; mt++) {
            int m = m0 + mw * 32 + mt * 16 + g;
            int b0i = m >> 11, tok0 = m & 2047;
            int m1 = m + 8, b1i = m1 >> 11, tok1 = m1 & 2047;
#pragma unroll
            for (int nt = 0; nt < 8; nt++) {
                int dcol = nt * 8 + t * 2;
                int n = n0 + nw * 64 + dcol;
                float bv0 = bias[n], bv1 = bias[n + 1];
                float v00 = rnd(acc[mt][nt][0] + bv0), v01 = rnd(acc[mt][nt][1] + bv1);
                float v10 = rnd(acc[mt][nt][2] + bv0), v11 = rnd(acc[mt][nt][3] + bv1);
                size_t base0 = ((size_t)(b0i * HH + hh) * DD + dcol) * TT;
                size_t base1 = ((size_t)(b1i * HH + hh) * DD + dcol) * TT;
                g_v[base0 + tok0] = v00;  g_v[base0 + TT + tok0] = v01;
                g_v[base1 + tok1] = v10;  g_v[base1 + TT + tok1] = v11;
            }
        }
    } else {
        float* dst = (s == 0) ? g_q : g_k;
#pragma unroll
        for (int mt = 0; mt < 2; mt++) {
            int m = m0 + mw * 32 + mt * 16 + g;
            int b0i = m >> 11, tok0 = m & 2047;
            int m1 = m + 8, b1i = m1 >> 11, tok1 = m1 & 2047;
#pragma unroll
            for (int nt = 0; nt < 8; nt++) {
                int dcol = nt * 8 + t * 2;
                int n = n0 + nw * 64 + dcol;
                float bv0 = bias[n], bv1 = bias[n + 1];
                float2 r0 = make_float2(rnd(acc[mt][nt][0] + bv0), rnd(acc[mt][nt][1] + bv1));
                float2 r1 = make_float2(rnd(acc[mt][nt][2] + bv0), rnd(acc[mt][nt][3] + bv1));
                *(float2*)(dst + ((size_t)(b0i * HH + hh) * TT + tok0) * DD + dcol) = r0;
                *(float2*)(dst + ((size_t)(b1i * HH + hh) * TT + tok1) * DD + dcol) = r1;
            }
        }
    }
}

// ---------------------------------------------------------------------------
// Out-proj GEMM: 128x64 tile (R13/R15-proven, unchanged).
// ---------------------------------------------------------------------------
#define NW_A   (128*36)
#define NW_B   (64*36)
#define NW_PR  (NW_A + NW_B)
#define NARROW_SMEM (2 * NW_PR * 4)   // 55296 B

__global__ __launch_bounds__(256) void out_gemm_kernel(
    const float* __restrict__ bias, float* __restrict__ out)
{
    extern __shared__ unsigned sm[];

    const float* Ag = (const float*)g_ctx;
    const float* W  = (const float*)g_w2r;

    const int K = CC;
    const int tid  = threadIdx.x;
    const int lane = tid & 31, warp = tid >> 5;
    const int mw = warp >> 1, nw = warp & 1;
    const int m0 = blockIdx.y * 128, n0 = blockIdx.x * 64;
    const int g = lane >> 2, t = lane & 3;

    const uint32_t smb = smem_u32(sm);

    const int a_row = (lane & 7) + ((lane >> 3) & 1) * 8;
    const int a_ws  = (lane >> 4) * 4;
    const int b_row = (lane & 7) + ((lane >> 4) << 3);
    const int b_ws  = ((lane >> 3) & 1) * 4;

    const uint32_t aad0 = smb + (uint32_t)(((mw * 32 + a_row) * 36 + a_ws) << 2);
    const uint32_t aad1 = aad0 + 16 * 36 * 4;
    const uint32_t bad0 = smb + (uint32_t)((NW_A + (nw * 32 + b_row) * 36 + b_ws) << 2);
    const uint32_t bad1 = bad0 + 16 * 36 * 4;

    const int lrow = tid >> 3;
    const int lkq  = (tid & 7) << 2;

    float acc[2][4][4];
#pragma unroll
    for (int mt = 0; mt < 2; mt++)
#pragma unroll
        for (int nt = 0; nt < 4; nt++)
#pragma unroll
            for (int c = 0; c < 4; c++) acc[mt][nt][c] = 0.f;

    {
        uint32_t ab = smb, bb = smb + NW_A * 4;
#pragma unroll
        for (int i = 0; i < 4; i++) {
            int row = lrow + i * 32;
            cpa16(ab + (uint32_t)((row * 36 + lkq) << 2),
                  Ag + (size_t)(m0 + row) * K + lkq);
        }
#pragma unroll
        for (int i = 0; i < 2; i++) {
            int row = lrow + i * 32;
            cpa16(bb + (uint32_t)((row * 36 + lkq) << 2),
                  W + (size_t)(n0 + row) * K + lkq);
        }
        CPA_COMMIT();
    }

    for (int c = 0; c < NCH; c++) {
        const uint32_t bo = (uint32_t)(c & 1) * (NW_PR * 4);
        CPA_WAIT(0);
        __syncthreads();
        if (c + 1 < NCH) {
            const int k0n = (c + 1) * 32;
            const uint32_t nbo = (uint32_t)((c + 1) & 1) * (NW_PR * 4);
            uint32_t ab = smb + nbo, bb = smb + nbo + NW_A * 4;
#pragma unroll
            for (int i = 0; i < 4; i++) {
                int row = lrow + i * 32;
                cpa16(ab + (uint32_t)((row * 36 + lkq) << 2),
                      Ag + (size_t)(m0 + row) * K + k0n + lkq);
            }
#pragma unroll
            for (int i = 0; i < 2; i++) {
                int row = lrow + i * 32;
                cpa16(bb + (uint32_t)((row * 36 + lkq) << 2),
                      W + (size_t)(n0 + row) * K + k0n + lkq);
            }
            CPA_COMMIT();
        }

#pragma unroll
        for (int ks = 0; ks < 4; ks++) {
            const uint32_t ko = bo + ks * 32;
            unsigned a0[4], a1[4], bA[4], bBr[4];
            ldsm4(a0[0], a0[1], a0[2], a0[3], aad0 + ko);
            ldsm4(a1[0], a1[1], a1[2], a1[3], aad1 + ko);
            ldsm4(bA[0], bA[1], bA[2], bA[3], bad0 + ko);
            ldsm4(bBr[0], bBr[1], bBr[2], bBr[3], bad1 + ko);
            mma8(acc[0][0], a0[0], a0[1], a0[2], a0[3], bA[0], bA[1]);
            mma8(acc[0][1], a0[0], a0[1], a0[2], a0[3], bA[2], bA[3]);
            mma8(acc[0][2], a0[0], a0[1], a0[2], a0[3], bBr[0], bBr[1]);
            mma8(acc[0][3], a0[0], a0[1], a0[2], a0[3], bBr[2], bBr[3]);
            mma8(acc[1][0], a1[0], a1[1], a1[2], a1[3], bA[0], bA[1]);
            mma8(acc[1][1], a1[0], a1[1], a1[2], a1[3], bA[2], bA[3]);
            mma8(acc[1][2], a1[0], a1[1], a1[2], a1[3], bBr[0], bBr[1]);
            mma8(acc[1][3], a1[0], a1[1], a1[2], a1[3], bBr[2], bBr[3]);
        }
    }

#pragma unroll
    for (int mt = 0; mt < 2; mt++) {
        int m = m0 + mw * 32 + mt * 16 + g;
#pragma unroll
        for (int nt = 0; nt < 4; nt++) {
            int n = n0 + nw * 32 + nt * 8 + t * 2;
            float bv0 = bias[n], bv1 = bias[n + 1];
            float2 r0 = make_float2(acc[mt][nt][0] + bv0, acc[mt][nt][1] + bv1);
            float2 r1 = make_float2(acc[mt][nt][2] + bv0, acc[mt][nt][3] + bv1);
            *(float2*)(out + (size_t)m * CC + n) = r0;
            *(float2*)(out + (size_t)(m + 8) * CC + n) = r1;
        }
    }
}

// ---------------------------------------------------------------------------
// tf32 MMA flash attention: k-split warp pairs, single barrier per k-block,
// cp.async K/V. NEW: V transposed [D][T] -> PV b-frags via ldmatrix;
// Q fragments hoisted into 32 persistent registers.
// ---------------------------------------------------------------------------
#define AQ   0
#define AK0  4352
#define AV0  8704
#define AK1  13056
#define AV1  17408
#define APS  21760
#define APM  26112
#define ATTN_SMEM ((28160) * 4)

__global__ __launch_bounds__(256) void attn_mma_kernel(const int* __restrict__ amask)
{
    extern __shared__ unsigned smu[];
    unsigned* Qs = smu + AQ;
    unsigned* Ps = smu + APS;
    float*    pmall = (float*)(smu + APM);

    const int bh = blockIdx.x;
    const int b = bh / HH, h = bh % HH;
    const bool left = (h < NLEFT);
    const int qb = left ? (TT / 64 - 1 - blockIdx.y) : blockIdx.y;   // LPT

    const float* Qg = g_q + (size_t)bh * TT * DD;
    const float* Kg = g_k + (size_t)bh * TT * DD;
    const float* Vg = g_v + (size_t)bh * DD * TT;     // [D][T]

    const int tid = threadIdx.x;
    const int lane = tid & 31, warp = tid >> 5;
    const int g = lane >> 2, t = lane & 3;
    const int qgrp = warp & 3, kh = warp >> 2;
    const int rm = qgrp * 16;
    const int kc0 = kh * 32;

    const int a_row = (lane & 7) + ((lane >> 3) & 1) * 8;
    const int a_ws  = (lane >> 4) * 4;
    const int b_row = (lane & 7) + ((lane >> 4) << 3);
    const int b_ws  = ((lane >> 3) & 1) * 4;

    const uint32_t smb = smem_u32(smu);
    const uint32_t qad  = smb + (uint32_t)(((rm + a_row) * 68 + a_ws + AQ)  << 2);
    const uint32_t padr = smb + (uint32_t)(((rm + a_row) * 68 + kc0 + a_ws + APS) << 2);
    uint32_t kad[2];
#pragma unroll
    for (int p = 0; p < 2; p++)
        kad[p] = smb + (uint32_t)((AK0 + (kc0 + p * 16 + b_row) * 68 + b_ws) << 2);
    uint32_t vad[4];                                   // Vt rows = dcol groups
#pragma unroll
    for (int p = 0; p < 4; p++)
        vad[p] = smb + (uint32_t)((AV0 + (p * 16 + b_row) * 68 + kc0 + b_ws) << 2);

    const int lrow0 = tid >> 4;
    const int ld4   = (tid & 15) << 2;

    // Q load (scaled by 1/8, exact; inputs already tf32-rounded)
#pragma unroll
    for (int i = 0; i < 4; i++) {
        int row = lrow0 + i * 16;
        float4 v = *(const float4*)(Qg + (size_t)(qb * 64 + row) * DD + ld4);
        Qs[row * 68 + ld4 + 0] = f2tf32(v.x * 0.125f);
        Qs[row * 68 + ld4 + 1] = f2tf32(v.y * 0.125f);
        Qs[row * 68 + ld4 + 2] = f2tf32(v.z * 0.125f);
        Qs[row * 68 + ld4 + 3] = f2tf32(v.w * 0.125f);
    }
#pragma unroll
    for (int i = 0; i < 8; i++) {
        int idx = tid + i * 256;
        pmall[idx] = amask[b * TT + idx] ? 0.f : NEGF;
    }

    const int kb0 = left ? 0 : qb;
    const int kb1 = left ? qb : (TT / 64 - 1);
    const int qi0 = qb * 64 + rm + g, qi1 = qi0 + 8;
    const bool skipdiag = left ? (kh == 1 && rm < 32) : (kh == 0 && rm >= 32);

    {   // prologue: prefetch kb0 into buffer 0 (K rows = kseq; Vt rows = d)
        const float* Kp = Kg + (size_t)kb0 * 64 * DD;
        uint32_t kb_ = smb + AK0 * 4, vb_ = smb + AV0 * 4;
#pragma unroll
        for (int i = 0; i < 4; i++) {
            int row = lrow0 + i * 16;
            uint32_t off = (uint32_t)((row * 68 + ld4) << 2);
            cpa16(kb_ + off, Kp + row * DD + ld4);
            cpa16(vb_ + off, Vg + (size_t)row * TT + kb0 * 64 + ld4);
        }
        CPA_COMMIT();
    }

    __syncthreads();                     // Q tile complete
    unsigned qa[8][4];                   // persistent Q fragments
#pragma unroll
    for (int ks = 0; ks < 8; ks++)
        ldsm4(qa[ks][0], qa[ks][1], qa[ks][2], qa[ks][3], qad + ks * 32);

    float m_r[2] = {NEGF, NEGF};
    float l_r[2] = {0.f, 0.f};
    float O[8][4];
#pragma unroll
    for (int nt = 0; nt < 8; nt++)
#pragma unroll
        for (int c = 0; c < 4; c++) O[nt][c] = 0.f;

    for (int kb = kb0, it = 0; kb <= kb1; kb++, it++) {
        const int buf = it & 1;
        const uint32_t bufoff = (uint32_t)buf * ((AK1 - AK0) * 4);
        CPA_WAIT(0);
        __syncthreads();                 // kb visible; other buffer free
        if (kb + 1 <= kb1) {
            const float* Kp = Kg + (size_t)(kb + 1) * 64 * DD;
            const uint32_t nbo = (uint32_t)(buf ^ 1) * ((AK1 - AK0) * 4);
            uint32_t kb_ = smb + AK0 * 4 + nbo, vb_ = smb + AV0 * 4 + nbo;
#pragma unroll
            for (int i = 0; i < 4; i++) {
                int row = lrow0 + i * 16;
                uint32_t off = (uint32_t)((row * 68 + ld4) << 2);
                cpa16(kb_ + off, Kp + row * DD + ld4);
                cpa16(vb_ + off, Vg + (size_t)row * TT + (kb + 1) * 64 + ld4);
            }
            CPA_COMMIT();
        }

        const bool diag = (kb == qb);
        if (diag && skipdiag) continue;  // prefetch already issued; safe

        // S = Q @ K^T  (warp: 16 rows x its 32 cols); Q frags from registers
        float S[4][4];
#pragma unroll
        for (int nt = 0; nt < 4; nt++)
#pragma unroll
            for (int c = 0; c < 4; c++) S[nt][c] = 0.f;

#pragma unroll
        for (int ks = 0; ks < 8; ks++) {
            const uint32_t ko = ks * 32;
#pragma unroll
            for (int p = 0; p < 2; p++) {
                unsigned k0, k1, k2, k3;
                ldsm4(k0, k1, k2, k3, kad[p] + bufoff + ko);
                mma8(S[2 * p],     qa[ks][0], qa[ks][1], qa[ks][2], qa[ks][3], k0, k1);
                mma8(S[2 * p + 1], qa[ks][0], qa[ks][1], qa[ks][2], qa[ks][3], k2, k3);
            }
        }

        // Mask + online softmax over this warp's 32 cols
        float mx0 = NEGF, mx1 = NEGF;
        const int kbase = kb * 64;
#pragma unroll
        for (int nt = 0; nt < 4; nt++) {
            int c0 = kc0 + nt * 8 + t * 2;
            float p0 = pmall[kbase + c0], p1 = pmall[kbase + c0 + 1];
            float s0 = S[nt][0] + p0, s1 = S[nt][1] + p1;
            float s2 = S[nt][2] + p0, s3 = S[nt][3] + p1;
            if (diag) {
                int k0i = kbase + c0, k1i = k0i + 1;
                if (left) {
                    if (k0i > qi0) s0 = NEGF;
                    if (k1i > qi0) s1 = NEGF;
                    if (k0i > qi1) s2 = NEGF;
                    if (k1i > qi1) s3 = NEGF;
                } else {
                    if (k0i < qi0) s0 = NEGF;
                    if (k1i < qi0) s1 = NEGF;
                    if (k0i < qi1) s2 = NEGF;
                    if (k1i < qi1) s3 = NEGF;
                }
            }
            S[nt][0] = s0; S[nt][1] = s1; S[nt][2] = s2; S[nt][3] = s3;
            mx0 = fmaxf(mx0, fmaxf(s0, s1));
            mx1 = fmaxf(mx1, fmaxf(s2, s3));
        }
        mx0 = fmaxf(mx0, __shfl_xor_sync(0xffffffffu, mx0, 1));
        mx0 = fmaxf(mx0, __shfl_xor_sync(0xffffffffu, mx0, 2));
        mx1 = fmaxf(mx1, __shfl_xor_sync(0xffffffffu, mx1, 1));
        mx1 = fmaxf(mx1, __shfl_xor_sync(0xffffffffu, mx1, 2));

        float mn0 = fmaxf(m_r[0], mx0), mn1 = fmaxf(m_r[1], mx1);
        float al0 = __expf(m_r[0] - mn0), al1 = __expf(m_r[1] - mn1);
        m_r[0] = mn0; m_r[1] = mn1;

        float rs0 = 0.f, rs1 = 0.f;
#pragma unroll
        for (int nt = 0; nt < 4; nt++) {
            float e0 = __expf(S[nt][0] - mn0), e1 = __expf(S[nt][1] - mn0);
            float e2 = __expf(S[nt][2] - mn1), e3 = __expf(S[nt][3] - mn1);
            S[nt][0] = e0; S[nt][1] = e1; S[nt][2] = e2; S[nt][3] = e3;
            rs0 += e0 + e1; rs1 += e2 + e3;
        }
        rs0 += __shfl_xor_sync(0xffffffffu, rs0, 1);
        rs0 += __shfl_xor_sync(0xffffffffu, rs0, 2);
        rs1 += __shfl_xor_sync(0xffffffffu, rs1, 1);
        rs1 += __shfl_xor_sync(0xffffffffu, rs1, 2);
        l_r[0] = l_r[0] * al0 + rs0;
        l_r[1] = l_r[1] * al1 + rs1;
#pragma unroll
        for (int nt = 0; nt < 8; nt++) {
            O[nt][0] *= al0; O[nt][1] *= al0;
            O[nt][2] *= al1; O[nt][3] *= al1;
        }

        // P -> smem (warp-private rows x warp-private cols)
        __syncwarp();
#pragma unroll
        for (int nt = 0; nt < 4; nt++) {
            int c0 = kc0 + nt * 8 + t * 2;
            Ps[(rm     + g) * 68 + c0    ] = f2tf32(S[nt][0]);
            Ps[(rm     + g) * 68 + c0 + 1] = f2tf32(S[nt][1]);
            Ps[(rm + 8 + g) * 68 + c0    ] = f2tf32(S[nt][2]);
            Ps[(rm + 8 + g) * 68 + c0 + 1] = f2tf32(S[nt][3]);
        }
        __syncwarp();

        // O += P(16 x its 32) @ Vt^T : b-frags via ldmatrix on Vt rows
#pragma unroll
        for (int ks = 0; ks < 4; ks++) {
            const uint32_t ko = ks * 32;         // 8 kseq words
            unsigned a0, a1, a2, a3;
            ldsm4(a0, a1, a2, a3, padr + ko);
#pragma unroll
            for (int p = 0; p < 4; p++) {
                unsigned bf[4];
                ldsm4(bf[0], bf[1], bf[2], bf[3], vad[p] + bufoff + ko);
                mma8(O[2*p],   a0, a1, a2, a3, bf[0], bf[1]);
                mma8(O[2*p+1], a0, a1, a2, a3, bf[2], bf[3]);
            }
        }
    }

    // ----- Merge warp pair (kh=0 <- kh=1) and write ctx -----
    __syncthreads();                     // all compute done; Ps/pm dead
    float* sc = (float*)(smu + APS);     // scratch [4 warps][32 lanes][37]
    if (kh == 1) {
        int base = (qgrp * 32 + lane) * 37;
#pragma unroll
        for (int nt = 0; nt < 8; nt++) {
            sc[base + nt * 4 + 0] = O[nt][0];
            sc[base + nt * 4 + 1] = O[nt][1];
            sc[base + nt * 4 + 2] = O[nt][2];
            sc[base + nt * 4 + 3] = O[nt][3];
        }
        sc[base + 32] = m_r[0]; sc[base + 33] = m_r[1];
        sc[base + 34] = l_r[0]; sc[base + 35] = l_r[1];
    }
    __syncthreads();
    if (kh == 0) {
        int base = (qgrp * 32 + lane) * 37;
        float mb0 = sc[base + 32], mb1 = sc[base + 33];
        float lb0 = sc[base + 34], lb1 = sc[base + 35];
        float M0 = fmaxf(m_r[0], mb0), M1 = fmaxf(m_r[1], mb1);
        float sa0 = __expf(m_r[0] - M0), sb0 = __expf(mb0 - M0);
        float sa1 = __expf(m_r[1] - M1), sb1 = __expf(mb1 - M1);
        float L0 = l_r[0] * sa0 + lb0 * sb0;
        float L1 = l_r[1] * sa1 + lb1 * sb1;
        float inv0 = 1.0f / L0, inv1 = 1.0f / L1;
        int t0 = qb * 64 + rm + g, t1 = t0 + 8;
#pragma unroll
        for (int nt = 0; nt < 8; nt++) {
            float o0 = O[nt][0] * sa0 + sc[base + nt * 4 + 0] * sb0;
            float o1 = O[nt][1] * sa0 + sc[base + nt * 4 + 1] * sb0;
            float o2 = O[nt][2] * sa1 + sc[base + nt * 4 + 2] * sb1;
            float o3 = O[nt][3] * sa1 + sc[base + nt * 4 + 3] * sb1;
            int col = h * DD + nt * 8 + t * 2;
            *(float2*)(g_ctx + ((size_t)b * TT + t0) * CC + col) =
                make_float2(rnd(o0 * inv0), rnd(o1 * inv0));
            *(float2*)(g_ctx + ((size_t)b * TT + t1) * CC + col) =
                make_float2(rnd(o2 * inv1), rnd(o3 * inv1));
        }
    }
}

// ---------------------------------------------------------------------------
extern "C" void kernel_launch(void* const* d_in, const int* in_sizes, int n_in,
                              void* d_out, int out_size)
{
    const float* x      = (const float*)d_in[0];
    const int*   amask  = (const int*)  d_in[1];
    const float* Wqkv_w = (const float*)d_in[2];
    const float* Wqkv_b = (const float*)d_in[3];
    const float* Wo_w   = (const float*)d_in[4];
    const float* Wo_b   = (const float*)d_in[5];
    float* out = (float*)d_out;

    (void)in_sizes; (void)n_in; (void)out_size;

    cudaFuncSetAttribute(attn_mma_kernel,
                         cudaFuncAttributeMaxDynamicSharedMemorySize, ATTN_SMEM);
    cudaFuncSetAttribute(qkv_gemm_kernel,
                         cudaFuncAttributeMaxDynamicSharedMemorySize, WIDE_SMEM);
    cudaFuncSetAttribute(out_gemm_kernel,
                         cudaFuncAttributeMaxDynamicSharedMemorySize, NARROW_SMEM);

    preround_kernel<<<(PRN4 + 255) / 256, 256>>>(x, Wqkv_w, Wo_w);
    qkv_gemm_kernel<<<dim3(N1 / 128, MM / 128), 256, WIDE_SMEM>>>(Wqkv_b);
    attn_mma_kernel<<<dim3(BB * HH, TT / 64), 256, ATTN_SMEM>>>(amask);
    out_gemm_kernel<<<dim3(CC / 64, MM / 128), 256, NARROW_SMEM>>>(Wo_b, out);
}